// round 6
// baseline (speedup 1.0000x reference)
#include <cuda_runtime.h>
#include <cuda_bf16.h>
#include <math.h>
#include <stdint.h>

// Shapes: B=16, N=512, D=256, H=8, DK=32, C=16
#define BB 16
#define NN 512
#define DD 256
#define HH 8
#define DKH 32
#define CC 16

__device__ float g_bufQ[BB * NN * DD];
__device__ float g_bufK[BB * NN * DD];
__device__ float g_bufV[BB * NN * DD];
__device__ float g_bufO[BB * NN * DD];
__device__ float g_bufX[BB * NN * DD];
__device__ float g_aggrg[BB * DD];
__device__ float g_ares[BB * DD];
__device__ float g_rbias[BB * DD];
__device__ float g_G[BB * CC * DD];
__device__ float g_CNT[BB * CC];

__device__ __forceinline__ float gelu_f(float x) {
    return 0.5f * x * (1.0f + erff(x * 0.7071067811865475f));
}

// exp(x) on the FMA/ALU pipes (no MUFU). ~1.2e-7 rel error.
__device__ __forceinline__ float fast_exp(float x) {
    float y = x * 1.4426950408889634f;
    y = fmaxf(y, -126.0f);
    float f = rintf(y);
    float z = y - f;
    float p = 1.5403530393381609e-4f;
    p = fmaf(p, z, 1.3333558146428443e-3f);
    p = fmaf(p, z, 9.6181291076284772e-3f);
    p = fmaf(p, z, 5.5504108664821580e-2f);
    p = fmaf(p, z, 2.4022650695910072e-1f);
    p = fmaf(p, z, 6.9314718055994531e-1f);
    p = fmaf(p, z, 1.0f);
    int e = (int)f;
    float s = __int_as_float((e + 127) << 23);
    return p * s;
}

__device__ __forceinline__ uint32_t f2tf32(float x) {
    uint32_t u;
    asm("cvt.rna.tf32.f32 %0, %1;" : "=r"(u) : "f"(x));
    return u;
}

__device__ __forceinline__ void mma_tf32(float c[4],
    uint32_t a0, uint32_t a1, uint32_t a2, uint32_t a3,
    uint32_t b0, uint32_t b1)
{
    asm volatile(
        "mma.sync.aligned.m16n8k8.row.col.f32.tf32.tf32.f32 "
        "{%0,%1,%2,%3},{%4,%5,%6,%7},{%8,%9},{%0,%1,%2,%3};"
        : "+f"(c[0]), "+f"(c[1]), "+f"(c[2]), "+f"(c[3])
        : "r"(a0), "r"(a1), "r"(a2), "r"(a3), "r"(b0), "r"(b1));
}

// ---------------------------------------------------------------------------
// tf32 tensor-core GEMM core (shared by plain and QKV-fused kernels)
// Block 128x128, BK=16, 256 threads = 8 warps of 64x32 warp-tiles.
// ---------------------------------------------------------------------------
#define GBM 128
#define GBN 128
#define GBK 16

template <int AIN, int AOUT, int BMODE>
__device__ __forceinline__ void gemm_tf32_body(
    const float* __restrict__ A, const float* __restrict__ W,
    const float* __restrict__ bias, float* __restrict__ C,
    int M, int N, int K, int bm, int bn)
{
    __shared__ uint32_t As[GBM][GBK + 4];
    __shared__ uint32_t Ws[GBK][GBN + 8];

    const int t    = threadIdx.x;
    const int lane = t & 31;
    const int wid  = t >> 5;
    const int wm   = (wid & 1) * 64;
    const int wn   = (wid >> 1) * 32;

    float c[4][4][4];
    #pragma unroll
    for (int mt = 0; mt < 4; mt++)
        #pragma unroll
        for (int nt = 0; nt < 4; nt++)
            #pragma unroll
            for (int i = 0; i < 4; i++) c[mt][nt][i] = 0.0f;

    const int ar = t >> 1, ac = (t & 1) * 8;
    const int wr = t >> 4, wc = (t & 15) * 8;
    const int lq = lane >> 2;
    const int lr = lane & 3;

    for (int k0 = 0; k0 < K; k0 += GBK) {
        float4 a0 = make_float4(0.f,0.f,0.f,0.f), a1 = make_float4(0.f,0.f,0.f,0.f);
        if (bm + ar < M) {
            a0 = *(const float4*)&A[(size_t)(bm + ar) * K + k0 + ac];
            a1 = *(const float4*)&A[(size_t)(bm + ar) * K + k0 + ac + 4];
        }
        if (AIN) {
            a0.x = gelu_f(a0.x); a0.y = gelu_f(a0.y); a0.z = gelu_f(a0.z); a0.w = gelu_f(a0.w);
            a1.x = gelu_f(a1.x); a1.y = gelu_f(a1.y); a1.z = gelu_f(a1.z); a1.w = gelu_f(a1.w);
        }
        As[ar][ac + 0] = f2tf32(a0.x); As[ar][ac + 1] = f2tf32(a0.y);
        As[ar][ac + 2] = f2tf32(a0.z); As[ar][ac + 3] = f2tf32(a0.w);
        As[ar][ac + 4] = f2tf32(a1.x); As[ar][ac + 5] = f2tf32(a1.y);
        As[ar][ac + 6] = f2tf32(a1.z); As[ar][ac + 7] = f2tf32(a1.w);

        float4 w0 = *(const float4*)&W[(size_t)(k0 + wr) * N + bn + wc];
        float4 w1 = *(const float4*)&W[(size_t)(k0 + wr) * N + bn + wc + 4];
        Ws[wr][wc + 0] = f2tf32(w0.x); Ws[wr][wc + 1] = f2tf32(w0.y);
        Ws[wr][wc + 2] = f2tf32(w0.z); Ws[wr][wc + 3] = f2tf32(w0.w);
        Ws[wr][wc + 4] = f2tf32(w1.x); Ws[wr][wc + 5] = f2tf32(w1.y);
        Ws[wr][wc + 6] = f2tf32(w1.z); Ws[wr][wc + 7] = f2tf32(w1.w);

        __syncthreads();

        #pragma unroll
        for (int ks = 0; ks < GBK; ks += 8) {
            uint32_t af[4][4];
            #pragma unroll
            for (int mt = 0; mt < 4; mt++) {
                int r = wm + mt * 16 + lq;
                af[mt][0] = As[r    ][ks + lr];
                af[mt][1] = As[r + 8][ks + lr];
                af[mt][2] = As[r    ][ks + lr + 4];
                af[mt][3] = As[r + 8][ks + lr + 4];
            }
            uint32_t bf[4][2];
            #pragma unroll
            for (int nt = 0; nt < 4; nt++) {
                int nc = wn + nt * 8 + lq;
                bf[nt][0] = Ws[ks + lr    ][nc];
                bf[nt][1] = Ws[ks + lr + 4][nc];
            }
            #pragma unroll
            for (int mt = 0; mt < 4; mt++)
                #pragma unroll
                for (int nt = 0; nt < 4; nt++)
                    mma_tf32(c[mt][nt], af[mt][0], af[mt][1], af[mt][2], af[mt][3],
                             bf[nt][0], bf[nt][1]);
        }
        __syncthreads();
    }

    #pragma unroll
    for (int mt = 0; mt < 4; mt++) {
        int row0 = bm + wm + mt * 16 + lq;
        int row1 = row0 + 8;
        #pragma unroll
        for (int nt = 0; nt < 4; nt++) {
            int col = bn + wn + nt * 8 + lr * 2;
            float v0 = c[mt][nt][0], v1 = c[mt][nt][1];
            float v2 = c[mt][nt][2], v3 = c[mt][nt][3];
            if (BMODE == 1) {
                float b0 = bias[col], b1 = bias[col + 1];
                v0 += b0; v1 += b1; v2 += b0; v3 += b1;
            }
            if (BMODE == 2) {
                if (row0 < M) {
                    const float* bb = bias + (size_t)(row0 >> 9) * N + col;
                    v0 += bb[0]; v1 += bb[1];
                }
                if (row1 < M) {
                    const float* bb = bias + (size_t)(row1 >> 9) * N + col;
                    v2 += bb[0]; v3 += bb[1];
                }
            }
            if (AOUT) { v0 = gelu_f(v0); v1 = gelu_f(v1); v2 = gelu_f(v2); v3 = gelu_f(v3); }
            if (row0 < M) *(float2*)&C[(size_t)row0 * N + col] = make_float2(v0, v1);
            if (row1 < M) *(float2*)&C[(size_t)row1 * N + col] = make_float2(v2, v3);
        }
    }
}

template <int AIN, int AOUT, int BMODE>
__global__ __launch_bounds__(256) void gemm_tf32_kernel(
    const float* __restrict__ A, const float* __restrict__ W,
    const float* __restrict__ bias, float* __restrict__ C,
    int M, int N, int K)
{
    gemm_tf32_body<AIN, AOUT, BMODE>(A, W, bias, C, M, N, K,
                                     blockIdx.x * GBM, blockIdx.y * GBN);
}

// QKV fused: gridDim.z = 3 selects W and C.
__global__ __launch_bounds__(256) void gemm_tf32_qkv_kernel(
    const float* __restrict__ A,
    const float* __restrict__ W0, const float* __restrict__ W1, const float* __restrict__ W2,
    float* __restrict__ C0, float* __restrict__ C1, float* __restrict__ C2,
    int M, int N, int K)
{
    const float* W = (blockIdx.z == 0) ? W0 : (blockIdx.z == 1) ? W1 : W2;
    float*       C = (blockIdx.z == 0) ? C0 : (blockIdx.z == 1) ? C1 : C2;
    gemm_tf32_body<0, 0, 0>(A, W, nullptr, C, M, N, K,
                            blockIdx.x * GBM, blockIdx.y * GBN);
}

// ---------------------------------------------------------------------------
// Fused attention v5: 32 queries per block, 256 threads, 2 CTAs/SM.
// Scores accumulated fully in registers (64 regs: 4 rows x 16 cols/thread);
// softmax (max/exp/sum/normalize) entirely in registers + warp shuffles.
// P hits smem exactly once (STS), PV reads it once (broadcast LDS).
// smem (floats): qs[32][36] @0, ks[32][132] @1152, vs[128][36] @5376,
//                sc[32][516] @9984; total 26496 fl = 103.5 KB.
// ---------------------------------------------------------------------------
#define SP 516
#define ATTN_SMEM_FLOATS 26496
#define ATTN_SMEM_BYTES  (ATTN_SMEM_FLOATS * 4)

__global__ __launch_bounds__(256, 2) void attn_kernel(
    const float* __restrict__ Qp, const float* __restrict__ Kp,
    const float* __restrict__ Vp, float* __restrict__ Op)
{
    extern __shared__ float sm[];
    float* qs = sm;            // [32][36]  d-major Q (prescaled)
    float* ks = sm + 1152;     // [32][132] d-major K tile (128 keys)
    float* vs = sm + 5376;     // [128][36] row-major V tile
    float* sc = sm + 9984;     // [32][516] normalized P

    const int t  = threadIdx.x;
    const int qb = blockIdx.x * 32;
    const int h  = blockIdx.y;
    const int b  = blockIdx.z;
    const float scale = 0.17677669529663688f;  // 1/sqrt(32)

    const size_t baseQ  = ((size_t)(b * NN + qb)) * DD + h * DKH;
    const size_t baseKV = ((size_t)(b * NN)) * DD + h * DKH;

    // load Q transposed (d-major), prescaled: 32 rows x 32 d
    {
        int r = t >> 3, cc = (t & 7) * 4;
        float4 q4 = *(const float4*)&Qp[baseQ + (size_t)r * DD + cc];
        qs[(cc + 0) * 36 + r] = q4.x * scale;
        qs[(cc + 1) * 36 + r] = q4.y * scale;
        qs[(cc + 2) * 36 + r] = q4.z * scale;
        qs[(cc + 3) * 36 + r] = q4.w * scale;
    }

    const int ty = t >> 5;   // warp 0..7 -> q rows ty*4 .. ty*4+3
    const int tx = t & 31;   // k group tx*4 within each 128-tile

    // score accumulators: acc[i][kt*4+j] = S(ty*4+i, kt*128+tx*4+j)
    float acc[4][16];
    #pragma unroll
    for (int i = 0; i < 4; i++)
        #pragma unroll
        for (int j = 0; j < 16; j++) acc[i][j] = 0.0f;

    // ---- scores = Q @ K^T over 4 key-tiles of 128, accumulate in regs ----
    #pragma unroll 1
    for (int kt = 0; kt < 4; kt++) {
        const int kb = kt * 128;
        __syncthreads();
        for (int i = t; i < 1024; i += 256) {
            int r = i >> 3, cc = (i & 7) * 4;
            float4 k4 = *(const float4*)&Kp[baseKV + (size_t)(kb + r) * DD + cc];
            ks[(cc + 0) * 132 + r] = k4.x;
            ks[(cc + 1) * 132 + r] = k4.y;
            ks[(cc + 2) * 132 + r] = k4.z;
            ks[(cc + 3) * 132 + r] = k4.w;
        }
        __syncthreads();

        #pragma unroll
        for (int d = 0; d < 32; d++) {
            float4 a  = *(const float4*)&qs[d * 36 + ty * 4];       // warp-broadcast
            float4 bk = *(const float4*)&ks[d * 132 + tx * 4];
            float ar[4] = {a.x, a.y, a.z, a.w};
            #pragma unroll
            for (int i = 0; i < 4; i++) {
                acc[i][kt * 4 + 0] = fmaf(ar[i], bk.x, acc[i][kt * 4 + 0]);
                acc[i][kt * 4 + 1] = fmaf(ar[i], bk.y, acc[i][kt * 4 + 1]);
                acc[i][kt * 4 + 2] = fmaf(ar[i], bk.z, acc[i][kt * 4 + 2]);
                acc[i][kt * 4 + 3] = fmaf(ar[i], bk.w, acc[i][kt * 4 + 3]);
            }
        }
    }

    // ---- softmax fully in registers (rows complete within the warp) ----
    #pragma unroll
    for (int i = 0; i < 4; i++) {
        float mx = acc[i][0];
        #pragma unroll
        for (int j = 1; j < 16; j++) mx = fmaxf(mx, acc[i][j]);
        #pragma unroll
        for (int o = 16; o; o >>= 1) mx = fmaxf(mx, __shfl_xor_sync(0xFFFFFFFFu, mx, o));
        float s = 0.0f;
        #pragma unroll
        for (int j = 0; j < 16; j++) {
            float e = fast_exp(acc[i][j] - mx);
            acc[i][j] = e;
            s += e;
        }
        #pragma unroll
        for (int o = 16; o; o >>= 1) s += __shfl_xor_sync(0xFFFFFFFFu, s, o);
        float inv = 1.0f / s;
        #pragma unroll
        for (int j = 0; j < 16; j++) acc[i][j] *= inv;
    }

    // single STS of normalized P
    #pragma unroll
    for (int i = 0; i < 4; i++)
        #pragma unroll
        for (int kt = 0; kt < 4; kt++)
            *(float4*)&sc[(ty * 4 + i) * SP + kt * 128 + tx * 4] =
                make_float4(acc[i][kt*4+0], acc[i][kt*4+1], acc[i][kt*4+2], acc[i][kt*4+3]);

    // ---- O = P @ V: 256 threads, 1q x 4d each; V staged per 128-tile ----
    const int q  = t >> 3;          // 0..31
    const int dg = (t & 7) * 4;     // 0..28
    float o[4] = {0, 0, 0, 0};

    #pragma unroll 1
    for (int kt = 0; kt < 4; kt++) {
        const int kb = kt * 128;
        __syncthreads();   // covers P STS on kt=0, vs reuse after
        for (int i = t; i < 1024; i += 256) {
            int r = i >> 3, cc = (i & 7) * 4;
            float4 v4 = *(const float4*)&Vp[baseKV + (size_t)(kb + r) * DD + cc];
            *(float4*)&vs[r * 36 + cc] = v4;
        }
        __syncthreads();

        const float* p = sc + (size_t)q * SP + kb;
        #pragma unroll 4
        for (int kk = 0; kk < 128; kk += 4) {
            float4 P = *(const float4*)&p[kk];   // broadcast across 8-lane group
            float4 v;
            v = *(const float4*)&vs[(kk + 0) * 36 + dg];
            o[0]=fmaf(P.x,v.x,o[0]); o[1]=fmaf(P.x,v.y,o[1]); o[2]=fmaf(P.x,v.z,o[2]); o[3]=fmaf(P.x,v.w,o[3]);
            v = *(const float4*)&vs[(kk + 1) * 36 + dg];
            o[0]=fmaf(P.y,v.x,o[0]); o[1]=fmaf(P.y,v.y,o[1]); o[2]=fmaf(P.y,v.z,o[2]); o[3]=fmaf(P.y,v.w,o[3]);
            v = *(const float4*)&vs[(kk + 2) * 36 + dg];
            o[0]=fmaf(P.z,v.x,o[0]); o[1]=fmaf(P.z,v.y,o[1]); o[2]=fmaf(P.z,v.z,o[2]); o[3]=fmaf(P.z,v.w,o[3]);
            v = *(const float4*)&vs[(kk + 3) * 36 + dg];
            o[0]=fmaf(P.w,v.x,o[0]); o[1]=fmaf(P.w,v.y,o[1]); o[2]=fmaf(P.w,v.z,o[2]); o[3]=fmaf(P.w,v.w,o[3]);
        }
    }
    *(float4*)&Op[baseQ + (size_t)q * DD + dg] = make_float4(o[0], o[1], o[2], o[3]);
}

// ---------------------------------------------------------------------------
__global__ __launch_bounds__(256) void colmean_gelu_kernel(
    const float* __restrict__ X, float* __restrict__ out)
{
    const int b = blockIdx.x;
    const int d = threadIdx.x;
    float s = 0.0f;
    const float* base = X + (size_t)b * NN * DD + d;
    for (int n = 0; n < NN; n++) s += base[(size_t)n * DD];
    out[b * DD + d] = gelu_f(s * (1.0f / (float)NN));
}

__global__ __launch_bounds__(256) void class_sum_kernel(
    const float* __restrict__ F, const int* __restrict__ lab,
    float* __restrict__ G, float* __restrict__ CNT)
{
    __shared__ float gs[CC * DD];
    __shared__ float cs[CC];
    const int b = blockIdx.x;
    const int t = threadIdx.x;
    for (int i = t; i < CC * DD; i += 256) gs[i] = 0.0f;
    if (t < CC) cs[t] = 0.0f;
    __syncthreads();
    for (int n = 0; n < NN; n++) {
        int c = lab[b * NN + n];
        gs[c * DD + t] += F[((size_t)b * NN + n) * DD + t];
        if (t == 0) cs[c] += 1.0f;
    }
    __syncthreads();
    for (int i = t; i < CC * DD; i += 256) G[(size_t)b * CC * DD + i] = gs[i];
    if (t < CC) CNT[b * CC + t] = cs[t];
}

__global__ __launch_bounds__(256) void proto_out_kernel(
    const float* __restrict__ F, const float* __restrict__ G,
    const float* __restrict__ CNT, const int* __restrict__ lab,
    float* __restrict__ out)
{
    __shared__ float fs[DD];
    const int n = blockIdx.x;
    const int b = blockIdx.y;
    const int t = threadIdx.x;
    fs[t] = F[((size_t)b * NN + n) * DD + t];
    __syncthreads();

    const int w = t >> 5, lane = t & 31;
    float sd = 0.0f;
    for (int i = lane; i < DD; i += 32) sd += fs[i] * fs[i];
    #pragma unroll
    for (int o = 16; o; o >>= 1) sd += __shfl_xor_sync(0xFFFFFFFFu, sd, o);

    const int labn = lab[b * NN + n];
    #pragma unroll
    for (int cc = 0; cc < 2; cc++) {
        const int c = w * 2 + cc;
        const float* g = G + (size_t)b * CC * DD + c * DD;
        float dp = 0.0f;
        for (int i = lane; i < DD; i += 32) dp += fs[i] * g[i];
        #pragma unroll
        for (int o = 16; o; o >>= 1) dp += __shfl_xor_sync(0xFFFFFFFFu, dp, o);
        if (lane == 0) {
            float same = (labn == c) ? 1.0f : 0.0f;
            out[((size_t)b * NN + n) * CC + c] =
                (dp - same * sd) / (CNT[b * CC + c] - same);
        }
    }
}

// ---------------------------------------------------------------------------
extern "C" void kernel_launch(void* const* d_in, const int* in_sizes, int n_in,
                              void* d_out, int out_size)
{
    const float* E    = (const float*)d_in[0];
    const int*   lab  = (const int*)  d_in[1];
    const float* Wq0  = (const float*)d_in[2];
    const float* Wk0  = (const float*)d_in[3];
    const float* Wv0  = (const float*)d_in[4];
    const float* Wo0  = (const float*)d_in[5];
    const float* Wq1  = (const float*)d_in[6];
    const float* Wk1  = (const float*)d_in[7];
    const float* Wv1  = (const float*)d_in[8];
    const float* Wo1  = (const float*)d_in[9];
    const float* resW = (const float*)d_in[10];
    const float* resb = (const float*)d_in[11];
    const float* ffW1 = (const float*)d_in[12];
    const float* ffb1 = (const float*)d_in[13];
    const float* ffW2 = (const float*)d_in[14];
    const float* ffb2 = (const float*)d_in[15];
    float* out = (float*)d_out;

    float *bQ, *bK, *bV, *bO, *bX, *aggrg, *ares, *rbias, *G, *CNT;
    cudaGetSymbolAddress((void**)&bQ,    g_bufQ);
    cudaGetSymbolAddress((void**)&bK,    g_bufK);
    cudaGetSymbolAddress((void**)&bV,    g_bufV);
    cudaGetSymbolAddress((void**)&bO,    g_bufO);
    cudaGetSymbolAddress((void**)&bX,    g_bufX);
    cudaGetSymbolAddress((void**)&aggrg, g_aggrg);
    cudaGetSymbolAddress((void**)&ares,  g_ares);
    cudaGetSymbolAddress((void**)&rbias, g_rbias);
    cudaGetSymbolAddress((void**)&G,     g_G);
    cudaGetSymbolAddress((void**)&CNT,   g_CNT);

    cudaFuncSetAttribute(attn_kernel,
                         cudaFuncAttributeMaxDynamicSharedMemorySize,
                         ATTN_SMEM_BYTES);

    const int M = BB * NN;                 // 8192
    dim3 gBig(M / GBM, DD / GBN);          // (64, 2)
    dim3 gQKV(M / GBM, DD / GBN, 3);       // (64, 2, 3)
    dim3 gSmall(1, DD / GBN);              // (1, 2)
    dim3 gAttn(NN / 32, HH, BB);           // (16, 8, 16)

    // ---- MHA 0 ----
    gemm_tf32_qkv_kernel<<<gQKV, 256>>>(E, Wq0, Wk0, Wv0, bQ, bK, bV, M, DD, DD);
    attn_kernel<<<gAttn, 256, ATTN_SMEM_BYTES>>>(bQ, bK, bV, bO);
    gemm_tf32_kernel<0, 1, 0><<<gBig, 256>>>(bO, Wo0, nullptr, bX, M, DD, DD);

    // ---- MHA 1 ----
    gemm_tf32_qkv_kernel<<<gQKV, 256>>>(bX, Wq1, Wk1, Wv1, bQ, bK, bV, M, DD, DD);
    attn_kernel<<<gAttn, 256, ATTN_SMEM_BYTES>>>(bQ, bK, bV, bO);
    gemm_tf32_kernel<0, 0, 0><<<gBig, 256>>>(bO, Wo1, nullptr, bX, M, DD, DD);

    // ---- aggregate path ----
    colmean_gelu_kernel<<<BB, 256>>>(bX, aggrg);
    gemm_tf32_kernel<0, 0, 1><<<gSmall, 256>>>(aggrg, resW, resb, ares, BB, DD, DD);
    gemm_tf32_kernel<1, 0, 1><<<gSmall, 256>>>(ares, ffW1, ffb1, rbias, BB, DD, DD);
    gemm_tf32_kernel<1, 1, 2><<<gBig, 256>>>(E, ffW1 + (size_t)DD * DD, rbias, bQ, M, DD, DD);
    gemm_tf32_kernel<0, 0, 1><<<gBig, 256>>>(bQ, ffW2, ffb2, bK, M, DD, DD);

    // ---- prototypical scoring ----
    class_sum_kernel<<<BB, 256>>>(bK, lab, G, CNT);
    proto_out_kernel<<<dim3(NN, BB), 256>>>(bK, G, CNT, lab, out);
}

// round 7
// speedup vs baseline: 1.1056x; 1.1056x over previous
#include <cuda_runtime.h>
#include <cuda_bf16.h>
#include <math.h>
#include <stdint.h>

// Shapes: B=16, N=512, D=256, H=8, DK=32, C=16
#define BB 16
#define NN 512
#define DD 256
#define HH 8
#define DKH 32
#define CC 16

__device__ float g_bufQ[BB * NN * DD];
__device__ float g_bufK[BB * NN * DD];
__device__ float g_bufV[BB * NN * DD];
__device__ float g_bufO[BB * NN * DD];
__device__ float g_bufX[BB * NN * DD];
__device__ float g_aggrg[BB * DD];
__device__ float g_ares[BB * DD];
__device__ float g_rbias[BB * DD];
__device__ float g_G[BB * CC * DD];
__device__ float g_CNT[BB * CC];

__device__ __forceinline__ float gelu_f(float x) {
    return 0.5f * x * (1.0f + erff(x * 0.7071067811865475f));
}

// exp(x) on the FMA/ALU pipes (no MUFU). ~1.2e-7 rel error.
__device__ __forceinline__ float fast_exp(float x) {
    float y = x * 1.4426950408889634f;
    y = fmaxf(y, -126.0f);
    float f = rintf(y);
    float z = y - f;
    float p = 1.5403530393381609e-4f;
    p = fmaf(p, z, 1.3333558146428443e-3f);
    p = fmaf(p, z, 9.6181291076284772e-3f);
    p = fmaf(p, z, 5.5504108664821580e-2f);
    p = fmaf(p, z, 2.4022650695910072e-1f);
    p = fmaf(p, z, 6.9314718055994531e-1f);
    p = fmaf(p, z, 1.0f);
    int e = (int)f;
    float s = __int_as_float((e + 127) << 23);
    return p * s;
}

__device__ __forceinline__ uint32_t f2tf32(float x) {
    uint32_t u;
    asm("cvt.rna.tf32.f32 %0, %1;" : "=r"(u) : "f"(x));
    return u;
}

__device__ __forceinline__ void mma_tf32(float c[4],
    uint32_t a0, uint32_t a1, uint32_t a2, uint32_t a3,
    uint32_t b0, uint32_t b1)
{
    asm volatile(
        "mma.sync.aligned.m16n8k8.row.col.f32.tf32.tf32.f32 "
        "{%0,%1,%2,%3},{%4,%5,%6,%7},{%8,%9},{%0,%1,%2,%3};"
        : "+f"(c[0]), "+f"(c[1]), "+f"(c[2]), "+f"(c[3])
        : "r"(a0), "r"(a1), "r"(a2), "r"(a3), "r"(b0), "r"(b1));
}

// ---------------------------------------------------------------------------
// tf32 tensor-core GEMM core (shared by plain and QKV-fused kernels)
// Block 128x128, BK=16, 256 threads = 8 warps of 64x32 warp-tiles.
// ---------------------------------------------------------------------------
#define GBM 128
#define GBN 128
#define GBK 16

template <int AIN, int AOUT, int BMODE>
__device__ __forceinline__ void gemm_tf32_body(
    const float* __restrict__ A, const float* __restrict__ W,
    const float* __restrict__ bias, float* __restrict__ C,
    int M, int N, int K, int bm, int bn)
{
    __shared__ uint32_t As[GBM][GBK + 4];
    __shared__ uint32_t Ws[GBK][GBN + 8];

    const int t    = threadIdx.x;
    const int lane = t & 31;
    const int wid  = t >> 5;
    const int wm   = (wid & 1) * 64;
    const int wn   = (wid >> 1) * 32;

    float c[4][4][4];
    #pragma unroll
    for (int mt = 0; mt < 4; mt++)
        #pragma unroll
        for (int nt = 0; nt < 4; nt++)
            #pragma unroll
            for (int i = 0; i < 4; i++) c[mt][nt][i] = 0.0f;

    const int ar = t >> 1, ac = (t & 1) * 8;
    const int wr = t >> 4, wc = (t & 15) * 8;
    const int lq = lane >> 2;
    const int lr = lane & 3;

    for (int k0 = 0; k0 < K; k0 += GBK) {
        float4 a0 = make_float4(0.f,0.f,0.f,0.f), a1 = make_float4(0.f,0.f,0.f,0.f);
        if (bm + ar < M) {
            a0 = *(const float4*)&A[(size_t)(bm + ar) * K + k0 + ac];
            a1 = *(const float4*)&A[(size_t)(bm + ar) * K + k0 + ac + 4];
        }
        if (AIN) {
            a0.x = gelu_f(a0.x); a0.y = gelu_f(a0.y); a0.z = gelu_f(a0.z); a0.w = gelu_f(a0.w);
            a1.x = gelu_f(a1.x); a1.y = gelu_f(a1.y); a1.z = gelu_f(a1.z); a1.w = gelu_f(a1.w);
        }
        As[ar][ac + 0] = f2tf32(a0.x); As[ar][ac + 1] = f2tf32(a0.y);
        As[ar][ac + 2] = f2tf32(a0.z); As[ar][ac + 3] = f2tf32(a0.w);
        As[ar][ac + 4] = f2tf32(a1.x); As[ar][ac + 5] = f2tf32(a1.y);
        As[ar][ac + 6] = f2tf32(a1.z); As[ar][ac + 7] = f2tf32(a1.w);

        float4 w0 = *(const float4*)&W[(size_t)(k0 + wr) * N + bn + wc];
        float4 w1 = *(const float4*)&W[(size_t)(k0 + wr) * N + bn + wc + 4];
        Ws[wr][wc + 0] = f2tf32(w0.x); Ws[wr][wc + 1] = f2tf32(w0.y);
        Ws[wr][wc + 2] = f2tf32(w0.z); Ws[wr][wc + 3] = f2tf32(w0.w);
        Ws[wr][wc + 4] = f2tf32(w1.x); Ws[wr][wc + 5] = f2tf32(w1.y);
        Ws[wr][wc + 6] = f2tf32(w1.z); Ws[wr][wc + 7] = f2tf32(w1.w);

        __syncthreads();

        #pragma unroll
        for (int ks = 0; ks < GBK; ks += 8) {
            uint32_t af[4][4];
            #pragma unroll
            for (int mt = 0; mt < 4; mt++) {
                int r = wm + mt * 16 + lq;
                af[mt][0] = As[r    ][ks + lr];
                af[mt][1] = As[r + 8][ks + lr];
                af[mt][2] = As[r    ][ks + lr + 4];
                af[mt][3] = As[r + 8][ks + lr + 4];
            }
            uint32_t bf[4][2];
            #pragma unroll
            for (int nt = 0; nt < 4; nt++) {
                int nc = wn + nt * 8 + lq;
                bf[nt][0] = Ws[ks + lr    ][nc];
                bf[nt][1] = Ws[ks + lr + 4][nc];
            }
            #pragma unroll
            for (int mt = 0; mt < 4; mt++)
                #pragma unroll
                for (int nt = 0; nt < 4; nt++)
                    mma_tf32(c[mt][nt], af[mt][0], af[mt][1], af[mt][2], af[mt][3],
                             bf[nt][0], bf[nt][1]);
        }
        __syncthreads();
    }

    #pragma unroll
    for (int mt = 0; mt < 4; mt++) {
        int row0 = bm + wm + mt * 16 + lq;
        int row1 = row0 + 8;
        #pragma unroll
        for (int nt = 0; nt < 4; nt++) {
            int col = bn + wn + nt * 8 + lr * 2;
            float v0 = c[mt][nt][0], v1 = c[mt][nt][1];
            float v2 = c[mt][nt][2], v3 = c[mt][nt][3];
            if (BMODE == 1) {
                float b0 = bias[col], b1 = bias[col + 1];
                v0 += b0; v1 += b1; v2 += b0; v3 += b1;
            }
            if (BMODE == 2) {
                if (row0 < M) {
                    const float* bb = bias + (size_t)(row0 >> 9) * N + col;
                    v0 += bb[0]; v1 += bb[1];
                }
                if (row1 < M) {
                    const float* bb = bias + (size_t)(row1 >> 9) * N + col;
                    v2 += bb[0]; v3 += bb[1];
                }
            }
            if (AOUT) { v0 = gelu_f(v0); v1 = gelu_f(v1); v2 = gelu_f(v2); v3 = gelu_f(v3); }
            if (row0 < M) *(float2*)&C[(size_t)row0 * N + col] = make_float2(v0, v1);
            if (row1 < M) *(float2*)&C[(size_t)row1 * N + col] = make_float2(v2, v3);
        }
    }
}

template <int AIN, int AOUT, int BMODE>
__global__ __launch_bounds__(256) void gemm_tf32_kernel(
    const float* __restrict__ A, const float* __restrict__ W,
    const float* __restrict__ bias, float* __restrict__ C,
    int M, int N, int K)
{
    gemm_tf32_body<AIN, AOUT, BMODE>(A, W, bias, C, M, N, K,
                                     blockIdx.x * GBM, blockIdx.y * GBN);
}

// QKV fused: gridDim.z = 3 selects W and C.
__global__ __launch_bounds__(256) void gemm_tf32_qkv_kernel(
    const float* __restrict__ A,
    const float* __restrict__ W0, const float* __restrict__ W1, const float* __restrict__ W2,
    float* __restrict__ C0, float* __restrict__ C1, float* __restrict__ C2,
    int M, int N, int K)
{
    const float* W = (blockIdx.z == 0) ? W0 : (blockIdx.z == 1) ? W1 : W2;
    float*       C = (blockIdx.z == 0) ? C0 : (blockIdx.z == 1) ? C1 : C2;
    gemm_tf32_body<0, 0, 0>(A, W, nullptr, C, M, N, K,
                            blockIdx.x * GBM, blockIdx.y * GBN);
}

// ---------------------------------------------------------------------------
// Fused attention v6: 32 queries per block, 256 threads, 2 CTAs/SM.
// exp applied in the QK epilogue REGISTERS (no max pass — scores are O(10),
// far from fp32 exp overflow); row sums accumulated in registers across
// key-tiles. P touches smem exactly once (STS); PV reads once and folds
// 1/rowsum into the output. No separate softmax phase at all.
// smem (floats): qs[32][36] @0, ks[32][132] @1152, vs[128][36] @5376,
//                rs[32] @9984, sc[32][516] @10016; total 26528 fl = 103.6 KB.
// ---------------------------------------------------------------------------
#define SP 516
#define ATTN_SMEM_FLOATS 26528
#define ATTN_SMEM_BYTES  (ATTN_SMEM_FLOATS * 4)

__global__ __launch_bounds__(256, 2) void attn_kernel(
    const float* __restrict__ Qp, const float* __restrict__ Kp,
    const float* __restrict__ Vp, float* __restrict__ Op)
{
    extern __shared__ float sm[];
    float* qs = sm;            // [32][36]  d-major Q (prescaled)
    float* ks = sm + 1152;     // [32][132] d-major K tile (128 keys)
    float* vs = sm + 5376;     // [128][36] row-major V tile
    float* rs = sm + 9984;     // [32] row sums of exp
    float* sc = sm + 10016;    // [32][516] exp(S) (unnormalized)

    const int t  = threadIdx.x;
    const int qb = blockIdx.x * 32;
    const int h  = blockIdx.y;
    const int b  = blockIdx.z;
    const float scale = 0.17677669529663688f;  // 1/sqrt(32)

    const size_t baseQ  = ((size_t)(b * NN + qb)) * DD + h * DKH;
    const size_t baseKV = ((size_t)(b * NN)) * DD + h * DKH;

    // load Q transposed (d-major), prescaled: 32 rows x 32 d (one shot, 256 thr)
    {
        int r = t >> 3, cc = (t & 7) * 4;
        float4 q4 = *(const float4*)&Qp[baseQ + (size_t)r * DD + cc];
        qs[(cc + 0) * 36 + r] = q4.x * scale;
        qs[(cc + 1) * 36 + r] = q4.y * scale;
        qs[(cc + 2) * 36 + r] = q4.z * scale;
        qs[(cc + 3) * 36 + r] = q4.w * scale;
    }

    const int ty = t >> 5;   // warp 0..7 -> q rows ty*4 .. ty*4+3
    const int tx = t & 31;   // k group tx*4 within each 128-tile

    float rsum[4] = {0.0f, 0.0f, 0.0f, 0.0f};

    // ---- scores tile-by-tile: QK^T -> exp in registers -> single STS ----
    #pragma unroll 1
    for (int kt = 0; kt < 4; kt++) {
        const int kb = kt * 128;
        __syncthreads();
        for (int i = t; i < 1024; i += 256) {
            int r = i >> 3, cc = (i & 7) * 4;
            float4 k4 = *(const float4*)&Kp[baseKV + (size_t)(kb + r) * DD + cc];
            ks[(cc + 0) * 132 + r] = k4.x;
            ks[(cc + 1) * 132 + r] = k4.y;
            ks[(cc + 2) * 132 + r] = k4.z;
            ks[(cc + 3) * 132 + r] = k4.w;
        }
        __syncthreads();

        float acc[4][4];
        #pragma unroll
        for (int i = 0; i < 4; i++)
            #pragma unroll
            for (int j = 0; j < 4; j++) acc[i][j] = 0.0f;

        #pragma unroll
        for (int d = 0; d < 32; d++) {
            float4 a  = *(const float4*)&qs[d * 36 + ty * 4];       // warp-broadcast
            float4 bk = *(const float4*)&ks[d * 132 + tx * 4];
            float ar[4] = {a.x, a.y, a.z, a.w};
            #pragma unroll
            for (int i = 0; i < 4; i++) {
                acc[i][0] = fmaf(ar[i], bk.x, acc[i][0]);
                acc[i][1] = fmaf(ar[i], bk.y, acc[i][1]);
                acc[i][2] = fmaf(ar[i], bk.z, acc[i][2]);
                acc[i][3] = fmaf(ar[i], bk.w, acc[i][3]);
            }
        }

        // exp in registers + row-sum accumulation + single STS
        #pragma unroll
        for (int i = 0; i < 4; i++) {
            float e0 = fast_exp(acc[i][0]);
            float e1 = fast_exp(acc[i][1]);
            float e2 = fast_exp(acc[i][2]);
            float e3 = fast_exp(acc[i][3]);
            rsum[i] += (e0 + e1) + (e2 + e3);
            *(float4*)&sc[(ty * 4 + i) * SP + kb + tx * 4] = make_float4(e0, e1, e2, e3);
        }
    }

    // warp-reduce row sums; lane 0 publishes
    #pragma unroll
    for (int i = 0; i < 4; i++) {
        float s = rsum[i];
        #pragma unroll
        for (int o = 16; o; o >>= 1) s += __shfl_xor_sync(0xFFFFFFFFu, s, o);
        if (tx == 0) rs[ty * 4 + i] = s;
    }

    // ---- O = P @ V: 256 threads, 1q x 4d each; V staged per 128-tile ----
    const int q  = t >> 3;          // 0..31
    const int dg = (t & 7) * 4;     // 0..28
    float o[4] = {0, 0, 0, 0};

    #pragma unroll 1
    for (int kt = 0; kt < 4; kt++) {
        const int kb = kt * 128;
        __syncthreads();   // covers sc/rs writes on kt=0, vs reuse after
        for (int i = t; i < 1024; i += 256) {
            int r = i >> 3, cc = (i & 7) * 4;
            float4 v4 = *(const float4*)&Vp[baseKV + (size_t)(kb + r) * DD + cc];
            *(float4*)&vs[r * 36 + cc] = v4;
        }
        __syncthreads();

        const float* p = sc + (size_t)q * SP + kb;
        #pragma unroll 4
        for (int kk = 0; kk < 128; kk += 4) {
            float4 P = *(const float4*)&p[kk];   // broadcast across 8-lane group
            float4 v;
            v = *(const float4*)&vs[(kk + 0) * 36 + dg];
            o[0]=fmaf(P.x,v.x,o[0]); o[1]=fmaf(P.x,v.y,o[1]); o[2]=fmaf(P.x,v.z,o[2]); o[3]=fmaf(P.x,v.w,o[3]);
            v = *(const float4*)&vs[(kk + 1) * 36 + dg];
            o[0]=fmaf(P.y,v.x,o[0]); o[1]=fmaf(P.y,v.y,o[1]); o[2]=fmaf(P.y,v.z,o[2]); o[3]=fmaf(P.y,v.w,o[3]);
            v = *(const float4*)&vs[(kk + 2) * 36 + dg];
            o[0]=fmaf(P.z,v.x,o[0]); o[1]=fmaf(P.z,v.y,o[1]); o[2]=fmaf(P.z,v.z,o[2]); o[3]=fmaf(P.z,v.w,o[3]);
            v = *(const float4*)&vs[(kk + 3) * 36 + dg];
            o[0]=fmaf(P.w,v.x,o[0]); o[1]=fmaf(P.w,v.y,o[1]); o[2]=fmaf(P.w,v.z,o[2]); o[3]=fmaf(P.w,v.w,o[3]);
        }
    }
    float inv = 1.0f / rs[q];
    *(float4*)&Op[baseQ + (size_t)q * DD + dg] =
        make_float4(o[0]*inv, o[1]*inv, o[2]*inv, o[3]*inv);
}

// ---------------------------------------------------------------------------
__global__ __launch_bounds__(256) void colmean_gelu_kernel(
    const float* __restrict__ X, float* __restrict__ out)
{
    const int b = blockIdx.x;
    const int d = threadIdx.x;
    float s = 0.0f;
    const float* base = X + (size_t)b * NN * DD + d;
    for (int n = 0; n < NN; n++) s += base[(size_t)n * DD];
    out[b * DD + d] = gelu_f(s * (1.0f / (float)NN));
}

__global__ __launch_bounds__(256) void class_sum_kernel(
    const float* __restrict__ F, const int* __restrict__ lab,
    float* __restrict__ G, float* __restrict__ CNT)
{
    __shared__ float gs[CC * DD];
    __shared__ float cs[CC];
    const int b = blockIdx.x;
    const int t = threadIdx.x;
    for (int i = t; i < CC * DD; i += 256) gs[i] = 0.0f;
    if (t < CC) cs[t] = 0.0f;
    __syncthreads();
    for (int n = 0; n < NN; n++) {
        int c = lab[b * NN + n];
        gs[c * DD + t] += F[((size_t)b * NN + n) * DD + t];
        if (t == 0) cs[c] += 1.0f;
    }
    __syncthreads();
    for (int i = t; i < CC * DD; i += 256) G[(size_t)b * CC * DD + i] = gs[i];
    if (t < CC) CNT[b * CC + t] = cs[t];
}

__global__ __launch_bounds__(256) void proto_out_kernel(
    const float* __restrict__ F, const float* __restrict__ G,
    const float* __restrict__ CNT, const int* __restrict__ lab,
    float* __restrict__ out)
{
    __shared__ float fs[DD];
    const int n = blockIdx.x;
    const int b = blockIdx.y;
    const int t = threadIdx.x;
    fs[t] = F[((size_t)b * NN + n) * DD + t];
    __syncthreads();

    const int w = t >> 5, lane = t & 31;
    float sd = 0.0f;
    for (int i = lane; i < DD; i += 32) sd += fs[i] * fs[i];
    #pragma unroll
    for (int o = 16; o; o >>= 1) sd += __shfl_xor_sync(0xFFFFFFFFu, sd, o);

    const int labn = lab[b * NN + n];
    #pragma unroll
    for (int cc = 0; cc < 2; cc++) {
        const int c = w * 2 + cc;
        const float* g = G + (size_t)b * CC * DD + c * DD;
        float dp = 0.0f;
        for (int i = lane; i < DD; i += 32) dp += fs[i] * g[i];
        #pragma unroll
        for (int o = 16; o; o >>= 1) dp += __shfl_xor_sync(0xFFFFFFFFu, dp, o);
        if (lane == 0) {
            float same = (labn == c) ? 1.0f : 0.0f;
            out[((size_t)b * NN + n) * CC + c] =
                (dp - same * sd) / (CNT[b * CC + c] - same);
        }
    }
}

// ---------------------------------------------------------------------------
extern "C" void kernel_launch(void* const* d_in, const int* in_sizes, int n_in,
                              void* d_out, int out_size)
{
    const float* E    = (const float*)d_in[0];
    const int*   lab  = (const int*)  d_in[1];
    const float* Wq0  = (const float*)d_in[2];
    const float* Wk0  = (const float*)d_in[3];
    const float* Wv0  = (const float*)d_in[4];
    const float* Wo0  = (const float*)d_in[5];
    const float* Wq1  = (const float*)d_in[6];
    const float* Wk1  = (const float*)d_in[7];
    const float* Wv1  = (const float*)d_in[8];
    const float* Wo1  = (const float*)d_in[9];
    const float* resW = (const float*)d_in[10];
    const float* resb = (const float*)d_in[11];
    const float* ffW1 = (const float*)d_in[12];
    const float* ffb1 = (const float*)d_in[13];
    const float* ffW2 = (const float*)d_in[14];
    const float* ffb2 = (const float*)d_in[15];
    float* out = (float*)d_out;

    float *bQ, *bK, *bV, *bO, *bX, *aggrg, *ares, *rbias, *G, *CNT;
    cudaGetSymbolAddress((void**)&bQ,    g_bufQ);
    cudaGetSymbolAddress((void**)&bK,    g_bufK);
    cudaGetSymbolAddress((void**)&bV,    g_bufV);
    cudaGetSymbolAddress((void**)&bO,    g_bufO);
    cudaGetSymbolAddress((void**)&bX,    g_bufX);
    cudaGetSymbolAddress((void**)&aggrg, g_aggrg);
    cudaGetSymbolAddress((void**)&ares,  g_ares);
    cudaGetSymbolAddress((void**)&rbias, g_rbias);
    cudaGetSymbolAddress((void**)&G,     g_G);
    cudaGetSymbolAddress((void**)&CNT,   g_CNT);

    cudaFuncSetAttribute(attn_kernel,
                         cudaFuncAttributeMaxDynamicSharedMemorySize,
                         ATTN_SMEM_BYTES);

    const int M = BB * NN;                 // 8192
    dim3 gBig(M / GBM, DD / GBN);          // (64, 2)
    dim3 gQKV(M / GBM, DD / GBN, 3);       // (64, 2, 3)
    dim3 gSmall(1, DD / GBN);              // (1, 2)
    dim3 gAttn(NN / 32, HH, BB);           // (16, 8, 16)

    // ---- MHA 0 ----
    gemm_tf32_qkv_kernel<<<gQKV, 256>>>(E, Wq0, Wk0, Wv0, bQ, bK, bV, M, DD, DD);
    attn_kernel<<<gAttn, 256, ATTN_SMEM_BYTES>>>(bQ, bK, bV, bO);
    gemm_tf32_kernel<0, 1, 0><<<gBig, 256>>>(bO, Wo0, nullptr, bX, M, DD, DD);

    // ---- MHA 1 ----
    gemm_tf32_qkv_kernel<<<gQKV, 256>>>(bX, Wq1, Wk1, Wv1, bQ, bK, bV, M, DD, DD);
    attn_kernel<<<gAttn, 256, ATTN_SMEM_BYTES>>>(bQ, bK, bV, bO);
    gemm_tf32_kernel<0, 0, 0><<<gBig, 256>>>(bO, Wo1, nullptr, bX, M, DD, DD);

    // ---- aggregate path ----
    colmean_gelu_kernel<<<BB, 256>>>(bX, aggrg);
    gemm_tf32_kernel<0, 0, 1><<<gSmall, 256>>>(aggrg, resW, resb, ares, BB, DD, DD);
    gemm_tf32_kernel<1, 0, 1><<<gSmall, 256>>>(ares, ffW1, ffb1, rbias, BB, DD, DD);
    gemm_tf32_kernel<1, 1, 2><<<gBig, 256>>>(E, ffW1 + (size_t)DD * DD, rbias, bQ, M, DD, DD);
    gemm_tf32_kernel<0, 0, 1><<<gBig, 256>>>(bQ, ffW2, ffb2, bK, M, DD, DD);

    // ---- prototypical scoring ----
    class_sum_kernel<<<BB, 256>>>(bK, lab, G, CNT);
    proto_out_kernel<<<dim3(NN, BB), 256>>>(bK, G, CNT, lab, out);
}

// round 8
// speedup vs baseline: 1.6579x; 1.4996x over previous
#include <cuda_runtime.h>
#include <cuda_bf16.h>
#include <math.h>
#include <stdint.h>

// Shapes: B=16, N=512, D=256, H=8, DK=32, C=16
#define BB 16
#define NN 512
#define DD 256
#define HH 8
#define DKH 32
#define CC 16

__device__ float g_bufQ[BB * NN * DD];
__device__ float g_bufK[BB * NN * DD];
__device__ float g_bufV[BB * NN * DD];
__device__ float g_bufO[BB * NN * DD];
__device__ float g_bufX[BB * NN * DD];
__device__ float g_aggrg[BB * DD];
__device__ float g_ares[BB * DD];
__device__ float g_rbias[BB * DD];
__device__ float g_G[BB * CC * DD];
__device__ float g_CNT[BB * CC];

__device__ __forceinline__ float gelu_f(float x) {
    return 0.5f * x * (1.0f + erff(x * 0.7071067811865475f));
}

// exp(x) on the FMA/ALU pipes (no MUFU). ~1.2e-7 rel error.
__device__ __forceinline__ float fast_exp(float x) {
    float y = x * 1.4426950408889634f;
    y = fmaxf(y, -126.0f);
    float f = rintf(y);
    float z = y - f;
    float p = 1.5403530393381609e-4f;
    p = fmaf(p, z, 1.3333558146428443e-3f);
    p = fmaf(p, z, 9.6181291076284772e-3f);
    p = fmaf(p, z, 5.5504108664821580e-2f);
    p = fmaf(p, z, 2.4022650695910072e-1f);
    p = fmaf(p, z, 6.9314718055994531e-1f);
    p = fmaf(p, z, 1.0f);
    int e = (int)f;
    float s = __int_as_float((e + 127) << 23);
    return p * s;
}

__device__ __forceinline__ uint32_t f2tf32(float x) {
    uint32_t u;
    asm("cvt.rna.tf32.f32 %0, %1;" : "=r"(u) : "f"(x));
    return u;
}

__device__ __forceinline__ void mma_tf32(float c[4],
    uint32_t a0, uint32_t a1, uint32_t a2, uint32_t a3,
    uint32_t b0, uint32_t b1)
{
    asm volatile(
        "mma.sync.aligned.m16n8k8.row.col.f32.tf32.tf32.f32 "
        "{%0,%1,%2,%3},{%4,%5,%6,%7},{%8,%9},{%0,%1,%2,%3};"
        : "+f"(c[0]), "+f"(c[1]), "+f"(c[2]), "+f"(c[3])
        : "r"(a0), "r"(a1), "r"(a2), "r"(a3), "r"(b0), "r"(b1));
}

// ---------------------------------------------------------------------------
// tf32 tensor-core GEMM core (unchanged from R7)
// ---------------------------------------------------------------------------
#define GBM 128
#define GBN 128
#define GBK 16

template <int AIN, int AOUT, int BMODE>
__device__ __forceinline__ void gemm_tf32_body(
    const float* __restrict__ A, const float* __restrict__ W,
    const float* __restrict__ bias, float* __restrict__ C,
    int M, int N, int K, int bm, int bn)
{
    __shared__ uint32_t As[GBM][GBK + 4];
    __shared__ uint32_t Ws[GBK][GBN + 8];

    const int t    = threadIdx.x;
    const int lane = t & 31;
    const int wid  = t >> 5;
    const int wm   = (wid & 1) * 64;
    const int wn   = (wid >> 1) * 32;

    float c[4][4][4];
    #pragma unroll
    for (int mt = 0; mt < 4; mt++)
        #pragma unroll
        for (int nt = 0; nt < 4; nt++)
            #pragma unroll
            for (int i = 0; i < 4; i++) c[mt][nt][i] = 0.0f;

    const int ar = t >> 1, ac = (t & 1) * 8;
    const int wr = t >> 4, wc = (t & 15) * 8;
    const int lq = lane >> 2;
    const int lr = lane & 3;

    for (int k0 = 0; k0 < K; k0 += GBK) {
        float4 a0 = make_float4(0.f,0.f,0.f,0.f), a1 = make_float4(0.f,0.f,0.f,0.f);
        if (bm + ar < M) {
            a0 = *(const float4*)&A[(size_t)(bm + ar) * K + k0 + ac];
            a1 = *(const float4*)&A[(size_t)(bm + ar) * K + k0 + ac + 4];
        }
        if (AIN) {
            a0.x = gelu_f(a0.x); a0.y = gelu_f(a0.y); a0.z = gelu_f(a0.z); a0.w = gelu_f(a0.w);
            a1.x = gelu_f(a1.x); a1.y = gelu_f(a1.y); a1.z = gelu_f(a1.z); a1.w = gelu_f(a1.w);
        }
        As[ar][ac + 0] = f2tf32(a0.x); As[ar][ac + 1] = f2tf32(a0.y);
        As[ar][ac + 2] = f2tf32(a0.z); As[ar][ac + 3] = f2tf32(a0.w);
        As[ar][ac + 4] = f2tf32(a1.x); As[ar][ac + 5] = f2tf32(a1.y);
        As[ar][ac + 6] = f2tf32(a1.z); As[ar][ac + 7] = f2tf32(a1.w);

        float4 w0 = *(const float4*)&W[(size_t)(k0 + wr) * N + bn + wc];
        float4 w1 = *(const float4*)&W[(size_t)(k0 + wr) * N + bn + wc + 4];
        Ws[wr][wc + 0] = f2tf32(w0.x); Ws[wr][wc + 1] = f2tf32(w0.y);
        Ws[wr][wc + 2] = f2tf32(w0.z); Ws[wr][wc + 3] = f2tf32(w0.w);
        Ws[wr][wc + 4] = f2tf32(w1.x); Ws[wr][wc + 5] = f2tf32(w1.y);
        Ws[wr][wc + 6] = f2tf32(w1.z); Ws[wr][wc + 7] = f2tf32(w1.w);

        __syncthreads();

        #pragma unroll
        for (int ks = 0; ks < GBK; ks += 8) {
            uint32_t af[4][4];
            #pragma unroll
            for (int mt = 0; mt < 4; mt++) {
                int r = wm + mt * 16 + lq;
                af[mt][0] = As[r    ][ks + lr];
                af[mt][1] = As[r + 8][ks + lr];
                af[mt][2] = As[r    ][ks + lr + 4];
                af[mt][3] = As[r + 8][ks + lr + 4];
            }
            uint32_t bf[4][2];
            #pragma unroll
            for (int nt = 0; nt < 4; nt++) {
                int nc = wn + nt * 8 + lq;
                bf[nt][0] = Ws[ks + lr    ][nc];
                bf[nt][1] = Ws[ks + lr + 4][nc];
            }
            #pragma unroll
            for (int mt = 0; mt < 4; mt++)
                #pragma unroll
                for (int nt = 0; nt < 4; nt++)
                    mma_tf32(c[mt][nt], af[mt][0], af[mt][1], af[mt][2], af[mt][3],
                             bf[nt][0], bf[nt][1]);
        }
        __syncthreads();
    }

    #pragma unroll
    for (int mt = 0; mt < 4; mt++) {
        int row0 = bm + wm + mt * 16 + lq;
        int row1 = row0 + 8;
        #pragma unroll
        for (int nt = 0; nt < 4; nt++) {
            int col = bn + wn + nt * 8 + lr * 2;
            float v0 = c[mt][nt][0], v1 = c[mt][nt][1];
            float v2 = c[mt][nt][2], v3 = c[mt][nt][3];
            if (BMODE == 1) {
                float b0 = bias[col], b1 = bias[col + 1];
                v0 += b0; v1 += b1; v2 += b0; v3 += b1;
            }
            if (BMODE == 2) {
                if (row0 < M) {
                    const float* bb = bias + (size_t)(row0 >> 9) * N + col;
                    v0 += bb[0]; v1 += bb[1];
                }
                if (row1 < M) {
                    const float* bb = bias + (size_t)(row1 >> 9) * N + col;
                    v2 += bb[0]; v3 += bb[1];
                }
            }
            if (AOUT) { v0 = gelu_f(v0); v1 = gelu_f(v1); v2 = gelu_f(v2); v3 = gelu_f(v3); }
            if (row0 < M) *(float2*)&C[(size_t)row0 * N + col] = make_float2(v0, v1);
            if (row1 < M) *(float2*)&C[(size_t)row1 * N + col] = make_float2(v2, v3);
        }
    }
}

template <int AIN, int AOUT, int BMODE>
__global__ __launch_bounds__(256) void gemm_tf32_kernel(
    const float* __restrict__ A, const float* __restrict__ W,
    const float* __restrict__ bias, float* __restrict__ C,
    int M, int N, int K)
{
    gemm_tf32_body<AIN, AOUT, BMODE>(A, W, bias, C, M, N, K,
                                     blockIdx.x * GBM, blockIdx.y * GBN);
}

__global__ __launch_bounds__(256) void gemm_tf32_qkv_kernel(
    const float* __restrict__ A,
    const float* __restrict__ W0, const float* __restrict__ W1, const float* __restrict__ W2,
    float* __restrict__ C0, float* __restrict__ C1, float* __restrict__ C2,
    int M, int N, int K)
{
    const float* W = (blockIdx.z == 0) ? W0 : (blockIdx.z == 1) ? W1 : W2;
    float*       C = (blockIdx.z == 0) ? C0 : (blockIdx.z == 1) ? C1 : C2;
    gemm_tf32_body<0, 0, 0>(A, W, nullptr, C, M, N, K,
                            blockIdx.x * GBM, blockIdx.y * GBN);
}

// ---------------------------------------------------------------------------
// Fused attention v7 — TENSOR CORE (tf32 m16n8k8) for QK^T and PV.
// 32 queries per block, 256 threads (8 warps), 2 CTAs/SM.
// QK: warp = (m-tile = w&1, 32-key range = (w>>1)*32 of each 128-key tile).
//     exp on MMA accumulators in registers; row sums in 2 regs; P stored to
//     smem once as tf32 bits (ready as PV A-operand).
// PV: warp = (m-tile = w&1, 8-dim tile = (w>>1)*8); 64 k8-step MMAs.
// smem layout (uint32 words):
//   qs[32][36] @0, ks[128][36] @1152, vs[128][40] @5760,
//   sc[32][516] @10880, rsp[8][16] @27392 (float), rs[32] @27520 (float)
// total 27552 words = 110208 B; 2 CTAs/SM fits (220 KB < 228 KB).
// Bank checks: qs/ks frag loads bank=(4*lq+lr) distinct; vs frag loads
// bank=(8*lr+lq) distinct; sc A-loads bank=(4*lq+lr) distinct.
// ---------------------------------------------------------------------------
#define SP 516
#define ATTN_SMEM_WORDS 27552
#define ATTN_SMEM_BYTES (ATTN_SMEM_WORDS * 4)

__global__ __launch_bounds__(256, 2) void attn_kernel(
    const float* __restrict__ Qp, const float* __restrict__ Kp,
    const float* __restrict__ Vp, float* __restrict__ Op)
{
    extern __shared__ uint32_t smu[];
    uint32_t* qs = smu;             // [32][36]  tf32 Q (prescaled)
    uint32_t* ks = smu + 1152;      // [128][36] tf32 K tile
    uint32_t* vs = smu + 5760;      // [128][40] tf32 V tile
    uint32_t* sc = smu + 10880;     // [32][516] tf32 exp(S)
    float*   rsp = (float*)(smu + 27392);  // [8][16] per-warp partial row sums
    float*   rs  = (float*)(smu + 27520);  // [32] row sums

    const int t    = threadIdx.x;
    const int lane = t & 31;
    const int w    = t >> 5;
    const int qb = blockIdx.x * 32;
    const int h  = blockIdx.y;
    const int b  = blockIdx.z;
    const float scale = 0.17677669529663688f;  // 1/sqrt(32)

    const size_t baseQ  = ((size_t)(b * NN + qb)) * DD + h * DKH;
    const size_t baseKV = ((size_t)(b * NN)) * DD + h * DKH;

    // stage Q (tf32, prescaled): 32 x 32, one float4 per thread
    {
        int r = t >> 3, c = (t & 7) * 4;
        float4 q4 = *(const float4*)&Qp[baseQ + (size_t)r * DD + c];
        *(uint4*)&qs[r * 36 + c] = make_uint4(
            f2tf32(q4.x * scale), f2tf32(q4.y * scale),
            f2tf32(q4.z * scale), f2tf32(q4.w * scale));
    }
    __syncthreads();

    const int lq = lane >> 2;      // 0..7
    const int lr = lane & 3;       // 0..3
    const int mb = (w & 1) * 16;   // m-tile base (query rows mb..mb+15)
    const int nqb = (w >> 1) * 32; // QK: key sub-range within a 128-key tile

    // Q fragments (persist across all key tiles): qa[kstep][4]
    uint32_t qa[4][4];
    #pragma unroll
    for (int kk = 0; kk < 4; kk++) {
        qa[kk][0] = qs[(mb + lq)     * 36 + kk * 8 + lr];
        qa[kk][1] = qs[(mb + 8 + lq) * 36 + kk * 8 + lr];
        qa[kk][2] = qs[(mb + lq)     * 36 + kk * 8 + lr + 4];
        qa[kk][3] = qs[(mb + 8 + lq) * 36 + kk * 8 + lr + 4];
    }

    float rlo = 0.0f, rhi = 0.0f;

    // ---- QK^T per 128-key tile: MMA -> exp in regs -> single STS (tf32) ----
    #pragma unroll 1
    for (int kt = 0; kt < 4; kt++) {
        const int kb = kt * 128;
        __syncthreads();
        for (int i = t; i < 1024; i += 256) {
            int r = i >> 3, c = (i & 7) * 4;
            float4 k4 = *(const float4*)&Kp[baseKV + (size_t)(kb + r) * DD + c];
            *(uint4*)&ks[r * 36 + c] = make_uint4(
                f2tf32(k4.x), f2tf32(k4.y), f2tf32(k4.z), f2tf32(k4.w));
        }
        __syncthreads();

        #pragma unroll
        for (int nt = 0; nt < 4; nt++) {
            const int nb = nqb + nt * 8;
            float c4[4] = {0.0f, 0.0f, 0.0f, 0.0f};
            #pragma unroll
            for (int kk = 0; kk < 4; kk++) {
                uint32_t b0 = ks[(nb + lq) * 36 + kk * 8 + lr];
                uint32_t b1 = ks[(nb + lq) * 36 + kk * 8 + lr + 4];
                mma_tf32(c4, qa[kk][0], qa[kk][1], qa[kk][2], qa[kk][3], b0, b1);
            }
            float e0 = fast_exp(c4[0]);
            float e1 = fast_exp(c4[1]);
            float e2 = fast_exp(c4[2]);
            float e3 = fast_exp(c4[3]);
            rlo += e0 + e1;
            rhi += e2 + e3;
            *(uint2*)&sc[(mb + lq)     * SP + kb + nb + 2 * lr] = make_uint2(f2tf32(e0), f2tf32(e1));
            *(uint2*)&sc[(mb + 8 + lq) * SP + kb + nb + 2 * lr] = make_uint2(f2tf32(e2), f2tf32(e3));
        }
    }

    // reduce row sums over lr lanes (lane = lq*4+lr; lr = low 2 bits)
    rlo += __shfl_xor_sync(0xFFFFFFFFu, rlo, 1);
    rlo += __shfl_xor_sync(0xFFFFFFFFu, rlo, 2);
    rhi += __shfl_xor_sync(0xFFFFFFFFu, rhi, 1);
    rhi += __shfl_xor_sync(0xFFFFFFFFu, rhi, 2);
    if (lr == 0) {
        rsp[w * 16 + lq]     = rlo;
        rsp[w * 16 + 8 + lq] = rhi;
    }
    __syncthreads();
    if (t < 32) {
        int mt = t >> 4, r = t & 15;   // global row = mt*16 + r
        rs[t] = rsp[mt * 16 + r] + rsp[(mt + 2) * 16 + r]
              + rsp[(mt + 4) * 16 + r] + rsp[(mt + 6) * 16 + r];
    }

    // ---- PV: warp = (m-tile, 8-dim tile); 64 k8-step MMAs ----
    const int nvb = (w >> 1) * 8;
    float oc[4] = {0.0f, 0.0f, 0.0f, 0.0f};

    #pragma unroll 1
    for (int kt = 0; kt < 4; kt++) {
        const int kb = kt * 128;
        __syncthreads();   // covers sc/rs writes on kt=0, vs reuse after
        for (int i = t; i < 1024; i += 256) {
            int r = i >> 3, c = (i & 7) * 4;
            float4 v4 = *(const float4*)&Vp[baseKV + (size_t)(kb + r) * DD + c];
            *(uint4*)&vs[r * 40 + c] = make_uint4(
                f2tf32(v4.x), f2tf32(v4.y), f2tf32(v4.z), f2tf32(v4.w));
        }
        __syncthreads();

        #pragma unroll
        for (int kk = 0; kk < 16; kk++) {
            const int kk8 = kk * 8;
            uint32_t a0 = sc[(mb + lq)     * SP + kb + kk8 + lr];
            uint32_t a1 = sc[(mb + 8 + lq) * SP + kb + kk8 + lr];
            uint32_t a2 = sc[(mb + lq)     * SP + kb + kk8 + lr + 4];
            uint32_t a3 = sc[(mb + 8 + lq) * SP + kb + kk8 + lr + 4];
            uint32_t b0 = vs[(kk8 + lr)     * 40 + nvb + lq];
            uint32_t b1 = vs[(kk8 + lr + 4) * 40 + nvb + lq];
            mma_tf32(oc, a0, a1, a2, a3, b0, b1);
        }
    }

    // epilogue: fold 1/rowsum, write float2
    {
        float inv0 = 1.0f / rs[mb + lq];
        float inv1 = 1.0f / rs[mb + 8 + lq];
        int col = nvb + 2 * lr;
        *(float2*)&Op[baseQ + (size_t)(mb + lq)     * DD + col] =
            make_float2(oc[0] * inv0, oc[1] * inv0);
        *(float2*)&Op[baseQ + (size_t)(mb + 8 + lq) * DD + col] =
            make_float2(oc[2] * inv1, oc[3] * inv1);
    }
}

// ---------------------------------------------------------------------------
__global__ __launch_bounds__(256) void colmean_gelu_kernel(
    const float* __restrict__ X, float* __restrict__ out)
{
    const int b = blockIdx.x;
    const int d = threadIdx.x;
    float s = 0.0f;
    const float* base = X + (size_t)b * NN * DD + d;
    for (int n = 0; n < NN; n++) s += base[(size_t)n * DD];
    out[b * DD + d] = gelu_f(s * (1.0f / (float)NN));
}

__global__ __launch_bounds__(256) void class_sum_kernel(
    const float* __restrict__ F, const int* __restrict__ lab,
    float* __restrict__ G, float* __restrict__ CNT)
{
    __shared__ float gs[CC * DD];
    __shared__ float cs[CC];
    const int b = blockIdx.x;
    const int t = threadIdx.x;
    for (int i = t; i < CC * DD; i += 256) gs[i] = 0.0f;
    if (t < CC) cs[t] = 0.0f;
    __syncthreads();
    for (int n = 0; n < NN; n++) {
        int c = lab[b * NN + n];
        gs[c * DD + t] += F[((size_t)b * NN + n) * DD + t];
        if (t == 0) cs[c] += 1.0f;
    }
    __syncthreads();
    for (int i = t; i < CC * DD; i += 256) G[(size_t)b * CC * DD + i] = gs[i];
    if (t < CC) CNT[b * CC + t] = cs[t];
}

__global__ __launch_bounds__(256) void proto_out_kernel(
    const float* __restrict__ F, const float* __restrict__ G,
    const float* __restrict__ CNT, const int* __restrict__ lab,
    float* __restrict__ out)
{
    __shared__ float fs[DD];
    const int n = blockIdx.x;
    const int b = blockIdx.y;
    const int t = threadIdx.x;
    fs[t] = F[((size_t)b * NN + n) * DD + t];
    __syncthreads();

    const int w = t >> 5, lane = t & 31;
    float sd = 0.0f;
    for (int i = lane; i < DD; i += 32) sd += fs[i] * fs[i];
    #pragma unroll
    for (int o = 16; o; o >>= 1) sd += __shfl_xor_sync(0xFFFFFFFFu, sd, o);

    const int labn = lab[b * NN + n];
    #pragma unroll
    for (int cc = 0; cc < 2; cc++) {
        const int c = w * 2 + cc;
        const float* g = G + (size_t)b * CC * DD + c * DD;
        float dp = 0.0f;
        for (int i = lane; i < DD; i += 32) dp += fs[i] * g[i];
        #pragma unroll
        for (int o = 16; o; o >>= 1) dp += __shfl_xor_sync(0xFFFFFFFFu, dp, o);
        if (lane == 0) {
            float same = (labn == c) ? 1.0f : 0.0f;
            out[((size_t)b * NN + n) * CC + c] =
                (dp - same * sd) / (CNT[b * CC + c] - same);
        }
    }
}

// ---------------------------------------------------------------------------
extern "C" void kernel_launch(void* const* d_in, const int* in_sizes, int n_in,
                              void* d_out, int out_size)
{
    const float* E    = (const float*)d_in[0];
    const int*   lab  = (const int*)  d_in[1];
    const float* Wq0  = (const float*)d_in[2];
    const float* Wk0  = (const float*)d_in[3];
    const float* Wv0  = (const float*)d_in[4];
    const float* Wo0  = (const float*)d_in[5];
    const float* Wq1  = (const float*)d_in[6];
    const float* Wk1  = (const float*)d_in[7];
    const float* Wv1  = (const float*)d_in[8];
    const float* Wo1  = (const float*)d_in[9];
    const float* resW = (const float*)d_in[10];
    const float* resb = (const float*)d_in[11];
    const float* ffW1 = (const float*)d_in[12];
    const float* ffb1 = (const float*)d_in[13];
    const float* ffW2 = (const float*)d_in[14];
    const float* ffb2 = (const float*)d_in[15];
    float* out = (float*)d_out;

    float *bQ, *bK, *bV, *bO, *bX, *aggrg, *ares, *rbias, *G, *CNT;
    cudaGetSymbolAddress((void**)&bQ,    g_bufQ);
    cudaGetSymbolAddress((void**)&bK,    g_bufK);
    cudaGetSymbolAddress((void**)&bV,    g_bufV);
    cudaGetSymbolAddress((void**)&bO,    g_bufO);
    cudaGetSymbolAddress((void**)&bX,    g_bufX);
    cudaGetSymbolAddress((void**)&aggrg, g_aggrg);
    cudaGetSymbolAddress((void**)&ares,  g_ares);
    cudaGetSymbolAddress((void**)&rbias, g_rbias);
    cudaGetSymbolAddress((void**)&G,     g_G);
    cudaGetSymbolAddress((void**)&CNT,   g_CNT);

    cudaFuncSetAttribute(attn_kernel,
                         cudaFuncAttributeMaxDynamicSharedMemorySize,
                         ATTN_SMEM_BYTES);

    const int M = BB * NN;                 // 8192
    dim3 gBig(M / GBM, DD / GBN);          // (64, 2)
    dim3 gQKV(M / GBM, DD / GBN, 3);       // (64, 2, 3)
    dim3 gSmall(1, DD / GBN);              // (1, 2)
    dim3 gAttn(NN / 32, HH, BB);           // (16, 8, 16)

    // ---- MHA 0 ----
    gemm_tf32_qkv_kernel<<<gQKV, 256>>>(E, Wq0, Wk0, Wv0, bQ, bK, bV, M, DD, DD);
    attn_kernel<<<gAttn, 256, ATTN_SMEM_BYTES>>>(bQ, bK, bV, bO);
    gemm_tf32_kernel<0, 1, 0><<<gBig, 256>>>(bO, Wo0, nullptr, bX, M, DD, DD);

    // ---- MHA 1 ----
    gemm_tf32_qkv_kernel<<<gQKV, 256>>>(bX, Wq1, Wk1, Wv1, bQ, bK, bV, M, DD, DD);
    attn_kernel<<<gAttn, 256, ATTN_SMEM_BYTES>>>(bQ, bK, bV, bO);
    gemm_tf32_kernel<0, 0, 0><<<gBig, 256>>>(bO, Wo1, nullptr, bX, M, DD, DD);

    // ---- aggregate path ----
    colmean_gelu_kernel<<<BB, 256>>>(bX, aggrg);
    gemm_tf32_kernel<0, 0, 1><<<gSmall, 256>>>(aggrg, resW, resb, ares, BB, DD, DD);
    gemm_tf32_kernel<1, 0, 1><<<gSmall, 256>>>(ares, ffW1, ffb1, rbias, BB, DD, DD);
    gemm_tf32_kernel<1, 1, 2><<<gBig, 256>>>(E, ffW1 + (size_t)DD * DD, rbias, bQ, M, DD, DD);
    gemm_tf32_kernel<0, 0, 1><<<gBig, 256>>>(bQ, ffW2, ffb2, bK, M, DD, DD);

    // ---- prototypical scoring ----
    class_sum_kernel<<<BB, 256>>>(bK, lab, G, CNT);
    proto_out_kernel<<<dim3(NN, BB), 256>>>(bK, G, CNT, lab, out);
}

// round 9
// speedup vs baseline: 1.7594x; 1.0613x over previous
#include <cuda_runtime.h>
#include <cuda_bf16.h>
#include <math.h>
#include <stdint.h>

// Shapes: B=16, N=512, D=256, H=8, DK=32, C=16
#define BB 16
#define NN 512
#define DD 256
#define HH 8
#define DKH 32
#define CC 16

__device__ float g_bufQ[BB * NN * DD];
__device__ float g_bufK[BB * NN * DD];
__device__ float g_bufV[BB * NN * DD];
__device__ float g_bufO[BB * NN * DD];
__device__ float g_bufX[BB * NN * DD];
__device__ float g_aggrg[BB * DD];
__device__ float g_ares[BB * DD];
__device__ float g_rbias[BB * DD];
__device__ float g_G[BB * CC * DD];
__device__ float g_CNT[BB * CC];

__device__ __forceinline__ float gelu_f(float x) {
    return 0.5f * x * (1.0f + erff(x * 0.7071067811865475f));
}

// exp(x) on the FMA/ALU pipes (no MUFU). ~1.2e-7 rel error.
__device__ __forceinline__ float fast_exp(float x) {
    float y = x * 1.4426950408889634f;
    y = fmaxf(y, -126.0f);
    float f = rintf(y);
    float z = y - f;
    float p = 1.5403530393381609e-4f;
    p = fmaf(p, z, 1.3333558146428443e-3f);
    p = fmaf(p, z, 9.6181291076284772e-3f);
    p = fmaf(p, z, 5.5504108664821580e-2f);
    p = fmaf(p, z, 2.4022650695910072e-1f);
    p = fmaf(p, z, 6.9314718055994531e-1f);
    p = fmaf(p, z, 1.0f);
    int e = (int)f;
    float s = __int_as_float((e + 127) << 23);
    return p * s;
}

__device__ __forceinline__ uint32_t f2tf32(float x) {
    uint32_t u;
    asm("cvt.rna.tf32.f32 %0, %1;" : "=r"(u) : "f"(x));
    return u;
}

__device__ __forceinline__ void mma_tf32(float c[4],
    uint32_t a0, uint32_t a1, uint32_t a2, uint32_t a3,
    uint32_t b0, uint32_t b1)
{
    asm volatile(
        "mma.sync.aligned.m16n8k8.row.col.f32.tf32.tf32.f32 "
        "{%0,%1,%2,%3},{%4,%5,%6,%7},{%8,%9},{%0,%1,%2,%3};"
        : "+f"(c[0]), "+f"(c[1]), "+f"(c[2]), "+f"(c[3])
        : "r"(a0), "r"(a1), "r"(a2), "r"(a3), "r"(b0), "r"(b1));
}

// ---------------------------------------------------------------------------
// tf32 tensor-core GEMM, DOUBLE-BUFFERED (reg prefetch, 1 sync/iter).
// Block 128x128, BK=16, 256 threads = 8 warps of 64x32 warp-tiles.
// TF32OUT: store tf32-rounded bits (scaled by oscale) for attention inputs.
// ---------------------------------------------------------------------------
#define GBM 128
#define GBN 128
#define GBK 16

template <int AIN, int AOUT, int BMODE, int TF32OUT>
__device__ __forceinline__ void gemm_tf32_body(
    const float* __restrict__ A, const float* __restrict__ W,
    const float* __restrict__ bias, float* __restrict__ C,
    int M, int N, int K, int bm, int bn, float oscale)
{
    __shared__ uint32_t As[2][GBM][GBK + 4];
    __shared__ uint32_t Ws[2][GBK][GBN + 8];

    const int t    = threadIdx.x;
    const int lane = t & 31;
    const int wid  = t >> 5;
    const int wm   = (wid & 1) * 64;
    const int wn   = (wid >> 1) * 32;

    const int ar = t >> 1, ac = (t & 1) * 8;
    const int wr = t >> 4, wc = (t & 15) * 8;
    const int lq = lane >> 2;
    const int lr = lane & 3;

    float c[4][4][4];
    #pragma unroll
    for (int mt = 0; mt < 4; mt++)
        #pragma unroll
        for (int nt = 0; nt < 4; nt++)
            #pragma unroll
            for (int i = 0; i < 4; i++) c[mt][nt][i] = 0.0f;

    const int NIT = K / GBK;

    // ---- stage 0 load directly into buffer 0 ----
    {
        float4 a0 = make_float4(0.f,0.f,0.f,0.f), a1 = make_float4(0.f,0.f,0.f,0.f);
        if (bm + ar < M) {
            a0 = *(const float4*)&A[(size_t)(bm + ar) * K + ac];
            a1 = *(const float4*)&A[(size_t)(bm + ar) * K + ac + 4];
        }
        if (AIN) {
            a0.x = gelu_f(a0.x); a0.y = gelu_f(a0.y); a0.z = gelu_f(a0.z); a0.w = gelu_f(a0.w);
            a1.x = gelu_f(a1.x); a1.y = gelu_f(a1.y); a1.z = gelu_f(a1.z); a1.w = gelu_f(a1.w);
        }
        As[0][ar][ac + 0] = f2tf32(a0.x); As[0][ar][ac + 1] = f2tf32(a0.y);
        As[0][ar][ac + 2] = f2tf32(a0.z); As[0][ar][ac + 3] = f2tf32(a0.w);
        As[0][ar][ac + 4] = f2tf32(a1.x); As[0][ar][ac + 5] = f2tf32(a1.y);
        As[0][ar][ac + 6] = f2tf32(a1.z); As[0][ar][ac + 7] = f2tf32(a1.w);

        float4 w0 = *(const float4*)&W[(size_t)wr * N + bn + wc];
        float4 w1 = *(const float4*)&W[(size_t)wr * N + bn + wc + 4];
        Ws[0][wr][wc + 0] = f2tf32(w0.x); Ws[0][wr][wc + 1] = f2tf32(w0.y);
        Ws[0][wr][wc + 2] = f2tf32(w0.z); Ws[0][wr][wc + 3] = f2tf32(w0.w);
        Ws[0][wr][wc + 4] = f2tf32(w1.x); Ws[0][wr][wc + 5] = f2tf32(w1.y);
        Ws[0][wr][wc + 6] = f2tf32(w1.z); Ws[0][wr][wc + 7] = f2tf32(w1.w);
    }
    __syncthreads();

    for (int it = 0; it < NIT; it++) {
        const int cur = it & 1, nxt = cur ^ 1;
        const bool has = (it + 1 < NIT);
        const int k0n = (it + 1) * GBK;

        // issue next-tile LDGs early (latency hidden by MMAs below)
        float4 na0, na1, nw0, nw1;
        if (has) {
            na0 = make_float4(0.f,0.f,0.f,0.f); na1 = na0;
            if (bm + ar < M) {
                na0 = *(const float4*)&A[(size_t)(bm + ar) * K + k0n + ac];
                na1 = *(const float4*)&A[(size_t)(bm + ar) * K + k0n + ac + 4];
            }
            nw0 = *(const float4*)&W[(size_t)(k0n + wr) * N + bn + wc];
            nw1 = *(const float4*)&W[(size_t)(k0n + wr) * N + bn + wc + 4];
        }

        // MMAs on current buffer
        #pragma unroll
        for (int ks = 0; ks < GBK; ks += 8) {
            uint32_t af[4][4];
            #pragma unroll
            for (int mt = 0; mt < 4; mt++) {
                int r = wm + mt * 16 + lq;
                af[mt][0] = As[cur][r    ][ks + lr];
                af[mt][1] = As[cur][r + 8][ks + lr];
                af[mt][2] = As[cur][r    ][ks + lr + 4];
                af[mt][3] = As[cur][r + 8][ks + lr + 4];
            }
            uint32_t bf[4][2];
            #pragma unroll
            for (int nt = 0; nt < 4; nt++) {
                int nc = wn + nt * 8 + lq;
                bf[nt][0] = Ws[cur][ks + lr    ][nc];
                bf[nt][1] = Ws[cur][ks + lr + 4][nc];
            }
            #pragma unroll
            for (int mt = 0; mt < 4; mt++)
                #pragma unroll
                for (int nt = 0; nt < 4; nt++)
                    mma_tf32(c[mt][nt], af[mt][0], af[mt][1], af[mt][2], af[mt][3],
                             bf[nt][0], bf[nt][1]);
        }

        if (has) {
            if (AIN) {
                na0.x = gelu_f(na0.x); na0.y = gelu_f(na0.y); na0.z = gelu_f(na0.z); na0.w = gelu_f(na0.w);
                na1.x = gelu_f(na1.x); na1.y = gelu_f(na1.y); na1.z = gelu_f(na1.z); na1.w = gelu_f(na1.w);
            }
            As[nxt][ar][ac + 0] = f2tf32(na0.x); As[nxt][ar][ac + 1] = f2tf32(na0.y);
            As[nxt][ar][ac + 2] = f2tf32(na0.z); As[nxt][ar][ac + 3] = f2tf32(na0.w);
            As[nxt][ar][ac + 4] = f2tf32(na1.x); As[nxt][ar][ac + 5] = f2tf32(na1.y);
            As[nxt][ar][ac + 6] = f2tf32(na1.z); As[nxt][ar][ac + 7] = f2tf32(na1.w);
            Ws[nxt][wr][wc + 0] = f2tf32(nw0.x); Ws[nxt][wr][wc + 1] = f2tf32(nw0.y);
            Ws[nxt][wr][wc + 2] = f2tf32(nw0.z); Ws[nxt][wr][wc + 3] = f2tf32(nw0.w);
            Ws[nxt][wr][wc + 4] = f2tf32(nw1.x); Ws[nxt][wr][wc + 5] = f2tf32(nw1.y);
            Ws[nxt][wr][wc + 6] = f2tf32(nw1.z); Ws[nxt][wr][wc + 7] = f2tf32(nw1.w);
            __syncthreads();
        }
    }

    // epilogue
    #pragma unroll
    for (int mt = 0; mt < 4; mt++) {
        int row0 = bm + wm + mt * 16 + lq;
        int row1 = row0 + 8;
        #pragma unroll
        for (int nt = 0; nt < 4; nt++) {
            int col = bn + wn + nt * 8 + lr * 2;
            float v0 = c[mt][nt][0], v1 = c[mt][nt][1];
            float v2 = c[mt][nt][2], v3 = c[mt][nt][3];
            if (BMODE == 1) {
                float b0 = bias[col], b1 = bias[col + 1];
                v0 += b0; v1 += b1; v2 += b0; v3 += b1;
            }
            if (BMODE == 2) {
                if (row0 < M) {
                    const float* bb = bias + (size_t)(row0 >> 9) * N + col;
                    v0 += bb[0]; v1 += bb[1];
                }
                if (row1 < M) {
                    const float* bb = bias + (size_t)(row1 >> 9) * N + col;
                    v2 += bb[0]; v3 += bb[1];
                }
            }
            if (AOUT) { v0 = gelu_f(v0); v1 = gelu_f(v1); v2 = gelu_f(v2); v3 = gelu_f(v3); }
            if (TF32OUT) {
                v0 = __uint_as_float(f2tf32(v0 * oscale));
                v1 = __uint_as_float(f2tf32(v1 * oscale));
                v2 = __uint_as_float(f2tf32(v2 * oscale));
                v3 = __uint_as_float(f2tf32(v3 * oscale));
            }
            if (row0 < M) *(float2*)&C[(size_t)row0 * N + col] = make_float2(v0, v1);
            if (row1 < M) *(float2*)&C[(size_t)row1 * N + col] = make_float2(v2, v3);
        }
    }
}

template <int AIN, int AOUT, int BMODE>
__global__ __launch_bounds__(256) void gemm_tf32_kernel(
    const float* __restrict__ A, const float* __restrict__ W,
    const float* __restrict__ bias, float* __restrict__ C,
    int M, int N, int K)
{
    gemm_tf32_body<AIN, AOUT, BMODE, 0>(A, W, bias, C, M, N, K,
                                        blockIdx.x * GBM, blockIdx.y * GBN, 1.0f);
}

// QKV fused: gridDim.z selects W and C; outputs tf32-rounded, Q prescaled.
__global__ __launch_bounds__(256) void gemm_tf32_qkv_kernel(
    const float* __restrict__ A,
    const float* __restrict__ W0, const float* __restrict__ W1, const float* __restrict__ W2,
    float* __restrict__ C0, float* __restrict__ C1, float* __restrict__ C2,
    int M, int N, int K)
{
    const float* W = (blockIdx.z == 0) ? W0 : (blockIdx.z == 1) ? W1 : W2;
    float*       C = (blockIdx.z == 0) ? C0 : (blockIdx.z == 1) ? C1 : C2;
    const float oscale = (blockIdx.z == 0) ? 0.17677669529663688f : 1.0f; // Q pre-scaled
    gemm_tf32_body<0, 0, 0, 1>(A, W, nullptr, C, M, N, K,
                               blockIdx.x * GBM, blockIdx.y * GBN, oscale);
}

// ---------------------------------------------------------------------------
// Fused attention v8 — tf32 m16n8k8 for QK^T and PV; inputs arrive ALREADY
// tf32-rounded (and Q prescaled) from the QKV GEMM epilogue, so staging is
// pure uint4 copies (no CVT).
// smem layout (uint32 words): qs[32][36] @0, ks[128][36] @1152,
//   vs[128][40] @5760, sc[32][516] @10880, rsp[8][16] @27392, rs[32] @27520.
// total 27552 words = 110208 B; 2 CTAs/SM.
// ---------------------------------------------------------------------------
#define SP 516
#define ATTN_SMEM_WORDS 27552
#define ATTN_SMEM_BYTES (ATTN_SMEM_WORDS * 4)

__global__ __launch_bounds__(256, 2) void attn_kernel(
    const float* __restrict__ Qp, const float* __restrict__ Kp,
    const float* __restrict__ Vp, float* __restrict__ Op)
{
    extern __shared__ uint32_t smu[];
    uint32_t* qs = smu;             // [32][36]  tf32 Q (prescaled)
    uint32_t* ks = smu + 1152;      // [128][36] tf32 K tile
    uint32_t* vs = smu + 5760;      // [128][40] tf32 V tile
    uint32_t* sc = smu + 10880;     // [32][516] tf32 exp(S)
    float*   rsp = (float*)(smu + 27392);
    float*   rs  = (float*)(smu + 27520);

    const int t    = threadIdx.x;
    const int lane = t & 31;
    const int w    = t >> 5;
    const int qb = blockIdx.x * 32;
    const int h  = blockIdx.y;
    const int b  = blockIdx.z;

    const size_t baseQ  = ((size_t)(b * NN + qb)) * DD + h * DKH;
    const size_t baseKV = ((size_t)(b * NN)) * DD + h * DKH;

    // stage Q: raw bit copy (already tf32 + prescaled)
    {
        int r = t >> 3, c = (t & 7) * 4;
        *(uint4*)&qs[r * 36 + c] = *(const uint4*)&Qp[baseQ + (size_t)r * DD + c];
    }
    __syncthreads();

    const int lq = lane >> 2;
    const int lr = lane & 3;
    const int mb = (w & 1) * 16;
    const int nqb = (w >> 1) * 32;

    uint32_t qa[4][4];
    #pragma unroll
    for (int kk = 0; kk < 4; kk++) {
        qa[kk][0] = qs[(mb + lq)     * 36 + kk * 8 + lr];
        qa[kk][1] = qs[(mb + 8 + lq) * 36 + kk * 8 + lr];
        qa[kk][2] = qs[(mb + lq)     * 36 + kk * 8 + lr + 4];
        qa[kk][3] = qs[(mb + 8 + lq) * 36 + kk * 8 + lr + 4];
    }

    float rlo = 0.0f, rhi = 0.0f;

    // ---- QK^T per 128-key tile: MMA -> exp in regs -> single STS (tf32) ----
    #pragma unroll 1
    for (int kt = 0; kt < 4; kt++) {
        const int kb = kt * 128;
        __syncthreads();
        for (int i = t; i < 1024; i += 256) {
            int r = i >> 3, c = (i & 7) * 4;
            *(uint4*)&ks[r * 36 + c] =
                *(const uint4*)&Kp[baseKV + (size_t)(kb + r) * DD + c];
        }
        __syncthreads();

        #pragma unroll
        for (int nt = 0; nt < 4; nt++) {
            const int nb = nqb + nt * 8;
            float c4[4] = {0.0f, 0.0f, 0.0f, 0.0f};
            #pragma unroll
            for (int kk = 0; kk < 4; kk++) {
                uint32_t b0 = ks[(nb + lq) * 36 + kk * 8 + lr];
                uint32_t b1 = ks[(nb + lq) * 36 + kk * 8 + lr + 4];
                mma_tf32(c4, qa[kk][0], qa[kk][1], qa[kk][2], qa[kk][3], b0, b1);
            }
            float e0 = fast_exp(c4[0]);
            float e1 = fast_exp(c4[1]);
            float e2 = fast_exp(c4[2]);
            float e3 = fast_exp(c4[3]);
            rlo += e0 + e1;
            rhi += e2 + e3;
            *(uint2*)&sc[(mb + lq)     * SP + kb + nb + 2 * lr] = make_uint2(f2tf32(e0), f2tf32(e1));
            *(uint2*)&sc[(mb + 8 + lq) * SP + kb + nb + 2 * lr] = make_uint2(f2tf32(e2), f2tf32(e3));
        }
    }

    rlo += __shfl_xor_sync(0xFFFFFFFFu, rlo, 1);
    rlo += __shfl_xor_sync(0xFFFFFFFFu, rlo, 2);
    rhi += __shfl_xor_sync(0xFFFFFFFFu, rhi, 1);
    rhi += __shfl_xor_sync(0xFFFFFFFFu, rhi, 2);
    if (lr == 0) {
        rsp[w * 16 + lq]     = rlo;
        rsp[w * 16 + 8 + lq] = rhi;
    }
    __syncthreads();
    if (t < 32) {
        int mt = t >> 4, r = t & 15;
        rs[t] = rsp[mt * 16 + r] + rsp[(mt + 2) * 16 + r]
              + rsp[(mt + 4) * 16 + r] + rsp[(mt + 6) * 16 + r];
    }

    // ---- PV ----
    const int nvb = (w >> 1) * 8;
    float oc[4] = {0.0f, 0.0f, 0.0f, 0.0f};

    #pragma unroll 1
    for (int kt = 0; kt < 4; kt++) {
        const int kb = kt * 128;
        __syncthreads();
        for (int i = t; i < 1024; i += 256) {
            int r = i >> 3, c = (i & 7) * 4;
            *(uint4*)&vs[r * 40 + c] =
                *(const uint4*)&Vp[baseKV + (size_t)(kb + r) * DD + c];
        }
        __syncthreads();

        #pragma unroll
        for (int kk = 0; kk < 16; kk++) {
            const int kk8 = kk * 8;
            uint32_t a0 = sc[(mb + lq)     * SP + kb + kk8 + lr];
            uint32_t a1 = sc[(mb + 8 + lq) * SP + kb + kk8 + lr];
            uint32_t a2 = sc[(mb + lq)     * SP + kb + kk8 + lr + 4];
            uint32_t a3 = sc[(mb + 8 + lq) * SP + kb + kk8 + lr + 4];
            uint32_t b0 = vs[(kk8 + lr)     * 40 + nvb + lq];
            uint32_t b1 = vs[(kk8 + lr + 4) * 40 + nvb + lq];
            mma_tf32(oc, a0, a1, a2, a3, b0, b1);
        }
    }

    {
        float inv0 = 1.0f / rs[mb + lq];
        float inv1 = 1.0f / rs[mb + 8 + lq];
        int col = nvb + 2 * lr;
        *(float2*)&Op[baseQ + (size_t)(mb + lq)     * DD + col] =
            make_float2(oc[0] * inv0, oc[1] * inv0);
        *(float2*)&Op[baseQ + (size_t)(mb + 8 + lq) * DD + col] =
            make_float2(oc[2] * inv1, oc[3] * inv1);
    }
}

// ---------------------------------------------------------------------------
__global__ __launch_bounds__(256) void colmean_gelu_kernel(
    const float* __restrict__ X, float* __restrict__ out)
{
    const int b = blockIdx.x;
    const int d = threadIdx.x;
    float s = 0.0f;
    const float* base = X + (size_t)b * NN * DD + d;
    for (int n = 0; n < NN; n++) s += base[(size_t)n * DD];
    out[b * DD + d] = gelu_f(s * (1.0f / (float)NN));
}

__global__ __launch_bounds__(256) void class_sum_kernel(
    const float* __restrict__ F, const int* __restrict__ lab,
    float* __restrict__ G, float* __restrict__ CNT)
{
    __shared__ float gs[CC * DD];
    __shared__ float cs[CC];
    const int b = blockIdx.x;
    const int t = threadIdx.x;
    for (int i = t; i < CC * DD; i += 256) gs[i] = 0.0f;
    if (t < CC) cs[t] = 0.0f;
    __syncthreads();
    for (int n = 0; n < NN; n++) {
        int c = lab[b * NN + n];
        gs[c * DD + t] += F[((size_t)b * NN + n) * DD + t];
        if (t == 0) cs[c] += 1.0f;
    }
    __syncthreads();
    for (int i = t; i < CC * DD; i += 256) G[(size_t)b * CC * DD + i] = gs[i];
    if (t < CC) CNT[b * CC + t] = cs[t];
}

__global__ __launch_bounds__(256) void proto_out_kernel(
    const float* __restrict__ F, const float* __restrict__ G,
    const float* __restrict__ CNT, const int* __restrict__ lab,
    float* __restrict__ out)
{
    __shared__ float fs[DD];
    const int n = blockIdx.x;
    const int b = blockIdx.y;
    const int t = threadIdx.x;
    fs[t] = F[((size_t)b * NN + n) * DD + t];
    __syncthreads();

    const int w = t >> 5, lane = t & 31;
    float sd = 0.0f;
    for (int i = lane; i < DD; i += 32) sd += fs[i] * fs[i];
    #pragma unroll
    for (int o = 16; o; o >>= 1) sd += __shfl_xor_sync(0xFFFFFFFFu, sd, o);

    const int labn = lab[b * NN + n];
    #pragma unroll
    for (int cc = 0; cc < 2; cc++) {
        const int c = w * 2 + cc;
        const float* g = G + (size_t)b * CC * DD + c * DD;
        float dp = 0.0f;
        for (int i = lane; i < DD; i += 32) dp += fs[i] * g[i];
        #pragma unroll
        for (int o = 16; o; o >>= 1) dp += __shfl_xor_sync(0xFFFFFFFFu, dp, o);
        if (lane == 0) {
            float same = (labn == c) ? 1.0f : 0.0f;
            out[((size_t)b * NN + n) * CC + c] =
                (dp - same * sd) / (CNT[b * CC + c] - same);
        }
    }
}

// ---------------------------------------------------------------------------
extern "C" void kernel_launch(void* const* d_in, const int* in_sizes, int n_in,
                              void* d_out, int out_size)
{
    const float* E    = (const float*)d_in[0];
    const int*   lab  = (const int*)  d_in[1];
    const float* Wq0  = (const float*)d_in[2];
    const float* Wk0  = (const float*)d_in[3];
    const float* Wv0  = (const float*)d_in[4];
    const float* Wo0  = (const float*)d_in[5];
    const float* Wq1  = (const float*)d_in[6];
    const float* Wk1  = (const float*)d_in[7];
    const float* Wv1  = (const float*)d_in[8];
    const float* Wo1  = (const float*)d_in[9];
    const float* resW = (const float*)d_in[10];
    const float* resb = (const float*)d_in[11];
    const float* ffW1 = (const float*)d_in[12];
    const float* ffb1 = (const float*)d_in[13];
    const float* ffW2 = (const float*)d_in[14];
    const float* ffb2 = (const float*)d_in[15];
    float* out = (float*)d_out;

    float *bQ, *bK, *bV, *bO, *bX, *aggrg, *ares, *rbias, *G, *CNT;
    cudaGetSymbolAddress((void**)&bQ,    g_bufQ);
    cudaGetSymbolAddress((void**)&bK,    g_bufK);
    cudaGetSymbolAddress((void**)&bV,    g_bufV);
    cudaGetSymbolAddress((void**)&bO,    g_bufO);
    cudaGetSymbolAddress((void**)&bX,    g_bufX);
    cudaGetSymbolAddress((void**)&aggrg, g_aggrg);
    cudaGetSymbolAddress((void**)&ares,  g_ares);
    cudaGetSymbolAddress((void**)&rbias, g_rbias);
    cudaGetSymbolAddress((void**)&G,     g_G);
    cudaGetSymbolAddress((void**)&CNT,   g_CNT);

    cudaFuncSetAttribute(attn_kernel,
                         cudaFuncAttributeMaxDynamicSharedMemorySize,
                         ATTN_SMEM_BYTES);

    const int M = BB * NN;                 // 8192
    dim3 gBig(M / GBM, DD / GBN);          // (64, 2)
    dim3 gQKV(M / GBM, DD / GBN, 3);       // (64, 2, 3)
    dim3 gSmall(1, DD / GBN);              // (1, 2)
    dim3 gAttn(NN / 32, HH, BB);           // (16, 8, 16)

    // ---- MHA 0 ----
    gemm_tf32_qkv_kernel<<<gQKV, 256>>>(E, Wq0, Wk0, Wv0, bQ, bK, bV, M, DD, DD);
    attn_kernel<<<gAttn, 256, ATTN_SMEM_BYTES>>>(bQ, bK, bV, bO);
    gemm_tf32_kernel<0, 1, 0><<<gBig, 256>>>(bO, Wo0, nullptr, bX, M, DD, DD);

    // ---- MHA 1 ----
    gemm_tf32_qkv_kernel<<<gQKV, 256>>>(bX, Wq1, Wk1, Wv1, bQ, bK, bV, M, DD, DD);
    attn_kernel<<<gAttn, 256, ATTN_SMEM_BYTES>>>(bQ, bK, bV, bO);
    gemm_tf32_kernel<0, 0, 0><<<gBig, 256>>>(bO, Wo1, nullptr, bX, M, DD, DD);

    // ---- aggregate path ----
    colmean_gelu_kernel<<<BB, 256>>>(bX, aggrg);
    gemm_tf32_kernel<0, 0, 1><<<gSmall, 256>>>(aggrg, resW, resb, ares, BB, DD, DD);
    gemm_tf32_kernel<1, 0, 1><<<gSmall, 256>>>(ares, ffW1, ffb1, rbias, BB, DD, DD);
    gemm_tf32_kernel<1, 1, 2><<<gBig, 256>>>(E, ffW1 + (size_t)DD * DD, rbias, bQ, M, DD, DD);
    gemm_tf32_kernel<0, 0, 1><<<gBig, 256>>>(bQ, ffW2, ffb2, bK, M, DD, DD);

    // ---- prototypical scoring ----
    class_sum_kernel<<<BB, 256>>>(bK, lab, G, CNT);
    proto_out_kernel<<<dim3(NN, BB), 256>>>(bK, G, CNT, lab, out);
}

// round 10
// speedup vs baseline: 1.9377x; 1.1013x over previous
#include <cuda_runtime.h>
#include <cuda_bf16.h>
#include <math.h>
#include <stdint.h>

// Shapes: B=16, N=512, D=256, H=8, DK=32, C=16
#define BB 16
#define NN 512
#define DD 256
#define HH 8
#define DKH 32
#define CC 16

__device__ float g_bufQ[BB * NN * DD];
__device__ float g_bufK[BB * NN * DD];
__device__ float g_bufV[BB * NN * DD];
__device__ float g_bufO[BB * NN * DD];
__device__ float g_bufX[BB * NN * DD];
__device__ float g_rbias[BB * DD];
__device__ float g_G[BB * CC * DD];
__device__ float g_CNT[BB * CC];

__device__ __forceinline__ float gelu_f(float x) {
    return 0.5f * x * (1.0f + erff(x * 0.7071067811865475f));
}

// exp(x) on the FMA/ALU pipes (no MUFU). ~1.2e-7 rel error.
__device__ __forceinline__ float fast_exp(float x) {
    float y = x * 1.4426950408889634f;
    y = fmaxf(y, -126.0f);
    float f = rintf(y);
    float z = y - f;
    float p = 1.5403530393381609e-4f;
    p = fmaf(p, z, 1.3333558146428443e-3f);
    p = fmaf(p, z, 9.6181291076284772e-3f);
    p = fmaf(p, z, 5.5504108664821580e-2f);
    p = fmaf(p, z, 2.4022650695910072e-1f);
    p = fmaf(p, z, 6.9314718055994531e-1f);
    p = fmaf(p, z, 1.0f);
    int e = (int)f;
    float s = __int_as_float((e + 127) << 23);
    return p * s;
}

__device__ __forceinline__ uint32_t f2tf32(float x) {
    uint32_t u;
    asm("cvt.rna.tf32.f32 %0, %1;" : "=r"(u) : "f"(x));
    return u;
}

__device__ __forceinline__ void mma_tf32(float c[4],
    uint32_t a0, uint32_t a1, uint32_t a2, uint32_t a3,
    uint32_t b0, uint32_t b1)
{
    asm volatile(
        "mma.sync.aligned.m16n8k8.row.col.f32.tf32.tf32.f32 "
        "{%0,%1,%2,%3},{%4,%5,%6,%7},{%8,%9},{%0,%1,%2,%3};"
        : "+f"(c[0]), "+f"(c[1]), "+f"(c[2]), "+f"(c[3])
        : "r"(a0), "r"(a1), "r"(a2), "r"(a3), "r"(b0), "r"(b1));
}

// ---------------------------------------------------------------------------
// tf32 tensor-core GEMM, double-buffered (unchanged from R9)
// ---------------------------------------------------------------------------
#define GBM 128
#define GBN 128
#define GBK 16

template <int AIN, int AOUT, int BMODE, int TF32OUT>
__device__ __forceinline__ void gemm_tf32_body(
    const float* __restrict__ A, const float* __restrict__ W,
    const float* __restrict__ bias, float* __restrict__ C,
    int M, int N, int K, int bm, int bn, float oscale)
{
    __shared__ uint32_t As[2][GBM][GBK + 4];
    __shared__ uint32_t Ws[2][GBK][GBN + 8];

    const int t    = threadIdx.x;
    const int lane = t & 31;
    const int wid  = t >> 5;
    const int wm   = (wid & 1) * 64;
    const int wn   = (wid >> 1) * 32;

    const int ar = t >> 1, ac = (t & 1) * 8;
    const int wr = t >> 4, wc = (t & 15) * 8;
    const int lq = lane >> 2;
    const int lr = lane & 3;

    float c[4][4][4];
    #pragma unroll
    for (int mt = 0; mt < 4; mt++)
        #pragma unroll
        for (int nt = 0; nt < 4; nt++)
            #pragma unroll
            for (int i = 0; i < 4; i++) c[mt][nt][i] = 0.0f;

    const int NIT = K / GBK;

    {
        float4 a0 = make_float4(0.f,0.f,0.f,0.f), a1 = make_float4(0.f,0.f,0.f,0.f);
        if (bm + ar < M) {
            a0 = *(const float4*)&A[(size_t)(bm + ar) * K + ac];
            a1 = *(const float4*)&A[(size_t)(bm + ar) * K + ac + 4];
        }
        if (AIN) {
            a0.x = gelu_f(a0.x); a0.y = gelu_f(a0.y); a0.z = gelu_f(a0.z); a0.w = gelu_f(a0.w);
            a1.x = gelu_f(a1.x); a1.y = gelu_f(a1.y); a1.z = gelu_f(a1.z); a1.w = gelu_f(a1.w);
        }
        As[0][ar][ac + 0] = f2tf32(a0.x); As[0][ar][ac + 1] = f2tf32(a0.y);
        As[0][ar][ac + 2] = f2tf32(a0.z); As[0][ar][ac + 3] = f2tf32(a0.w);
        As[0][ar][ac + 4] = f2tf32(a1.x); As[0][ar][ac + 5] = f2tf32(a1.y);
        As[0][ar][ac + 6] = f2tf32(a1.z); As[0][ar][ac + 7] = f2tf32(a1.w);

        float4 w0 = *(const float4*)&W[(size_t)wr * N + bn + wc];
        float4 w1 = *(const float4*)&W[(size_t)wr * N + bn + wc + 4];
        Ws[0][wr][wc + 0] = f2tf32(w0.x); Ws[0][wr][wc + 1] = f2tf32(w0.y);
        Ws[0][wr][wc + 2] = f2tf32(w0.z); Ws[0][wr][wc + 3] = f2tf32(w0.w);
        Ws[0][wr][wc + 4] = f2tf32(w1.x); Ws[0][wr][wc + 5] = f2tf32(w1.y);
        Ws[0][wr][wc + 6] = f2tf32(w1.z); Ws[0][wr][wc + 7] = f2tf32(w1.w);
    }
    __syncthreads();

    for (int it = 0; it < NIT; it++) {
        const int cur = it & 1, nxt = cur ^ 1;
        const bool has = (it + 1 < NIT);
        const int k0n = (it + 1) * GBK;

        float4 na0, na1, nw0, nw1;
        if (has) {
            na0 = make_float4(0.f,0.f,0.f,0.f); na1 = na0;
            if (bm + ar < M) {
                na0 = *(const float4*)&A[(size_t)(bm + ar) * K + k0n + ac];
                na1 = *(const float4*)&A[(size_t)(bm + ar) * K + k0n + ac + 4];
            }
            nw0 = *(const float4*)&W[(size_t)(k0n + wr) * N + bn + wc];
            nw1 = *(const float4*)&W[(size_t)(k0n + wr) * N + bn + wc + 4];
        }

        #pragma unroll
        for (int ks = 0; ks < GBK; ks += 8) {
            uint32_t af[4][4];
            #pragma unroll
            for (int mt = 0; mt < 4; mt++) {
                int r = wm + mt * 16 + lq;
                af[mt][0] = As[cur][r    ][ks + lr];
                af[mt][1] = As[cur][r + 8][ks + lr];
                af[mt][2] = As[cur][r    ][ks + lr + 4];
                af[mt][3] = As[cur][r + 8][ks + lr + 4];
            }
            uint32_t bf[4][2];
            #pragma unroll
            for (int nt = 0; nt < 4; nt++) {
                int nc = wn + nt * 8 + lq;
                bf[nt][0] = Ws[cur][ks + lr    ][nc];
                bf[nt][1] = Ws[cur][ks + lr + 4][nc];
            }
            #pragma unroll
            for (int mt = 0; mt < 4; mt++)
                #pragma unroll
                for (int nt = 0; nt < 4; nt++)
                    mma_tf32(c[mt][nt], af[mt][0], af[mt][1], af[mt][2], af[mt][3],
                             bf[nt][0], bf[nt][1]);
        }

        if (has) {
            if (AIN) {
                na0.x = gelu_f(na0.x); na0.y = gelu_f(na0.y); na0.z = gelu_f(na0.z); na0.w = gelu_f(na0.w);
                na1.x = gelu_f(na1.x); na1.y = gelu_f(na1.y); na1.z = gelu_f(na1.z); na1.w = gelu_f(na1.w);
            }
            As[nxt][ar][ac + 0] = f2tf32(na0.x); As[nxt][ar][ac + 1] = f2tf32(na0.y);
            As[nxt][ar][ac + 2] = f2tf32(na0.z); As[nxt][ar][ac + 3] = f2tf32(na0.w);
            As[nxt][ar][ac + 4] = f2tf32(na1.x); As[nxt][ar][ac + 5] = f2tf32(na1.y);
            As[nxt][ar][ac + 6] = f2tf32(na1.z); As[nxt][ar][ac + 7] = f2tf32(na1.w);
            Ws[nxt][wr][wc + 0] = f2tf32(nw0.x); Ws[nxt][wr][wc + 1] = f2tf32(nw0.y);
            Ws[nxt][wr][wc + 2] = f2tf32(nw0.z); Ws[nxt][wr][wc + 3] = f2tf32(nw0.w);
            Ws[nxt][wr][wc + 4] = f2tf32(nw1.x); Ws[nxt][wr][wc + 5] = f2tf32(nw1.y);
            Ws[nxt][wr][wc + 6] = f2tf32(nw1.z); Ws[nxt][wr][wc + 7] = f2tf32(nw1.w);
            __syncthreads();
        }
    }

    #pragma unroll
    for (int mt = 0; mt < 4; mt++) {
        int row0 = bm + wm + mt * 16 + lq;
        int row1 = row0 + 8;
        #pragma unroll
        for (int nt = 0; nt < 4; nt++) {
            int col = bn + wn + nt * 8 + lr * 2;
            float v0 = c[mt][nt][0], v1 = c[mt][nt][1];
            float v2 = c[mt][nt][2], v3 = c[mt][nt][3];
            if (BMODE == 1) {
                float b0 = bias[col], b1 = bias[col + 1];
                v0 += b0; v1 += b1; v2 += b0; v3 += b1;
            }
            if (BMODE == 2) {
                if (row0 < M) {
                    const float* bb = bias + (size_t)(row0 >> 9) * N + col;
                    v0 += bb[0]; v1 += bb[1];
                }
                if (row1 < M) {
                    const float* bb = bias + (size_t)(row1 >> 9) * N + col;
                    v2 += bb[0]; v3 += bb[1];
                }
            }
            if (AOUT) { v0 = gelu_f(v0); v1 = gelu_f(v1); v2 = gelu_f(v2); v3 = gelu_f(v3); }
            if (TF32OUT) {
                v0 = __uint_as_float(f2tf32(v0 * oscale));
                v1 = __uint_as_float(f2tf32(v1 * oscale));
                v2 = __uint_as_float(f2tf32(v2 * oscale));
                v3 = __uint_as_float(f2tf32(v3 * oscale));
            }
            if (row0 < M) *(float2*)&C[(size_t)row0 * N + col] = make_float2(v0, v1);
            if (row1 < M) *(float2*)&C[(size_t)row1 * N + col] = make_float2(v2, v3);
        }
    }
}

template <int AIN, int AOUT, int BMODE>
__global__ __launch_bounds__(256) void gemm_tf32_kernel(
    const float* __restrict__ A, const float* __restrict__ W,
    const float* __restrict__ bias, float* __restrict__ C,
    int M, int N, int K)
{
    gemm_tf32_body<AIN, AOUT, BMODE, 0>(A, W, bias, C, M, N, K,
                                        blockIdx.x * GBM, blockIdx.y * GBN, 1.0f);
}

__global__ __launch_bounds__(256) void gemm_tf32_qkv_kernel(
    const float* __restrict__ A,
    const float* __restrict__ W0, const float* __restrict__ W1, const float* __restrict__ W2,
    float* __restrict__ C0, float* __restrict__ C1, float* __restrict__ C2,
    int M, int N, int K)
{
    const float* W = (blockIdx.z == 0) ? W0 : (blockIdx.z == 1) ? W1 : W2;
    float*       C = (blockIdx.z == 0) ? C0 : (blockIdx.z == 1) ? C1 : C2;
    const float oscale = (blockIdx.z == 0) ? 0.17677669529663688f : 1.0f;
    gemm_tf32_body<0, 0, 0, 1>(A, W, nullptr, C, M, N, K,
                               blockIdx.x * GBM, blockIdx.y * GBN, oscale);
}

// ---------------------------------------------------------------------------
// Fused attention v9 — per-key-tile fused QK->exp->PV. P lives in a
// single-tile smem buffer [32][132] (16.5 KB instead of 66 KB), so smem
// drops to ~61 KB -> 3 CTAs/SM.
// smem (uint32 words): qs[32][36] @0, ks[128][36] @1152, vs[128][40] @5760,
//   sc[32][132] @10880, rsp[8][16] @15104, rs[32] @15232; total 15264.
// ---------------------------------------------------------------------------
#define SCT 132
#define ATTN_SMEM_WORDS 15264
#define ATTN_SMEM_BYTES (ATTN_SMEM_WORDS * 4)

__global__ __launch_bounds__(256, 3) void attn_kernel(
    const float* __restrict__ Qp, const float* __restrict__ Kp,
    const float* __restrict__ Vp, float* __restrict__ Op)
{
    extern __shared__ uint32_t smu[];
    uint32_t* qs = smu;             // [32][36]  tf32 Q (prescaled)
    uint32_t* ks = smu + 1152;      // [128][36] tf32 K tile
    uint32_t* vs = smu + 5760;      // [128][40] tf32 V tile
    uint32_t* sc = smu + 10880;     // [32][132] tf32 exp(S) tile
    float*   rsp = (float*)(smu + 15104);
    float*   rs  = (float*)(smu + 15232);

    const int t    = threadIdx.x;
    const int lane = t & 31;
    const int w    = t >> 5;
    const int qb = blockIdx.x * 32;
    const int h  = blockIdx.y;
    const int b  = blockIdx.z;

    const size_t baseQ  = ((size_t)(b * NN + qb)) * DD + h * DKH;
    const size_t baseKV = ((size_t)(b * NN)) * DD + h * DKH;

    // stage Q: raw bit copy (already tf32 + prescaled)
    {
        int r = t >> 3, c = (t & 7) * 4;
        *(uint4*)&qs[r * 36 + c] = *(const uint4*)&Qp[baseQ + (size_t)r * DD + c];
    }
    __syncthreads();

    const int lq = lane >> 2;
    const int lr = lane & 3;
    const int mb = (w & 1) * 16;
    const int nqb = (w >> 1) * 32;   // QK: key sub-range in tile
    const int nvb = (w >> 1) * 8;    // PV: dim sub-range

    uint32_t qa[4][4];
    #pragma unroll
    for (int kk = 0; kk < 4; kk++) {
        qa[kk][0] = qs[(mb + lq)     * 36 + kk * 8 + lr];
        qa[kk][1] = qs[(mb + 8 + lq) * 36 + kk * 8 + lr];
        qa[kk][2] = qs[(mb + lq)     * 36 + kk * 8 + lr + 4];
        qa[kk][3] = qs[(mb + 8 + lq) * 36 + kk * 8 + lr + 4];
    }

    float rlo = 0.0f, rhi = 0.0f;
    float oc[4] = {0.0f, 0.0f, 0.0f, 0.0f};

    #pragma unroll 1
    for (int kt = 0; kt < 4; kt++) {
        const int kb = kt * 128;
        __syncthreads();   // ks/vs/sc safe to overwrite (prev PV done)
        // stage K tile + V tile (raw bit copies)
        for (int i = t; i < 1024; i += 256) {
            int r = i >> 3, c = (i & 7) * 4;
            *(uint4*)&ks[r * 36 + c] =
                *(const uint4*)&Kp[baseKV + (size_t)(kb + r) * DD + c];
        }
        for (int i = t; i < 1024; i += 256) {
            int r = i >> 3, c = (i & 7) * 4;
            *(uint4*)&vs[r * 40 + c] =
                *(const uint4*)&Vp[baseKV + (size_t)(kb + r) * DD + c];
        }
        __syncthreads();

        // QK MMAs -> exp in regs -> STS P tile
        #pragma unroll
        for (int nt = 0; nt < 4; nt++) {
            const int nb = nqb + nt * 8;
            float c4[4] = {0.0f, 0.0f, 0.0f, 0.0f};
            #pragma unroll
            for (int kk = 0; kk < 4; kk++) {
                uint32_t b0 = ks[(nb + lq) * 36 + kk * 8 + lr];
                uint32_t b1 = ks[(nb + lq) * 36 + kk * 8 + lr + 4];
                mma_tf32(c4, qa[kk][0], qa[kk][1], qa[kk][2], qa[kk][3], b0, b1);
            }
            float e0 = fast_exp(c4[0]);
            float e1 = fast_exp(c4[1]);
            float e2 = fast_exp(c4[2]);
            float e3 = fast_exp(c4[3]);
            rlo += e0 + e1;
            rhi += e2 + e3;
            *(uint2*)&sc[(mb + lq)     * SCT + nb + 2 * lr] = make_uint2(f2tf32(e0), f2tf32(e1));
            *(uint2*)&sc[(mb + 8 + lq) * SCT + nb + 2 * lr] = make_uint2(f2tf32(e2), f2tf32(e3));
        }
        __syncthreads();   // P tile complete

        // PV MMAs over this tile
        #pragma unroll
        for (int kk = 0; kk < 16; kk++) {
            const int kk8 = kk * 8;
            uint32_t a0 = sc[(mb + lq)     * SCT + kk8 + lr];
            uint32_t a1 = sc[(mb + 8 + lq) * SCT + kk8 + lr];
            uint32_t a2 = sc[(mb + lq)     * SCT + kk8 + lr + 4];
            uint32_t a3 = sc[(mb + 8 + lq) * SCT + kk8 + lr + 4];
            uint32_t b0 = vs[(kk8 + lr)     * 40 + nvb + lq];
            uint32_t b1 = vs[(kk8 + lr + 4) * 40 + nvb + lq];
            mma_tf32(oc, a0, a1, a2, a3, b0, b1);
        }
    }

    // row-sum reduction (lr lanes within each lq group)
    rlo += __shfl_xor_sync(0xFFFFFFFFu, rlo, 1);
    rlo += __shfl_xor_sync(0xFFFFFFFFu, rlo, 2);
    rhi += __shfl_xor_sync(0xFFFFFFFFu, rhi, 1);
    rhi += __shfl_xor_sync(0xFFFFFFFFu, rhi, 2);
    if (lr == 0) {
        rsp[w * 16 + lq]     = rlo;
        rsp[w * 16 + 8 + lq] = rhi;
    }
    __syncthreads();
    if (t < 32) {
        int mt = t >> 4, r = t & 15;
        rs[t] = rsp[mt * 16 + r] + rsp[(mt + 2) * 16 + r]
              + rsp[(mt + 4) * 16 + r] + rsp[(mt + 6) * 16 + r];
    }
    __syncthreads();

    {
        float inv0 = 1.0f / rs[mb + lq];
        float inv1 = 1.0f / rs[mb + 8 + lq];
        int col = nvb + 2 * lr;
        *(float2*)&Op[baseQ + (size_t)(mb + lq)     * DD + col] =
            make_float2(oc[0] * inv0, oc[1] * inv0);
        *(float2*)&Op[baseQ + (size_t)(mb + 8 + lq) * DD + col] =
            make_float2(oc[2] * inv1, oc[3] * inv1);
    }
}

// ---------------------------------------------------------------------------
// Fused aggregate chain: rbias[b] = gelu(gelu(mean(X_b))@resW + resb)@ffW1[:256] + ffb1
// grid = B (16 blocks), 256 threads (thread = output column).
// ---------------------------------------------------------------------------
__global__ __launch_bounds__(256) void aggr_kernel(
    const float* __restrict__ X,
    const float* __restrict__ resW, const float* __restrict__ resb,
    const float* __restrict__ ffW1, const float* __restrict__ ffb1,
    float* __restrict__ rbias)
{
    __shared__ float ag[DD];
    __shared__ float ar[DD];
    const int b = blockIdx.x;
    const int t = threadIdx.x;

    // column mean + gelu
    float s = 0.0f;
    const float* base = X + (size_t)b * NN * DD + t;
    #pragma unroll 8
    for (int n = 0; n < NN; n++) s += base[(size_t)n * DD];
    ag[t] = gelu_f(s * (1.0f / (float)NN));
    __syncthreads();

    // ares = ag @ resW + resb; keep gelu(ares)
    s = 0.0f;
    #pragma unroll 8
    for (int k = 0; k < DD; k++) s = fmaf(ag[k], resW[(size_t)k * DD + t], s);
    ar[t] = gelu_f(s + resb[t]);
    __syncthreads();

    // rbias = ar @ ffW1[:256] + ffb1
    s = 0.0f;
    #pragma unroll 8
    for (int k = 0; k < DD; k++) s = fmaf(ar[k], ffW1[(size_t)k * DD + t], s);
    rbias[b * DD + t] = s + ffb1[t];
}

// ---------------------------------------------------------------------------
__global__ __launch_bounds__(256) void class_sum_kernel(
    const float* __restrict__ F, const int* __restrict__ lab,
    float* __restrict__ G, float* __restrict__ CNT)
{
    __shared__ float gs[CC * DD];
    __shared__ float cs[CC];
    const int b = blockIdx.x;
    const int t = threadIdx.x;
    for (int i = t; i < CC * DD; i += 256) gs[i] = 0.0f;
    if (t < CC) cs[t] = 0.0f;
    __syncthreads();
    for (int n = 0; n < NN; n++) {
        int c = lab[b * NN + n];
        gs[c * DD + t] += F[((size_t)b * NN + n) * DD + t];
        if (t == 0) cs[c] += 1.0f;
    }
    __syncthreads();
    for (int i = t; i < CC * DD; i += 256) G[(size_t)b * CC * DD + i] = gs[i];
    if (t < CC) CNT[b * CC + t] = cs[t];
}

__global__ __launch_bounds__(256) void proto_out_kernel(
    const float* __restrict__ F, const float* __restrict__ G,
    const float* __restrict__ CNT, const int* __restrict__ lab,
    float* __restrict__ out)
{
    __shared__ float fs[DD];
    const int n = blockIdx.x;
    const int b = blockIdx.y;
    const int t = threadIdx.x;
    fs[t] = F[((size_t)b * NN + n) * DD + t];
    __syncthreads();

    const int w = t >> 5, lane = t & 31;
    float sd = 0.0f;
    for (int i = lane; i < DD; i += 32) sd += fs[i] * fs[i];
    #pragma unroll
    for (int o = 16; o; o >>= 1) sd += __shfl_xor_sync(0xFFFFFFFFu, sd, o);

    const int labn = lab[b * NN + n];
    #pragma unroll
    for (int cc = 0; cc < 2; cc++) {
        const int c = w * 2 + cc;
        const float* g = G + (size_t)b * CC * DD + c * DD;
        float dp = 0.0f;
        for (int i = lane; i < DD; i += 32) dp += fs[i] * g[i];
        #pragma unroll
        for (int o = 16; o; o >>= 1) dp += __shfl_xor_sync(0xFFFFFFFFu, dp, o);
        if (lane == 0) {
            float same = (labn == c) ? 1.0f : 0.0f;
            out[((size_t)b * NN + n) * CC + c] =
                (dp - same * sd) / (CNT[b * CC + c] - same);
        }
    }
}

// ---------------------------------------------------------------------------
extern "C" void kernel_launch(void* const* d_in, const int* in_sizes, int n_in,
                              void* d_out, int out_size)
{
    const float* E    = (const float*)d_in[0];
    const int*   lab  = (const int*)  d_in[1];
    const float* Wq0  = (const float*)d_in[2];
    const float* Wk0  = (const float*)d_in[3];
    const float* Wv0  = (const float*)d_in[4];
    const float* Wo0  = (const float*)d_in[5];
    const float* Wq1  = (const float*)d_in[6];
    const float* Wk1  = (const float*)d_in[7];
    const float* Wv1  = (const float*)d_in[8];
    const float* Wo1  = (const float*)d_in[9];
    const float* resW = (const float*)d_in[10];
    const float* resb = (const float*)d_in[11];
    const float* ffW1 = (const float*)d_in[12];
    const float* ffb1 = (const float*)d_in[13];
    const float* ffW2 = (const float*)d_in[14];
    const float* ffb2 = (const float*)d_in[15];
    float* out = (float*)d_out;

    float *bQ, *bK, *bV, *bO, *bX, *rbias, *G, *CNT;
    cudaGetSymbolAddress((void**)&bQ,    g_bufQ);
    cudaGetSymbolAddress((void**)&bK,    g_bufK);
    cudaGetSymbolAddress((void**)&bV,    g_bufV);
    cudaGetSymbolAddress((void**)&bO,    g_bufO);
    cudaGetSymbolAddress((void**)&bX,    g_bufX);
    cudaGetSymbolAddress((void**)&rbias, g_rbias);
    cudaGetSymbolAddress((void**)&G,     g_G);
    cudaGetSymbolAddress((void**)&CNT,   g_CNT);

    cudaFuncSetAttribute(attn_kernel,
                         cudaFuncAttributeMaxDynamicSharedMemorySize,
                         ATTN_SMEM_BYTES);

    const int M = BB * NN;                 // 8192
    dim3 gBig(M / GBM, DD / GBN);          // (64, 2)
    dim3 gQKV(M / GBM, DD / GBN, 3);       // (64, 2, 3)
    dim3 gAttn(NN / 32, HH, BB);           // (16, 8, 16)

    // ---- MHA 0 ----
    gemm_tf32_qkv_kernel<<<gQKV, 256>>>(E, Wq0, Wk0, Wv0, bQ, bK, bV, M, DD, DD);
    attn_kernel<<<gAttn, 256, ATTN_SMEM_BYTES>>>(bQ, bK, bV, bO);
    gemm_tf32_kernel<0, 1, 0><<<gBig, 256>>>(bO, Wo0, nullptr, bX, M, DD, DD);

    // ---- MHA 1 ----
    gemm_tf32_qkv_kernel<<<gQKV, 256>>>(bX, Wq1, Wk1, Wv1, bQ, bK, bV, M, DD, DD);
    attn_kernel<<<gAttn, 256, ATTN_SMEM_BYTES>>>(bQ, bK, bV, bO);
    gemm_tf32_kernel<0, 0, 0><<<gBig, 256>>>(bO, Wo1, nullptr, bX, M, DD, DD);

    // ---- aggregate path (fused) ----
    aggr_kernel<<<BB, 256>>>(bX, resW, resb, ffW1, ffb1, rbias);
    // h = gelu( gelu(E) @ ff_W1[256:] + rbias[b] )
    gemm_tf32_kernel<1, 1, 2><<<gBig, 256>>>(E, ffW1 + (size_t)DD * DD, rbias, bQ, M, DD, DD);
    // f = h @ ff_W2 + ff_b2
    gemm_tf32_kernel<0, 0, 1><<<gBig, 256>>>(bQ, ffW2, ffb2, bK, M, DD, DD);

    // ---- prototypical scoring ----
    class_sum_kernel<<<BB, 256>>>(bK, lab, G, CNT);
    proto_out_kernel<<<dim3(NN, BB), 256>>>(bK, G, CNT, lab, out);
}

// round 11
// speedup vs baseline: 2.1920x; 1.1312x over previous
#include <cuda_runtime.h>
#include <cuda_bf16.h>
#include <math.h>
#include <stdint.h>

// Shapes: B=16, N=512, D=256, H=8, DK=32, C=16
#define BB 16
#define NN 512
#define DD 256
#define HH 8
#define DKH 32
#define CC 16

__device__ float g_bufQ[BB * NN * DD];
__device__ float g_bufK[BB * NN * DD];
__device__ float g_bufV[BB * NN * DD];
__device__ float g_bufO[BB * NN * DD];
__device__ float g_bufX[BB * NN * DD];
__device__ float g_rbias[BB * DD];
__device__ float g_G[BB * CC * DD];
__device__ float g_CNT[BB * CC];

__device__ __forceinline__ float gelu_f(float x) {
    return 0.5f * x * (1.0f + erff(x * 0.7071067811865475f));
}

// exp(x) on the FMA/ALU pipes (no MUFU). ~1.2e-7 rel error.
__device__ __forceinline__ float fast_exp(float x) {
    float y = x * 1.4426950408889634f;
    y = fmaxf(y, -126.0f);
    float f = rintf(y);
    float z = y - f;
    float p = 1.5403530393381609e-4f;
    p = fmaf(p, z, 1.3333558146428443e-3f);
    p = fmaf(p, z, 9.6181291076284772e-3f);
    p = fmaf(p, z, 5.5504108664821580e-2f);
    p = fmaf(p, z, 2.4022650695910072e-1f);
    p = fmaf(p, z, 6.9314718055994531e-1f);
    p = fmaf(p, z, 1.0f);
    int e = (int)f;
    float s = __int_as_float((e + 127) << 23);
    return p * s;
}

__device__ __forceinline__ uint32_t f2tf32(float x) {
    uint32_t u;
    asm("cvt.rna.tf32.f32 %0, %1;" : "=r"(u) : "f"(x));
    return u;
}

__device__ __forceinline__ void mma_tf32(float c[4],
    uint32_t a0, uint32_t a1, uint32_t a2, uint32_t a3,
    uint32_t b0, uint32_t b1)
{
    asm volatile(
        "mma.sync.aligned.m16n8k8.row.col.f32.tf32.tf32.f32 "
        "{%0,%1,%2,%3},{%4,%5,%6,%7},{%8,%9},{%0,%1,%2,%3};"
        : "+f"(c[0]), "+f"(c[1]), "+f"(c[2]), "+f"(c[3])
        : "r"(a0), "r"(a1), "r"(a2), "r"(a3), "r"(b0), "r"(b1));
}

// ---------------------------------------------------------------------------
// tf32 tensor-core GEMM, double-buffered. A staged with k-permuted layout
// (k -> (k&3)*2 + (k>>2) within each 8-group) so fragment loads are LDS.64.
// ---------------------------------------------------------------------------
#define GBM 128
#define GBN 128
#define GBK 16

template <int AIN, int AOUT, int BMODE, int TF32OUT>
__device__ __forceinline__ void gemm_tf32_body(
    const float* __restrict__ A, const float* __restrict__ W,
    const float* __restrict__ bias, float* __restrict__ C,
    int M, int N, int K, int bm, int bn, float oscale)
{
    __shared__ uint32_t As[2][GBM][GBK + 4];
    __shared__ uint32_t Ws[2][GBK][GBN + 8];

    const int t    = threadIdx.x;
    const int lane = t & 31;
    const int wid  = t >> 5;
    const int wm   = (wid & 1) * 64;
    const int wn   = (wid >> 1) * 32;

    const int ar = t >> 1, ac = (t & 1) * 8;
    const int wr = t >> 4, wc = (t & 15) * 8;
    const int lq = lane >> 2;
    const int lr = lane & 3;

    float c[4][4][4];
    #pragma unroll
    for (int mt = 0; mt < 4; mt++)
        #pragma unroll
        for (int nt = 0; nt < 4; nt++)
            #pragma unroll
            for (int i = 0; i < 4; i++) c[mt][nt][i] = 0.0f;

    const int NIT = K / GBK;

    // stage 0 (A in k-permuted order: value k=ac+j at column ac+pk(j))
    {
        float4 a0 = make_float4(0.f,0.f,0.f,0.f), a1 = make_float4(0.f,0.f,0.f,0.f);
        if (bm + ar < M) {
            a0 = *(const float4*)&A[(size_t)(bm + ar) * K + ac];
            a1 = *(const float4*)&A[(size_t)(bm + ar) * K + ac + 4];
        }
        if (AIN) {
            a0.x = gelu_f(a0.x); a0.y = gelu_f(a0.y); a0.z = gelu_f(a0.z); a0.w = gelu_f(a0.w);
            a1.x = gelu_f(a1.x); a1.y = gelu_f(a1.y); a1.z = gelu_f(a1.z); a1.w = gelu_f(a1.w);
        }
        As[0][ar][ac + 0] = f2tf32(a0.x); As[0][ar][ac + 2] = f2tf32(a0.y);
        As[0][ar][ac + 4] = f2tf32(a0.z); As[0][ar][ac + 6] = f2tf32(a0.w);
        As[0][ar][ac + 1] = f2tf32(a1.x); As[0][ar][ac + 3] = f2tf32(a1.y);
        As[0][ar][ac + 5] = f2tf32(a1.z); As[0][ar][ac + 7] = f2tf32(a1.w);

        float4 w0 = *(const float4*)&W[(size_t)wr * N + bn + wc];
        float4 w1 = *(const float4*)&W[(size_t)wr * N + bn + wc + 4];
        Ws[0][wr][wc + 0] = f2tf32(w0.x); Ws[0][wr][wc + 1] = f2tf32(w0.y);
        Ws[0][wr][wc + 2] = f2tf32(w0.z); Ws[0][wr][wc + 3] = f2tf32(w0.w);
        Ws[0][wr][wc + 4] = f2tf32(w1.x); Ws[0][wr][wc + 5] = f2tf32(w1.y);
        Ws[0][wr][wc + 6] = f2tf32(w1.z); Ws[0][wr][wc + 7] = f2tf32(w1.w);
    }
    __syncthreads();

    for (int it = 0; it < NIT; it++) {
        const int cur = it & 1, nxt = cur ^ 1;
        const bool has = (it + 1 < NIT);
        const int k0n = (it + 1) * GBK;

        float4 na0, na1, nw0, nw1;
        if (has) {
            na0 = make_float4(0.f,0.f,0.f,0.f); na1 = na0;
            if (bm + ar < M) {
                na0 = *(const float4*)&A[(size_t)(bm + ar) * K + k0n + ac];
                na1 = *(const float4*)&A[(size_t)(bm + ar) * K + k0n + ac + 4];
            }
            nw0 = *(const float4*)&W[(size_t)(k0n + wr) * N + bn + wc];
            nw1 = *(const float4*)&W[(size_t)(k0n + wr) * N + bn + wc + 4];
        }

        #pragma unroll
        for (int ks = 0; ks < GBK; ks += 8) {
            uint2 af0[4], af1[4];   // af0: row r (k, k+4); af1: row r+8
            #pragma unroll
            for (int mt = 0; mt < 4; mt++) {
                int r = wm + mt * 16 + lq;
                af0[mt] = *(const uint2*)&As[cur][r    ][ks + 2 * lr];
                af1[mt] = *(const uint2*)&As[cur][r + 8][ks + 2 * lr];
            }
            uint32_t bf[4][2];
            #pragma unroll
            for (int nt = 0; nt < 4; nt++) {
                int nc = wn + nt * 8 + lq;
                bf[nt][0] = Ws[cur][ks + lr    ][nc];
                bf[nt][1] = Ws[cur][ks + lr + 4][nc];
            }
            #pragma unroll
            for (int mt = 0; mt < 4; mt++)
                #pragma unroll
                for (int nt = 0; nt < 4; nt++)
                    mma_tf32(c[mt][nt], af0[mt].x, af1[mt].x, af0[mt].y, af1[mt].y,
                             bf[nt][0], bf[nt][1]);
        }

        if (has) {
            if (AIN) {
                na0.x = gelu_f(na0.x); na0.y = gelu_f(na0.y); na0.z = gelu_f(na0.z); na0.w = gelu_f(na0.w);
                na1.x = gelu_f(na1.x); na1.y = gelu_f(na1.y); na1.z = gelu_f(na1.z); na1.w = gelu_f(na1.w);
            }
            As[nxt][ar][ac + 0] = f2tf32(na0.x); As[nxt][ar][ac + 2] = f2tf32(na0.y);
            As[nxt][ar][ac + 4] = f2tf32(na0.z); As[nxt][ar][ac + 6] = f2tf32(na0.w);
            As[nxt][ar][ac + 1] = f2tf32(na1.x); As[nxt][ar][ac + 3] = f2tf32(na1.y);
            As[nxt][ar][ac + 5] = f2tf32(na1.z); As[nxt][ar][ac + 7] = f2tf32(na1.w);
            Ws[nxt][wr][wc + 0] = f2tf32(nw0.x); Ws[nxt][wr][wc + 1] = f2tf32(nw0.y);
            Ws[nxt][wr][wc + 2] = f2tf32(nw0.z); Ws[nxt][wr][wc + 3] = f2tf32(nw0.w);
            Ws[nxt][wr][wc + 4] = f2tf32(nw1.x); Ws[nxt][wr][wc + 5] = f2tf32(nw1.y);
            Ws[nxt][wr][wc + 6] = f2tf32(nw1.z); Ws[nxt][wr][wc + 7] = f2tf32(nw1.w);
            __syncthreads();
        }
    }

    #pragma unroll
    for (int mt = 0; mt < 4; mt++) {
        int row0 = bm + wm + mt * 16 + lq;
        int row1 = row0 + 8;
        #pragma unroll
        for (int nt = 0; nt < 4; nt++) {
            int col = bn + wn + nt * 8 + lr * 2;
            float v0 = c[mt][nt][0], v1 = c[mt][nt][1];
            float v2 = c[mt][nt][2], v3 = c[mt][nt][3];
            if (BMODE == 1) {
                float b0 = bias[col], b1 = bias[col + 1];
                v0 += b0; v1 += b1; v2 += b0; v3 += b1;
            }
            if (BMODE == 2) {
                if (row0 < M) {
                    const float* bb = bias + (size_t)(row0 >> 9) * N + col;
                    v0 += bb[0]; v1 += bb[1];
                }
                if (row1 < M) {
                    const float* bb = bias + (size_t)(row1 >> 9) * N + col;
                    v2 += bb[0]; v3 += bb[1];
                }
            }
            if (AOUT) { v0 = gelu_f(v0); v1 = gelu_f(v1); v2 = gelu_f(v2); v3 = gelu_f(v3); }
            if (TF32OUT) {
                v0 = __uint_as_float(f2tf32(v0 * oscale));
                v1 = __uint_as_float(f2tf32(v1 * oscale));
                v2 = __uint_as_float(f2tf32(v2 * oscale));
                v3 = __uint_as_float(f2tf32(v3 * oscale));
            }
            if (row0 < M) *(float2*)&C[(size_t)row0 * N + col] = make_float2(v0, v1);
            if (row1 < M) *(float2*)&C[(size_t)row1 * N + col] = make_float2(v2, v3);
        }
    }
}

template <int AIN, int AOUT, int BMODE>
__global__ __launch_bounds__(256) void gemm_tf32_kernel(
    const float* __restrict__ A, const float* __restrict__ W,
    const float* __restrict__ bias, float* __restrict__ C,
    int M, int N, int K)
{
    gemm_tf32_body<AIN, AOUT, BMODE, 0>(A, W, bias, C, M, N, K,
                                        blockIdx.x * GBM, blockIdx.y * GBN, 1.0f);
}

__global__ __launch_bounds__(256) void gemm_tf32_qkv_kernel(
    const float* __restrict__ A,
    const float* __restrict__ W0, const float* __restrict__ W1, const float* __restrict__ W2,
    float* __restrict__ C0, float* __restrict__ C1, float* __restrict__ C2,
    int M, int N, int K)
{
    const float* W = (blockIdx.z == 0) ? W0 : (blockIdx.z == 1) ? W1 : W2;
    float*       C = (blockIdx.z == 0) ? C0 : (blockIdx.z == 1) ? C1 : C2;
    const float oscale = (blockIdx.z == 0) ? 0.17677669529663688f : 1.0f;
    gemm_tf32_body<0, 0, 0, 1>(A, W, nullptr, C, M, N, K,
                               blockIdx.x * GBM, blockIdx.y * GBN, oscale);
}

// ---------------------------------------------------------------------------
// Fused attention v9 (unchanged from R10) — per-key-tile QK->exp->PV, 3 CTAs/SM.
// ---------------------------------------------------------------------------
#define SCT 132
#define ATTN_SMEM_WORDS 15264
#define ATTN_SMEM_BYTES (ATTN_SMEM_WORDS * 4)

__global__ __launch_bounds__(256, 3) void attn_kernel(
    const float* __restrict__ Qp, const float* __restrict__ Kp,
    const float* __restrict__ Vp, float* __restrict__ Op)
{
    extern __shared__ uint32_t smu[];
    uint32_t* qs = smu;             // [32][36]
    uint32_t* ks = smu + 1152;      // [128][36]
    uint32_t* vs = smu + 5760;      // [128][40]
    uint32_t* sc = smu + 10880;     // [32][132]
    float*   rsp = (float*)(smu + 15104);
    float*   rs  = (float*)(smu + 15232);

    const int t    = threadIdx.x;
    const int lane = t & 31;
    const int w    = t >> 5;
    const int qb = blockIdx.x * 32;
    const int h  = blockIdx.y;
    const int b  = blockIdx.z;

    const size_t baseQ  = ((size_t)(b * NN + qb)) * DD + h * DKH;
    const size_t baseKV = ((size_t)(b * NN)) * DD + h * DKH;

    {
        int r = t >> 3, c = (t & 7) * 4;
        *(uint4*)&qs[r * 36 + c] = *(const uint4*)&Qp[baseQ + (size_t)r * DD + c];
    }
    __syncthreads();

    const int lq = lane >> 2;
    const int lr = lane & 3;
    const int mb = (w & 1) * 16;
    const int nqb = (w >> 1) * 32;
    const int nvb = (w >> 1) * 8;

    uint32_t qa[4][4];
    #pragma unroll
    for (int kk = 0; kk < 4; kk++) {
        qa[kk][0] = qs[(mb + lq)     * 36 + kk * 8 + lr];
        qa[kk][1] = qs[(mb + 8 + lq) * 36 + kk * 8 + lr];
        qa[kk][2] = qs[(mb + lq)     * 36 + kk * 8 + lr + 4];
        qa[kk][3] = qs[(mb + 8 + lq) * 36 + kk * 8 + lr + 4];
    }

    float rlo = 0.0f, rhi = 0.0f;
    float oc[4] = {0.0f, 0.0f, 0.0f, 0.0f};

    #pragma unroll 1
    for (int kt = 0; kt < 4; kt++) {
        const int kb = kt * 128;
        __syncthreads();
        for (int i = t; i < 1024; i += 256) {
            int r = i >> 3, c = (i & 7) * 4;
            *(uint4*)&ks[r * 36 + c] =
                *(const uint4*)&Kp[baseKV + (size_t)(kb + r) * DD + c];
        }
        for (int i = t; i < 1024; i += 256) {
            int r = i >> 3, c = (i & 7) * 4;
            *(uint4*)&vs[r * 40 + c] =
                *(const uint4*)&Vp[baseKV + (size_t)(kb + r) * DD + c];
        }
        __syncthreads();

        #pragma unroll
        for (int nt = 0; nt < 4; nt++) {
            const int nb = nqb + nt * 8;
            float c4[4] = {0.0f, 0.0f, 0.0f, 0.0f};
            #pragma unroll
            for (int kk = 0; kk < 4; kk++) {
                uint32_t b0 = ks[(nb + lq) * 36 + kk * 8 + lr];
                uint32_t b1 = ks[(nb + lq) * 36 + kk * 8 + lr + 4];
                mma_tf32(c4, qa[kk][0], qa[kk][1], qa[kk][2], qa[kk][3], b0, b1);
            }
            float e0 = fast_exp(c4[0]);
            float e1 = fast_exp(c4[1]);
            float e2 = fast_exp(c4[2]);
            float e3 = fast_exp(c4[3]);
            rlo += e0 + e1;
            rhi += e2 + e3;
            *(uint2*)&sc[(mb + lq)     * SCT + nb + 2 * lr] = make_uint2(f2tf32(e0), f2tf32(e1));
            *(uint2*)&sc[(mb + 8 + lq) * SCT + nb + 2 * lr] = make_uint2(f2tf32(e2), f2tf32(e3));
        }
        __syncthreads();

        #pragma unroll
        for (int kk = 0; kk < 16; kk++) {
            const int kk8 = kk * 8;
            uint32_t a0 = sc[(mb + lq)     * SCT + kk8 + lr];
            uint32_t a1 = sc[(mb + 8 + lq) * SCT + kk8 + lr];
            uint32_t a2 = sc[(mb + lq)     * SCT + kk8 + lr + 4];
            uint32_t a3 = sc[(mb + 8 + lq) * SCT + kk8 + lr + 4];
            uint32_t b0 = vs[(kk8 + lr)     * 40 + nvb + lq];
            uint32_t b1 = vs[(kk8 + lr + 4) * 40 + nvb + lq];
            mma_tf32(oc, a0, a1, a2, a3, b0, b1);
        }
    }

    rlo += __shfl_xor_sync(0xFFFFFFFFu, rlo, 1);
    rlo += __shfl_xor_sync(0xFFFFFFFFu, rlo, 2);
    rhi += __shfl_xor_sync(0xFFFFFFFFu, rhi, 1);
    rhi += __shfl_xor_sync(0xFFFFFFFFu, rhi, 2);
    if (lr == 0) {
        rsp[w * 16 + lq]     = rlo;
        rsp[w * 16 + 8 + lq] = rhi;
    }
    __syncthreads();
    if (t < 32) {
        int mt = t >> 4, r = t & 15;
        rs[t] = rsp[mt * 16 + r] + rsp[(mt + 2) * 16 + r]
              + rsp[(mt + 4) * 16 + r] + rsp[(mt + 6) * 16 + r];
    }
    __syncthreads();

    {
        float inv0 = 1.0f / rs[mb + lq];
        float inv1 = 1.0f / rs[mb + 8 + lq];
        int col = nvb + 2 * lr;
        *(float2*)&Op[baseQ + (size_t)(mb + lq)     * DD + col] =
            make_float2(oc[0] * inv0, oc[1] * inv0);
        *(float2*)&Op[baseQ + (size_t)(mb + 8 + lq) * DD + col] =
            make_float2(oc[2] * inv1, oc[3] * inv1);
    }
}

// ---------------------------------------------------------------------------
// Fused aggregate chain, 1024 threads with 4-way k-split (serial depth
// 512+256+256 -> 128+64+64).
// ---------------------------------------------------------------------------
__global__ __launch_bounds__(1024) void aggr_kernel(
    const float* __restrict__ X,
    const float* __restrict__ resW, const float* __restrict__ resb,
    const float* __restrict__ ffW1, const float* __restrict__ ffb1,
    float* __restrict__ rbias)
{
    __shared__ float part[4][DD];
    __shared__ float ag[DD];
    __shared__ float ar[DD];
    const int b = blockIdx.x;
    const int t = threadIdx.x & 255;
    const int p = threadIdx.x >> 8;   // 0..3

    // column mean over rows [p*128, p*128+128)
    float s = 0.0f;
    const float* base = X + (size_t)b * NN * DD + (size_t)p * 128 * DD + t;
    #pragma unroll 8
    for (int n = 0; n < 128; n++) s += base[(size_t)n * DD];
    part[p][t] = s;
    __syncthreads();
    if (p == 0)
        ag[t] = gelu_f((part[0][t] + part[1][t] + part[2][t] + part[3][t]) * (1.0f / (float)NN));
    __syncthreads();

    // ares = ag @ resW + resb (k-split by 4)
    s = 0.0f;
    #pragma unroll 8
    for (int k = p * 64; k < p * 64 + 64; k++)
        s = fmaf(ag[k], resW[(size_t)k * DD + t], s);
    part[p][t] = s;
    __syncthreads();
    if (p == 0)
        ar[t] = gelu_f(part[0][t] + part[1][t] + part[2][t] + part[3][t] + resb[t]);
    __syncthreads();

    // rbias = ar @ ffW1[:256] + ffb1
    s = 0.0f;
    #pragma unroll 8
    for (int k = p * 64; k < p * 64 + 64; k++)
        s = fmaf(ar[k], ffW1[(size_t)k * DD + t], s);
    part[p][t] = s;
    __syncthreads();
    if (p == 0)
        rbias[b * DD + t] = part[0][t] + part[1][t] + part[2][t] + part[3][t] + ffb1[t];
}

// ---------------------------------------------------------------------------
// class_sum v2: grid (C, B) = (16,16); ballot-compaction (deterministic),
// then unrolled gather of the ~32 matching rows (MLP 4).
// ---------------------------------------------------------------------------
__global__ __launch_bounds__(256) void class_sum_kernel(
    const float* __restrict__ F, const int* __restrict__ lab,
    float* __restrict__ G, float* __restrict__ CNT)
{
    __shared__ int slab[NN];
    __shared__ int idx[NN];
    __shared__ int scnt;
    const int c = blockIdx.x;
    const int b = blockIdx.y;
    const int t = threadIdx.x;

    for (int n = t; n < NN; n += 256) slab[n] = lab[b * NN + n];
    __syncthreads();

    if (t < 32) {
        int cnt = 0;
        for (int ch = 0; ch < NN / 32; ch++) {
            int n = ch * 32 + t;
            bool m = (slab[n] == c);
            unsigned mask = __ballot_sync(0xFFFFFFFFu, m);
            if (m) idx[cnt + __popc(mask & ((1u << t) - 1u))] = n;
            cnt += __popc(mask);
        }
        if (t == 0) scnt = cnt;
    }
    __syncthreads();

    const int m = scnt;
    const float* Fb = F + (size_t)b * NN * DD;
    float s = 0.0f;
    int i = 0;
    for (; i + 4 <= m; i += 4) {
        int n0 = idx[i], n1 = idx[i+1], n2 = idx[i+2], n3 = idx[i+3];
        float v0 = Fb[(size_t)n0 * DD + t];
        float v1 = Fb[(size_t)n1 * DD + t];
        float v2 = Fb[(size_t)n2 * DD + t];
        float v3 = Fb[(size_t)n3 * DD + t];
        s += (v0 + v1) + (v2 + v3);
    }
    for (; i < m; i++) s += Fb[(size_t)idx[i] * DD + t];

    G[((size_t)b * CC + c) * DD + t] = s;
    if (t == 0) CNT[b * CC + c] = (float)m;
}

// ---------------------------------------------------------------------------
__global__ __launch_bounds__(256) void proto_out_kernel(
    const float* __restrict__ F, const float* __restrict__ G,
    const float* __restrict__ CNT, const int* __restrict__ lab,
    float* __restrict__ out)
{
    __shared__ float fs[DD];
    const int n = blockIdx.x;
    const int b = blockIdx.y;
    const int t = threadIdx.x;
    fs[t] = F[((size_t)b * NN + n) * DD + t];
    __syncthreads();

    const int w = t >> 5, lane = t & 31;
    float sd = 0.0f;
    for (int i = lane; i < DD; i += 32) sd += fs[i] * fs[i];
    #pragma unroll
    for (int o = 16; o; o >>= 1) sd += __shfl_xor_sync(0xFFFFFFFFu, sd, o);

    const int labn = lab[b * NN + n];
    #pragma unroll
    for (int cc = 0; cc < 2; cc++) {
        const int c = w * 2 + cc;
        const float* g = G + (size_t)b * CC * DD + c * DD;
        float dp = 0.0f;
        for (int i = lane; i < DD; i += 32) dp += fs[i] * g[i];
        #pragma unroll
        for (int o = 16; o; o >>= 1) dp += __shfl_xor_sync(0xFFFFFFFFu, dp, o);
        if (lane == 0) {
            float same = (labn == c) ? 1.0f : 0.0f;
            out[((size_t)b * NN + n) * CC + c] =
                (dp - same * sd) / (CNT[b * CC + c] - same);
        }
    }
}

// ---------------------------------------------------------------------------
extern "C" void kernel_launch(void* const* d_in, const int* in_sizes, int n_in,
                              void* d_out, int out_size)
{
    const float* E    = (const float*)d_in[0];
    const int*   lab  = (const int*)  d_in[1];
    const float* Wq0  = (const float*)d_in[2];
    const float* Wk0  = (const float*)d_in[3];
    const float* Wv0  = (const float*)d_in[4];
    const float* Wo0  = (const float*)d_in[5];
    const float* Wq1  = (const float*)d_in[6];
    const float* Wk1  = (const float*)d_in[7];
    const float* Wv1  = (const float*)d_in[8];
    const float* Wo1  = (const float*)d_in[9];
    const float* resW = (const float*)d_in[10];
    const float* resb = (const float*)d_in[11];
    const float* ffW1 = (const float*)d_in[12];
    const float* ffb1 = (const float*)d_in[13];
    const float* ffW2 = (const float*)d_in[14];
    const float* ffb2 = (const float*)d_in[15];
    float* out = (float*)d_out;

    float *bQ, *bK, *bV, *bO, *bX, *rbias, *G, *CNT;
    cudaGetSymbolAddress((void**)&bQ,    g_bufQ);
    cudaGetSymbolAddress((void**)&bK,    g_bufK);
    cudaGetSymbolAddress((void**)&bV,    g_bufV);
    cudaGetSymbolAddress((void**)&bO,    g_bufO);
    cudaGetSymbolAddress((void**)&bX,    g_bufX);
    cudaGetSymbolAddress((void**)&rbias, g_rbias);
    cudaGetSymbolAddress((void**)&G,     g_G);
    cudaGetSymbolAddress((void**)&CNT,   g_CNT);

    cudaFuncSetAttribute(attn_kernel,
                         cudaFuncAttributeMaxDynamicSharedMemorySize,
                         ATTN_SMEM_BYTES);

    const int M = BB * NN;                 // 8192
    dim3 gBig(M / GBM, DD / GBN);          // (64, 2)
    dim3 gQKV(M / GBM, DD / GBN, 3);       // (64, 2, 3)
    dim3 gAttn(NN / 32, HH, BB);           // (16, 8, 16)

    // ---- MHA 0 ----
    gemm_tf32_qkv_kernel<<<gQKV, 256>>>(E, Wq0, Wk0, Wv0, bQ, bK, bV, M, DD, DD);
    attn_kernel<<<gAttn, 256, ATTN_SMEM_BYTES>>>(bQ, bK, bV, bO);
    gemm_tf32_kernel<0, 1, 0><<<gBig, 256>>>(bO, Wo0, nullptr, bX, M, DD, DD);

    // ---- MHA 1 ----
    gemm_tf32_qkv_kernel<<<gQKV, 256>>>(bX, Wq1, Wk1, Wv1, bQ, bK, bV, M, DD, DD);
    attn_kernel<<<gAttn, 256, ATTN_SMEM_BYTES>>>(bQ, bK, bV, bO);
    gemm_tf32_kernel<0, 0, 0><<<gBig, 256>>>(bO, Wo1, nullptr, bX, M, DD, DD);

    // ---- aggregate path (fused, 1024 thr) ----
    aggr_kernel<<<BB, 1024>>>(bX, resW, resb, ffW1, ffb1, rbias);
    gemm_tf32_kernel<1, 1, 2><<<gBig, 256>>>(E, ffW1 + (size_t)DD * DD, rbias, bQ, M, DD, DD);
    gemm_tf32_kernel<0, 0, 1><<<gBig, 256>>>(bQ, ffW2, ffb2, bK, M, DD, DD);

    // ---- prototypical scoring ----
    class_sum_kernel<<<dim3(CC, BB), 256>>>(bK, lab, G, CNT);
    proto_out_kernel<<<dim3(NN, BB), 256>>>(bK, G, CNT, lab, out);
}

// round 13
// speedup vs baseline: 2.3026x; 1.0505x over previous
#include <cuda_runtime.h>
#include <cuda_bf16.h>
#include <math.h>
#include <stdint.h>

// Shapes: B=16, N=512, D=256, H=8, DK=32, C=16
#define BB 16
#define NN 512
#define DD 256
#define HH 8
#define DKH 32
#define CC 16

__device__ float g_bufQ[BB * NN * DD];
__device__ float g_bufK[BB * NN * DD];
__device__ float g_bufV[BB * NN * DD];
__device__ float g_bufO[BB * NN * DD];
__device__ float g_bufX[BB * NN * DD];
__device__ float g_rbias[BB * DD];
__device__ float g_G[BB * CC * DD];
__device__ float g_CNT[BB * CC];

__device__ __forceinline__ float gelu_f(float x) {
    return 0.5f * x * (1.0f + erff(x * 0.7071067811865475f));
}

// exp(x) on the FMA/ALU pipes (no MUFU). ~1.2e-7 rel error.
__device__ __forceinline__ float fast_exp(float x) {
    float y = x * 1.4426950408889634f;
    y = fmaxf(y, -126.0f);
    float f = rintf(y);
    float z = y - f;
    float p = 1.5403530393381609e-4f;
    p = fmaf(p, z, 1.3333558146428443e-3f);
    p = fmaf(p, z, 9.6181291076284772e-3f);
    p = fmaf(p, z, 5.5504108664821580e-2f);
    p = fmaf(p, z, 2.4022650695910072e-1f);
    p = fmaf(p, z, 6.9314718055994531e-1f);
    p = fmaf(p, z, 1.0f);
    int e = (int)f;
    float s = __int_as_float((e + 127) << 23);
    return p * s;
}

__device__ __forceinline__ uint32_t f2tf32(float x) {
    uint32_t u;
    asm("cvt.rna.tf32.f32 %0, %1;" : "=r"(u) : "f"(x));
    return u;
}

__device__ __forceinline__ void mma_tf32(float c[4],
    uint32_t a0, uint32_t a1, uint32_t a2, uint32_t a3,
    uint32_t b0, uint32_t b1)
{
    asm volatile(
        "mma.sync.aligned.m16n8k8.row.col.f32.tf32.tf32.f32 "
        "{%0,%1,%2,%3},{%4,%5,%6,%7},{%8,%9},{%0,%1,%2,%3};"
        : "+f"(c[0]), "+f"(c[1]), "+f"(c[2]), "+f"(c[3])
        : "r"(a0), "r"(a1), "r"(a2), "r"(a3), "r"(b0), "r"(b1));
}

// ---------------------------------------------------------------------------
// tf32 tensor-core GEMM, double-buffered — R9 layout (rna CVT staging).
// TF32OUT: store tf32-rounded bits (scaled by oscale) for attention inputs.
// ---------------------------------------------------------------------------
#define GBM 128
#define GBN 128
#define GBK 16

template <int AIN, int AOUT, int BMODE, int TF32OUT>
__device__ __forceinline__ void gemm_tf32_body(
    const float* __restrict__ A, const float* __restrict__ W,
    const float* __restrict__ bias, float* __restrict__ C,
    int M, int N, int K, int bm, int bn, float oscale)
{
    __shared__ uint32_t As[2][GBM][GBK + 4];
    __shared__ uint32_t Ws[2][GBK][GBN + 8];

    const int t    = threadIdx.x;
    const int lane = t & 31;
    const int wid  = t >> 5;
    const int wm   = (wid & 1) * 64;
    const int wn   = (wid >> 1) * 32;

    const int ar = t >> 1, ac = (t & 1) * 8;
    const int wr = t >> 4, wc = (t & 15) * 8;
    const int lq = lane >> 2;
    const int lr = lane & 3;

    float c[4][4][4];
    #pragma unroll
    for (int mt = 0; mt < 4; mt++)
        #pragma unroll
        for (int nt = 0; nt < 4; nt++)
            #pragma unroll
            for (int i = 0; i < 4; i++) c[mt][nt][i] = 0.0f;

    const int NIT = K / GBK;

    {
        float4 a0 = make_float4(0.f,0.f,0.f,0.f), a1 = make_float4(0.f,0.f,0.f,0.f);
        if (bm + ar < M) {
            a0 = *(const float4*)&A[(size_t)(bm + ar) * K + ac];
            a1 = *(const float4*)&A[(size_t)(bm + ar) * K + ac + 4];
        }
        if (AIN) {
            a0.x = gelu_f(a0.x); a0.y = gelu_f(a0.y); a0.z = gelu_f(a0.z); a0.w = gelu_f(a0.w);
            a1.x = gelu_f(a1.x); a1.y = gelu_f(a1.y); a1.z = gelu_f(a1.z); a1.w = gelu_f(a1.w);
        }
        As[0][ar][ac + 0] = f2tf32(a0.x); As[0][ar][ac + 1] = f2tf32(a0.y);
        As[0][ar][ac + 2] = f2tf32(a0.z); As[0][ar][ac + 3] = f2tf32(a0.w);
        As[0][ar][ac + 4] = f2tf32(a1.x); As[0][ar][ac + 5] = f2tf32(a1.y);
        As[0][ar][ac + 6] = f2tf32(a1.z); As[0][ar][ac + 7] = f2tf32(a1.w);

        float4 w0 = *(const float4*)&W[(size_t)wr * N + bn + wc];
        float4 w1 = *(const float4*)&W[(size_t)wr * N + bn + wc + 4];
        Ws[0][wr][wc + 0] = f2tf32(w0.x); Ws[0][wr][wc + 1] = f2tf32(w0.y);
        Ws[0][wr][wc + 2] = f2tf32(w0.z); Ws[0][wr][wc + 3] = f2tf32(w0.w);
        Ws[0][wr][wc + 4] = f2tf32(w1.x); Ws[0][wr][wc + 5] = f2tf32(w1.y);
        Ws[0][wr][wc + 6] = f2tf32(w1.z); Ws[0][wr][wc + 7] = f2tf32(w1.w);
    }
    __syncthreads();

    for (int it = 0; it < NIT; it++) {
        const int cur = it & 1, nxt = cur ^ 1;
        const bool has = (it + 1 < NIT);
        const int k0n = (it + 1) * GBK;

        float4 na0, na1, nw0, nw1;
        if (has) {
            na0 = make_float4(0.f,0.f,0.f,0.f); na1 = na0;
            if (bm + ar < M) {
                na0 = *(const float4*)&A[(size_t)(bm + ar) * K + k0n + ac];
                na1 = *(const float4*)&A[(size_t)(bm + ar) * K + k0n + ac + 4];
            }
            nw0 = *(const float4*)&W[(size_t)(k0n + wr) * N + bn + wc];
            nw1 = *(const float4*)&W[(size_t)(k0n + wr) * N + bn + wc + 4];
        }

        #pragma unroll
        for (int ks = 0; ks < GBK; ks += 8) {
            uint32_t af[4][4];
            #pragma unroll
            for (int mt = 0; mt < 4; mt++) {
                int r = wm + mt * 16 + lq;
                af[mt][0] = As[cur][r    ][ks + lr];
                af[mt][1] = As[cur][r + 8][ks + lr];
                af[mt][2] = As[cur][r    ][ks + lr + 4];
                af[mt][3] = As[cur][r + 8][ks + lr + 4];
            }
            uint32_t bf[4][2];
            #pragma unroll
            for (int nt = 0; nt < 4; nt++) {
                int nc = wn + nt * 8 + lq;
                bf[nt][0] = Ws[cur][ks + lr    ][nc];
                bf[nt][1] = Ws[cur][ks + lr + 4][nc];
            }
            #pragma unroll
            for (int mt = 0; mt < 4; mt++)
                #pragma unroll
                for (int nt = 0; nt < 4; nt++)
                    mma_tf32(c[mt][nt], af[mt][0], af[mt][1], af[mt][2], af[mt][3],
                             bf[nt][0], bf[nt][1]);
        }

        if (has) {
            if (AIN) {
                na0.x = gelu_f(na0.x); na0.y = gelu_f(na0.y); na0.z = gelu_f(na0.z); na0.w = gelu_f(na0.w);
                na1.x = gelu_f(na1.x); na1.y = gelu_f(na1.y); na1.z = gelu_f(na1.z); na1.w = gelu_f(na1.w);
            }
            As[nxt][ar][ac + 0] = f2tf32(na0.x); As[nxt][ar][ac + 1] = f2tf32(na0.y);
            As[nxt][ar][ac + 2] = f2tf32(na0.z); As[nxt][ar][ac + 3] = f2tf32(na0.w);
            As[nxt][ar][ac + 4] = f2tf32(na1.x); As[nxt][ar][ac + 5] = f2tf32(na1.y);
            As[nxt][ar][ac + 6] = f2tf32(na1.z); As[nxt][ar][ac + 7] = f2tf32(na1.w);
            Ws[nxt][wr][wc + 0] = f2tf32(nw0.x); Ws[nxt][wr][wc + 1] = f2tf32(nw0.y);
            Ws[nxt][wr][wc + 2] = f2tf32(nw0.z); Ws[nxt][wr][wc + 3] = f2tf32(nw0.w);
            Ws[nxt][wr][wc + 4] = f2tf32(nw1.x); Ws[nxt][wr][wc + 5] = f2tf32(nw1.y);
            Ws[nxt][wr][wc + 6] = f2tf32(nw1.z); Ws[nxt][wr][wc + 7] = f2tf32(nw1.w);
            __syncthreads();
        }
    }

    #pragma unroll
    for (int mt = 0; mt < 4; mt++) {
        int row0 = bm + wm + mt * 16 + lq;
        int row1 = row0 + 8;
        #pragma unroll
        for (int nt = 0; nt < 4; nt++) {
            int col = bn + wn + nt * 8 + lr * 2;
            float v0 = c[mt][nt][0], v1 = c[mt][nt][1];
            float v2 = c[mt][nt][2], v3 = c[mt][nt][3];
            if (BMODE == 1) {
                float b0 = bias[col], b1 = bias[col + 1];
                v0 += b0; v1 += b1; v2 += b0; v3 += b1;
            }
            if (BMODE == 2) {
                if (row0 < M) {
                    const float* bb = bias + (size_t)(row0 >> 9) * N + col;
                    v0 += bb[0]; v1 += bb[1];
                }
                if (row1 < M) {
                    const float* bb = bias + (size_t)(row1 >> 9) * N + col;
                    v2 += bb[0]; v3 += bb[1];
                }
            }
            if (AOUT) { v0 = gelu_f(v0); v1 = gelu_f(v1); v2 = gelu_f(v2); v3 = gelu_f(v3); }
            if (TF32OUT) {
                v0 = __uint_as_float(f2tf32(v0 * oscale));
                v1 = __uint_as_float(f2tf32(v1 * oscale));
                v2 = __uint_as_float(f2tf32(v2 * oscale));
                v3 = __uint_as_float(f2tf32(v3 * oscale));
            }
            if (row0 < M) *(float2*)&C[(size_t)row0 * N + col] = make_float2(v0, v1);
            if (row1 < M) *(float2*)&C[(size_t)row1 * N + col] = make_float2(v2, v3);
        }
    }
}

template <int AIN, int AOUT, int BMODE>
__global__ __launch_bounds__(256) void gemm_tf32_kernel(
    const float* __restrict__ A, const float* __restrict__ W,
    const float* __restrict__ bias, float* __restrict__ C,
    int M, int N, int K)
{
    gemm_tf32_body<AIN, AOUT, BMODE, 0>(A, W, bias, C, M, N, K,
                                        blockIdx.x * GBM, blockIdx.y * GBN, 1.0f);
}

__global__ __launch_bounds__(256) void gemm_tf32_qkv_kernel(
    const float* __restrict__ A,
    const float* __restrict__ W0, const float* __restrict__ W1, const float* __restrict__ W2,
    float* __restrict__ C0, float* __restrict__ C1, float* __restrict__ C2,
    int M, int N, int K)
{
    const float* W = (blockIdx.z == 0) ? W0 : (blockIdx.z == 1) ? W1 : W2;
    float*       C = (blockIdx.z == 0) ? C0 : (blockIdx.z == 1) ? C1 : C2;
    const float oscale = (blockIdx.z == 0) ? 0.17677669529663688f : 1.0f;
    gemm_tf32_body<0, 0, 0, 1>(A, W, nullptr, C, M, N, K,
                               blockIdx.x * GBM, blockIdx.y * GBN, oscale);
}

// ---------------------------------------------------------------------------
// Fused attention v9 — per-key-tile QK->exp->PV, 3 CTAs/SM.
// Inputs pre-rounded (rna) by the QKV epilogue; P stored with rna CVT.
// ---------------------------------------------------------------------------
#define SCT 132
#define ATTN_SMEM_WORDS 15264
#define ATTN_SMEM_BYTES (ATTN_SMEM_WORDS * 4)

__global__ __launch_bounds__(256, 3) void attn_kernel(
    const float* __restrict__ Qp, const float* __restrict__ Kp,
    const float* __restrict__ Vp, float* __restrict__ Op)
{
    extern __shared__ uint32_t smu[];
    uint32_t* qs = smu;             // [32][36]
    uint32_t* ks = smu + 1152;      // [128][36]
    uint32_t* vs = smu + 5760;      // [128][40]
    uint32_t* sc = smu + 10880;     // [32][132]
    float*   rsp = (float*)(smu + 15104);
    float*   rs  = (float*)(smu + 15232);

    const int t    = threadIdx.x;
    const int lane = t & 31;
    const int w    = t >> 5;
    const int qb = blockIdx.x * 32;
    const int h  = blockIdx.y;
    const int b  = blockIdx.z;

    const size_t baseQ  = ((size_t)(b * NN + qb)) * DD + h * DKH;
    const size_t baseKV = ((size_t)(b * NN)) * DD + h * DKH;

    {
        int r = t >> 3, c = (t & 7) * 4;
        *(uint4*)&qs[r * 36 + c] = *(const uint4*)&Qp[baseQ + (size_t)r * DD + c];
    }
    __syncthreads();

    const int lq = lane >> 2;
    const int lr = lane & 3;
    const int mb = (w & 1) * 16;
    const int nqb = (w >> 1) * 32;
    const int nvb = (w >> 1) * 8;

    uint32_t qa[4][4];
    #pragma unroll
    for (int kk = 0; kk < 4; kk++) {
        qa[kk][0] = qs[(mb + lq)     * 36 + kk * 8 + lr];
        qa[kk][1] = qs[(mb + 8 + lq) * 36 + kk * 8 + lr];
        qa[kk][2] = qs[(mb + lq)     * 36 + kk * 8 + lr + 4];
        qa[kk][3] = qs[(mb + 8 + lq) * 36 + kk * 8 + lr + 4];
    }

    float rlo = 0.0f, rhi = 0.0f;
    float oc[4] = {0.0f, 0.0f, 0.0f, 0.0f};

    #pragma unroll 1
    for (int kt = 0; kt < 4; kt++) {
        const int kb = kt * 128;
        __syncthreads();
        for (int i = t; i < 1024; i += 256) {
            int r = i >> 3, c = (i & 7) * 4;
            *(uint4*)&ks[r * 36 + c] =
                *(const uint4*)&Kp[baseKV + (size_t)(kb + r) * DD + c];
        }
        for (int i = t; i < 1024; i += 256) {
            int r = i >> 3, c = (i & 7) * 4;
            *(uint4*)&vs[r * 40 + c] =
                *(const uint4*)&Vp[baseKV + (size_t)(kb + r) * DD + c];
        }
        __syncthreads();

        #pragma unroll
        for (int nt = 0; nt < 4; nt++) {
            const int nb = nqb + nt * 8;
            float c4[4] = {0.0f, 0.0f, 0.0f, 0.0f};
            #pragma unroll
            for (int kk = 0; kk < 4; kk++) {
                uint32_t b0 = ks[(nb + lq) * 36 + kk * 8 + lr];
                uint32_t b1 = ks[(nb + lq) * 36 + kk * 8 + lr + 4];
                mma_tf32(c4, qa[kk][0], qa[kk][1], qa[kk][2], qa[kk][3], b0, b1);
            }
            float e0 = fast_exp(c4[0]);
            float e1 = fast_exp(c4[1]);
            float e2 = fast_exp(c4[2]);
            float e3 = fast_exp(c4[3]);
            rlo += e0 + e1;
            rhi += e2 + e3;
            *(uint2*)&sc[(mb + lq)     * SCT + nb + 2 * lr] = make_uint2(f2tf32(e0), f2tf32(e1));
            *(uint2*)&sc[(mb + 8 + lq) * SCT + nb + 2 * lr] = make_uint2(f2tf32(e2), f2tf32(e3));
        }
        __syncthreads();

        #pragma unroll
        for (int kk = 0; kk < 16; kk++) {
            const int kk8 = kk * 8;
            uint32_t a0 = sc[(mb + lq)     * SCT + kk8 + lr];
            uint32_t a1 = sc[(mb + 8 + lq) * SCT + kk8 + lr];
            uint32_t a2 = sc[(mb + lq)     * SCT + kk8 + lr + 4];
            uint32_t a3 = sc[(mb + 8 + lq) * SCT + kk8 + lr + 4];
            uint32_t b0 = vs[(kk8 + lr)     * 40 + nvb + lq];
            uint32_t b1 = vs[(kk8 + lr + 4) * 40 + nvb + lq];
            mma_tf32(oc, a0, a1, a2, a3, b0, b1);
        }
    }

    rlo += __shfl_xor_sync(0xFFFFFFFFu, rlo, 1);
    rlo += __shfl_xor_sync(0xFFFFFFFFu, rlo, 2);
    rhi += __shfl_xor_sync(0xFFFFFFFFu, rhi, 1);
    rhi += __shfl_xor_sync(0xFFFFFFFFu, rhi, 2);
    if (lr == 0) {
        rsp[w * 16 + lq]     = rlo;
        rsp[w * 16 + 8 + lq] = rhi;
    }
    __syncthreads();
    if (t < 32) {
        int mt = t >> 4, r = t & 15;
        rs[t] = rsp[mt * 16 + r] + rsp[(mt + 2) * 16 + r]
              + rsp[(mt + 4) * 16 + r] + rsp[(mt + 6) * 16 + r];
    }
    __syncthreads();

    {
        float inv0 = 1.0f / rs[mb + lq];
        float inv1 = 1.0f / rs[mb + 8 + lq];
        int col = nvb + 2 * lr;
        *(float2*)&Op[baseQ + (size_t)(mb + lq)     * DD + col] =
            make_float2(oc[0] * inv0, oc[1] * inv0);
        *(float2*)&Op[baseQ + (size_t)(mb + 8 + lq) * DD + col] =
            make_float2(oc[2] * inv1, oc[3] * inv1);
    }
}

// ---------------------------------------------------------------------------
// Fused aggregate chain, 1024 threads, 4-way k-split.
// ---------------------------------------------------------------------------
__global__ __launch_bounds__(1024) void aggr_kernel(
    const float* __restrict__ X,
    const float* __restrict__ resW, const float* __restrict__ resb,
    const float* __restrict__ ffW1, const float* __restrict__ ffb1,
    float* __restrict__ rbias)
{
    __shared__ float part[4][DD];
    __shared__ float ag[DD];
    __shared__ float ar[DD];
    const int b = blockIdx.x;
    const int t = threadIdx.x & 255;
    const int p = threadIdx.x >> 8;

    float s = 0.0f;
    const float* base = X + (size_t)b * NN * DD + (size_t)p * 128 * DD + t;
    #pragma unroll 8
    for (int n = 0; n < 128; n++) s += base[(size_t)n * DD];
    part[p][t] = s;
    __syncthreads();
    if (p == 0)
        ag[t] = gelu_f((part[0][t] + part[1][t] + part[2][t] + part[3][t]) * (1.0f / (float)NN));
    __syncthreads();

    s = 0.0f;
    #pragma unroll 8
    for (int k = p * 64; k < p * 64 + 64; k++)
        s = fmaf(ag[k], resW[(size_t)k * DD + t], s);
    part[p][t] = s;
    __syncthreads();
    if (p == 0)
        ar[t] = gelu_f(part[0][t] + part[1][t] + part[2][t] + part[3][t] + resb[t]);
    __syncthreads();

    s = 0.0f;
    #pragma unroll 8
    for (int k = p * 64; k < p * 64 + 64; k++)
        s = fmaf(ar[k], ffW1[(size_t)k * DD + t], s);
    part[p][t] = s;
    __syncthreads();
    if (p == 0)
        rbias[b * DD + t] = part[0][t] + part[1][t] + part[2][t] + part[3][t] + ffb1[t];
}

// ---------------------------------------------------------------------------
// class_sum: ballot-compaction + unrolled gather.
// ---------------------------------------------------------------------------
__global__ __launch_bounds__(256) void class_sum_kernel(
    const float* __restrict__ F, const int* __restrict__ lab,
    float* __restrict__ G, float* __restrict__ CNT)
{
    __shared__ int slab[NN];
    __shared__ int idx[NN];
    __shared__ int scnt;
    const int c = blockIdx.x;
    const int b = blockIdx.y;
    const int t = threadIdx.x;

    for (int n = t; n < NN; n += 256) slab[n] = lab[b * NN + n];
    __syncthreads();

    if (t < 32) {
        int cnt = 0;
        for (int ch = 0; ch < NN / 32; ch++) {
            int n = ch * 32 + t;
            bool m = (slab[n] == c);
            unsigned mask = __ballot_sync(0xFFFFFFFFu, m);
            if (m) idx[cnt + __popc(mask & ((1u << t) - 1u))] = n;
            cnt += __popc(mask);
        }
        if (t == 0) scnt = cnt;
    }
    __syncthreads();

    const int m = scnt;
    const float* Fb = F + (size_t)b * NN * DD;
    float s = 0.0f;
    int i = 0;
    for (; i + 4 <= m; i += 4) {
        int n0 = idx[i], n1 = idx[i+1], n2 = idx[i+2], n3 = idx[i+3];
        float v0 = Fb[(size_t)n0 * DD + t];
        float v1 = Fb[(size_t)n1 * DD + t];
        float v2 = Fb[(size_t)n2 * DD + t];
        float v3 = Fb[(size_t)n3 * DD + t];
        s += (v0 + v1) + (v2 + v3);
    }
    for (; i < m; i++) s += Fb[(size_t)idx[i] * DD + t];

    G[((size_t)b * CC + c) * DD + t] = s;
    if (t == 0) CNT[b * CC + c] = (float)m;
}

// ---------------------------------------------------------------------------
__global__ __launch_bounds__(256) void proto_out_kernel(
    const float* __restrict__ F, const float* __restrict__ G,
    const float* __restrict__ CNT, const int* __restrict__ lab,
    float* __restrict__ out)
{
    __shared__ float fs[DD];
    const int n = blockIdx.x;
    const int b = blockIdx.y;
    const int t = threadIdx.x;
    fs[t] = F[((size_t)b * NN + n) * DD + t];
    __syncthreads();

    const int w = t >> 5, lane = t & 31;
    float sd = 0.0f;
    for (int i = lane; i < DD; i += 32) sd += fs[i] * fs[i];
    #pragma unroll
    for (int o = 16; o; o >>= 1) sd += __shfl_xor_sync(0xFFFFFFFFu, sd, o);

    const int labn = lab[b * NN + n];
    #pragma unroll
    for (int cc = 0; cc < 2; cc++) {
        const int c = w * 2 + cc;
        const float* g = G + (size_t)b * CC * DD + c * DD;
        float dp = 0.0f;
        for (int i = lane; i < DD; i += 32) dp += fs[i] * g[i];
        #pragma unroll
        for (int o = 16; o; o >>= 1) dp += __shfl_xor_sync(0xFFFFFFFFu, dp, o);
        if (lane == 0) {
            float same = (labn == c) ? 1.0f : 0.0f;
            out[((size_t)b * NN + n) * CC + c] =
                (dp - same * sd) / (CNT[b * CC + c] - same);
        }
    }
}

// ---------------------------------------------------------------------------
extern "C" void kernel_launch(void* const* d_in, const int* in_sizes, int n_in,
                              void* d_out, int out_size)
{
    const float* E    = (const float*)d_in[0];
    const int*   lab  = (const int*)  d_in[1];
    const float* Wq0  = (const float*)d_in[2];
    const float* Wk0  = (const float*)d_in[3];
    const float* Wv0  = (const float*)d_in[4];
    const float* Wo0  = (const float*)d_in[5];
    const float* Wq1  = (const float*)d_in[6];
    const float* Wk1  = (const float*)d_in[7];
    const float* Wv1  = (const float*)d_in[8];
    const float* Wo1  = (const float*)d_in[9];
    const float* resW = (const float*)d_in[10];
    const float* resb = (const float*)d_in[11];
    const float* ffW1 = (const float*)d_in[12];
    const float* ffb1 = (const float*)d_in[13];
    const float* ffW2 = (const float*)d_in[14];
    const float* ffb2 = (const float*)d_in[15];
    float* out = (float*)d_out;

    float *bQ, *bK, *bV, *bO, *bX, *rbias, *G, *CNT;
    cudaGetSymbolAddress((void**)&bQ,    g_bufQ);
    cudaGetSymbolAddress((void**)&bK,    g_bufK);
    cudaGetSymbolAddress((void**)&bV,    g_bufV);
    cudaGetSymbolAddress((void**)&bO,    g_bufO);
    cudaGetSymbolAddress((void**)&bX,    g_bufX);
    cudaGetSymbolAddress((void**)&rbias, g_rbias);
    cudaGetSymbolAddress((void**)&G,     g_G);
    cudaGetSymbolAddress((void**)&CNT,   g_CNT);

    cudaFuncSetAttribute(attn_kernel,
                         cudaFuncAttributeMaxDynamicSharedMemorySize,
                         ATTN_SMEM_BYTES);

    const int M = BB * NN;                 // 8192
    dim3 gBig(M / GBM, DD / GBN);          // (64, 2)
    dim3 gQKV(M / GBM, DD / GBN, 3);       // (64, 2, 3)
    dim3 gAttn(NN / 32, HH, BB);           // (16, 8, 16)

    // ---- MHA 0 ----
    gemm_tf32_qkv_kernel<<<gQKV, 256>>>(E, Wq0, Wk0, Wv0, bQ, bK, bV, M, DD, DD);
    attn_kernel<<<gAttn, 256, ATTN_SMEM_BYTES>>>(bQ, bK, bV, bO);
    gemm_tf32_kernel<0, 1, 0><<<gBig, 256>>>(bO, Wo0, nullptr, bX, M, DD, DD);

    // ---- MHA 1 ----
    gemm_tf32_qkv_kernel<<<gQKV, 256>>>(bX, Wq1, Wk1, Wv1, bQ, bK, bV, M, DD, DD);
    attn_kernel<<<gAttn, 256, ATTN_SMEM_BYTES>>>(bQ, bK, bV, bO);
    gemm_tf32_kernel<0, 0, 0><<<gBig, 256>>>(bO, Wo1, nullptr, bX, M, DD, DD);

    // ---- aggregate path ----
    aggr_kernel<<<BB, 1024>>>(bX, resW, resb, ffW1, ffb1, rbias);
    gemm_tf32_kernel<1, 1, 2><<<gBig, 256>>>(E, ffW1 + (size_t)DD * DD, rbias, bQ, M, DD, DD);
    gemm_tf32_kernel<0, 0, 1><<<gBig, 256>>>(bQ, ffW2, ffb2, bK, M, DD, DD);

    // ---- prototypical scoring ----
    class_sum_kernel<<<dim3(CC, BB), 256>>>(bK, lab, G, CNT);
    proto_out_kernel<<<dim3(NN, BB), 256>>>(bK, G, CNT, lab, out);
}

// round 14
// speedup vs baseline: 2.3296x; 1.0117x over previous
#include <cuda_runtime.h>
#include <cuda_bf16.h>
#include <math.h>
#include <stdint.h>

// Shapes: B=16, N=512, D=256, H=8, DK=32, C=16
#define BB 16
#define NN 512
#define DD 256
#define HH 8
#define DKH 32
#define CC 16

__device__ float g_bufQ[BB * NN * DD];
__device__ float g_bufK[BB * NN * DD];
__device__ float g_bufV[BB * NN * DD];
__device__ float g_bufO[BB * NN * DD];
__device__ float g_bufX[BB * NN * DD];
__device__ float g_rbias[BB * DD];
__device__ float g_G[BB * CC * DD];
__device__ float g_CNT[BB * CC];

__device__ __forceinline__ float gelu_f(float x) {
    return 0.5f * x * (1.0f + erff(x * 0.7071067811865475f));
}

// exp(x) on the FMA/ALU pipes (no MUFU). ~1.2e-7 rel error.
__device__ __forceinline__ float fast_exp(float x) {
    float y = x * 1.4426950408889634f;
    y = fmaxf(y, -126.0f);
    float f = rintf(y);
    float z = y - f;
    float p = 1.5403530393381609e-4f;
    p = fmaf(p, z, 1.3333558146428443e-3f);
    p = fmaf(p, z, 9.6181291076284772e-3f);
    p = fmaf(p, z, 5.5504108664821580e-2f);
    p = fmaf(p, z, 2.4022650695910072e-1f);
    p = fmaf(p, z, 6.9314718055994531e-1f);
    p = fmaf(p, z, 1.0f);
    int e = (int)f;
    float s = __int_as_float((e + 127) << 23);
    return p * s;
}

__device__ __forceinline__ uint32_t f2tf32(float x) {
    uint32_t u;
    asm("cvt.rna.tf32.f32 %0, %1;" : "=r"(u) : "f"(x));
    return u;
}

__device__ __forceinline__ void mma_tf32(float c[4],
    uint32_t a0, uint32_t a1, uint32_t a2, uint32_t a3,
    uint32_t b0, uint32_t b1)
{
    asm volatile(
        "mma.sync.aligned.m16n8k8.row.col.f32.tf32.tf32.f32 "
        "{%0,%1,%2,%3},{%4,%5,%6,%7},{%8,%9},{%0,%1,%2,%3};"
        : "+f"(c[0]), "+f"(c[1]), "+f"(c[2]), "+f"(c[3])
        : "r"(a0), "r"(a1), "r"(a2), "r"(a3), "r"(b0), "r"(b1));
}

// ---------------------------------------------------------------------------
// tf32 tensor-core GEMM, double-buffered (unchanged from R13).
// ---------------------------------------------------------------------------
#define GBM 128
#define GBN 128
#define GBK 16

template <int AIN, int AOUT, int BMODE, int TF32OUT>
__device__ __forceinline__ void gemm_tf32_body(
    const float* __restrict__ A, const float* __restrict__ W,
    const float* __restrict__ bias, float* __restrict__ C,
    int M, int N, int K, int bm, int bn, float oscale)
{
    __shared__ uint32_t As[2][GBM][GBK + 4];
    __shared__ uint32_t Ws[2][GBK][GBN + 8];

    const int t    = threadIdx.x;
    const int lane = t & 31;
    const int wid  = t >> 5;
    const int wm   = (wid & 1) * 64;
    const int wn   = (wid >> 1) * 32;

    const int ar = t >> 1, ac = (t & 1) * 8;
    const int wr = t >> 4, wc = (t & 15) * 8;
    const int lq = lane >> 2;
    const int lr = lane & 3;

    float c[4][4][4];
    #pragma unroll
    for (int mt = 0; mt < 4; mt++)
        #pragma unroll
        for (int nt = 0; nt < 4; nt++)
            #pragma unroll
            for (int i = 0; i < 4; i++) c[mt][nt][i] = 0.0f;

    const int NIT = K / GBK;

    {
        float4 a0 = make_float4(0.f,0.f,0.f,0.f), a1 = make_float4(0.f,0.f,0.f,0.f);
        if (bm + ar < M) {
            a0 = *(const float4*)&A[(size_t)(bm + ar) * K + ac];
            a1 = *(const float4*)&A[(size_t)(bm + ar) * K + ac + 4];
        }
        if (AIN) {
            a0.x = gelu_f(a0.x); a0.y = gelu_f(a0.y); a0.z = gelu_f(a0.z); a0.w = gelu_f(a0.w);
            a1.x = gelu_f(a1.x); a1.y = gelu_f(a1.y); a1.z = gelu_f(a1.z); a1.w = gelu_f(a1.w);
        }
        As[0][ar][ac + 0] = f2tf32(a0.x); As[0][ar][ac + 1] = f2tf32(a0.y);
        As[0][ar][ac + 2] = f2tf32(a0.z); As[0][ar][ac + 3] = f2tf32(a0.w);
        As[0][ar][ac + 4] = f2tf32(a1.x); As[0][ar][ac + 5] = f2tf32(a1.y);
        As[0][ar][ac + 6] = f2tf32(a1.z); As[0][ar][ac + 7] = f2tf32(a1.w);

        float4 w0 = *(const float4*)&W[(size_t)wr * N + bn + wc];
        float4 w1 = *(const float4*)&W[(size_t)wr * N + bn + wc + 4];
        Ws[0][wr][wc + 0] = f2tf32(w0.x); Ws[0][wr][wc + 1] = f2tf32(w0.y);
        Ws[0][wr][wc + 2] = f2tf32(w0.z); Ws[0][wr][wc + 3] = f2tf32(w0.w);
        Ws[0][wr][wc + 4] = f2tf32(w1.x); Ws[0][wr][wc + 5] = f2tf32(w1.y);
        Ws[0][wr][wc + 6] = f2tf32(w1.z); Ws[0][wr][wc + 7] = f2tf32(w1.w);
    }
    __syncthreads();

    for (int it = 0; it < NIT; it++) {
        const int cur = it & 1, nxt = cur ^ 1;
        const bool has = (it + 1 < NIT);
        const int k0n = (it + 1) * GBK;

        float4 na0, na1, nw0, nw1;
        if (has) {
            na0 = make_float4(0.f,0.f,0.f,0.f); na1 = na0;
            if (bm + ar < M) {
                na0 = *(const float4*)&A[(size_t)(bm + ar) * K + k0n + ac];
                na1 = *(const float4*)&A[(size_t)(bm + ar) * K + k0n + ac + 4];
            }
            nw0 = *(const float4*)&W[(size_t)(k0n + wr) * N + bn + wc];
            nw1 = *(const float4*)&W[(size_t)(k0n + wr) * N + bn + wc + 4];
        }

        #pragma unroll
        for (int ks = 0; ks < GBK; ks += 8) {
            uint32_t af[4][4];
            #pragma unroll
            for (int mt = 0; mt < 4; mt++) {
                int r = wm + mt * 16 + lq;
                af[mt][0] = As[cur][r    ][ks + lr];
                af[mt][1] = As[cur][r + 8][ks + lr];
                af[mt][2] = As[cur][r    ][ks + lr + 4];
                af[mt][3] = As[cur][r + 8][ks + lr + 4];
            }
            uint32_t bf[4][2];
            #pragma unroll
            for (int nt = 0; nt < 4; nt++) {
                int nc = wn + nt * 8 + lq;
                bf[nt][0] = Ws[cur][ks + lr    ][nc];
                bf[nt][1] = Ws[cur][ks + lr + 4][nc];
            }
            #pragma unroll
            for (int mt = 0; mt < 4; mt++)
                #pragma unroll
                for (int nt = 0; nt < 4; nt++)
                    mma_tf32(c[mt][nt], af[mt][0], af[mt][1], af[mt][2], af[mt][3],
                             bf[nt][0], bf[nt][1]);
        }

        if (has) {
            if (AIN) {
                na0.x = gelu_f(na0.x); na0.y = gelu_f(na0.y); na0.z = gelu_f(na0.z); na0.w = gelu_f(na0.w);
                na1.x = gelu_f(na1.x); na1.y = gelu_f(na1.y); na1.z = gelu_f(na1.z); na1.w = gelu_f(na1.w);
            }
            As[nxt][ar][ac + 0] = f2tf32(na0.x); As[nxt][ar][ac + 1] = f2tf32(na0.y);
            As[nxt][ar][ac + 2] = f2tf32(na0.z); As[nxt][ar][ac + 3] = f2tf32(na0.w);
            As[nxt][ar][ac + 4] = f2tf32(na1.x); As[nxt][ar][ac + 5] = f2tf32(na1.y);
            As[nxt][ar][ac + 6] = f2tf32(na1.z); As[nxt][ar][ac + 7] = f2tf32(na1.w);
            Ws[nxt][wr][wc + 0] = f2tf32(nw0.x); Ws[nxt][wr][wc + 1] = f2tf32(nw0.y);
            Ws[nxt][wr][wc + 2] = f2tf32(nw0.z); Ws[nxt][wr][wc + 3] = f2tf32(nw0.w);
            Ws[nxt][wr][wc + 4] = f2tf32(nw1.x); Ws[nxt][wr][wc + 5] = f2tf32(nw1.y);
            Ws[nxt][wr][wc + 6] = f2tf32(nw1.z); Ws[nxt][wr][wc + 7] = f2tf32(nw1.w);
            __syncthreads();
        }
    }

    #pragma unroll
    for (int mt = 0; mt < 4; mt++) {
        int row0 = bm + wm + mt * 16 + lq;
        int row1 = row0 + 8;
        #pragma unroll
        for (int nt = 0; nt < 4; nt++) {
            int col = bn + wn + nt * 8 + lr * 2;
            float v0 = c[mt][nt][0], v1 = c[mt][nt][1];
            float v2 = c[mt][nt][2], v3 = c[mt][nt][3];
            if (BMODE == 1) {
                float b0 = bias[col], b1 = bias[col + 1];
                v0 += b0; v1 += b1; v2 += b0; v3 += b1;
            }
            if (BMODE == 2) {
                if (row0 < M) {
                    const float* bb = bias + (size_t)(row0 >> 9) * N + col;
                    v0 += bb[0]; v1 += bb[1];
                }
                if (row1 < M) {
                    const float* bb = bias + (size_t)(row1 >> 9) * N + col;
                    v2 += bb[0]; v3 += bb[1];
                }
            }
            if (AOUT) { v0 = gelu_f(v0); v1 = gelu_f(v1); v2 = gelu_f(v2); v3 = gelu_f(v3); }
            if (TF32OUT) {
                v0 = __uint_as_float(f2tf32(v0 * oscale));
                v1 = __uint_as_float(f2tf32(v1 * oscale));
                v2 = __uint_as_float(f2tf32(v2 * oscale));
                v3 = __uint_as_float(f2tf32(v3 * oscale));
            }
            if (row0 < M) *(float2*)&C[(size_t)row0 * N + col] = make_float2(v0, v1);
            if (row1 < M) *(float2*)&C[(size_t)row1 * N + col] = make_float2(v2, v3);
        }
    }
}

template <int AIN, int AOUT, int BMODE>
__global__ __launch_bounds__(256) void gemm_tf32_kernel(
    const float* __restrict__ A, const float* __restrict__ W,
    const float* __restrict__ bias, float* __restrict__ C,
    int M, int N, int K)
{
    gemm_tf32_body<AIN, AOUT, BMODE, 0>(A, W, bias, C, M, N, K,
                                        blockIdx.x * GBM, blockIdx.y * GBN, 1.0f);
}

__global__ __launch_bounds__(256) void gemm_tf32_qkv_kernel(
    const float* __restrict__ A,
    const float* __restrict__ W0, const float* __restrict__ W1, const float* __restrict__ W2,
    float* __restrict__ C0, float* __restrict__ C1, float* __restrict__ C2,
    int M, int N, int K)
{
    const float* W = (blockIdx.z == 0) ? W0 : (blockIdx.z == 1) ? W1 : W2;
    float*       C = (blockIdx.z == 0) ? C0 : (blockIdx.z == 1) ? C1 : C2;
    const float oscale = (blockIdx.z == 0) ? 0.17677669529663688f : 1.0f;
    gemm_tf32_body<0, 0, 0, 1>(A, W, nullptr, C, M, N, K,
                               blockIdx.x * GBM, blockIdx.y * GBN, oscale);
}

// ---------------------------------------------------------------------------
// Fused attention v9 (unchanged from R13) — per-key-tile QK->exp->PV, 3 CTAs/SM.
// ---------------------------------------------------------------------------
#define SCT 132
#define ATTN_SMEM_WORDS 15264
#define ATTN_SMEM_BYTES (ATTN_SMEM_WORDS * 4)

__global__ __launch_bounds__(256, 3) void attn_kernel(
    const float* __restrict__ Qp, const float* __restrict__ Kp,
    const float* __restrict__ Vp, float* __restrict__ Op)
{
    extern __shared__ uint32_t smu[];
    uint32_t* qs = smu;             // [32][36]
    uint32_t* ks = smu + 1152;      // [128][36]
    uint32_t* vs = smu + 5760;      // [128][40]
    uint32_t* sc = smu + 10880;     // [32][132]
    float*   rsp = (float*)(smu + 15104);
    float*   rs  = (float*)(smu + 15232);

    const int t    = threadIdx.x;
    const int lane = t & 31;
    const int w    = t >> 5;
    const int qb = blockIdx.x * 32;
    const int h  = blockIdx.y;
    const int b  = blockIdx.z;

    const size_t baseQ  = ((size_t)(b * NN + qb)) * DD + h * DKH;
    const size_t baseKV = ((size_t)(b * NN)) * DD + h * DKH;

    {
        int r = t >> 3, c = (t & 7) * 4;
        *(uint4*)&qs[r * 36 + c] = *(const uint4*)&Qp[baseQ + (size_t)r * DD + c];
    }
    __syncthreads();

    const int lq = lane >> 2;
    const int lr = lane & 3;
    const int mb = (w & 1) * 16;
    const int nqb = (w >> 1) * 32;
    const int nvb = (w >> 1) * 8;

    uint32_t qa[4][4];
    #pragma unroll
    for (int kk = 0; kk < 4; kk++) {
        qa[kk][0] = qs[(mb + lq)     * 36 + kk * 8 + lr];
        qa[kk][1] = qs[(mb + 8 + lq) * 36 + kk * 8 + lr];
        qa[kk][2] = qs[(mb + lq)     * 36 + kk * 8 + lr + 4];
        qa[kk][3] = qs[(mb + 8 + lq) * 36 + kk * 8 + lr + 4];
    }

    float rlo = 0.0f, rhi = 0.0f;
    float oc[4] = {0.0f, 0.0f, 0.0f, 0.0f};

    #pragma unroll 1
    for (int kt = 0; kt < 4; kt++) {
        const int kb = kt * 128;
        __syncthreads();
        for (int i = t; i < 1024; i += 256) {
            int r = i >> 3, c = (i & 7) * 4;
            *(uint4*)&ks[r * 36 + c] =
                *(const uint4*)&Kp[baseKV + (size_t)(kb + r) * DD + c];
        }
        for (int i = t; i < 1024; i += 256) {
            int r = i >> 3, c = (i & 7) * 4;
            *(uint4*)&vs[r * 40 + c] =
                *(const uint4*)&Vp[baseKV + (size_t)(kb + r) * DD + c];
        }
        __syncthreads();

        #pragma unroll
        for (int nt = 0; nt < 4; nt++) {
            const int nb = nqb + nt * 8;
            float c4[4] = {0.0f, 0.0f, 0.0f, 0.0f};
            #pragma unroll
            for (int kk = 0; kk < 4; kk++) {
                uint32_t b0 = ks[(nb + lq) * 36 + kk * 8 + lr];
                uint32_t b1 = ks[(nb + lq) * 36 + kk * 8 + lr + 4];
                mma_tf32(c4, qa[kk][0], qa[kk][1], qa[kk][2], qa[kk][3], b0, b1);
            }
            float e0 = fast_exp(c4[0]);
            float e1 = fast_exp(c4[1]);
            float e2 = fast_exp(c4[2]);
            float e3 = fast_exp(c4[3]);
            rlo += e0 + e1;
            rhi += e2 + e3;
            *(uint2*)&sc[(mb + lq)     * SCT + nb + 2 * lr] = make_uint2(f2tf32(e0), f2tf32(e1));
            *(uint2*)&sc[(mb + 8 + lq) * SCT + nb + 2 * lr] = make_uint2(f2tf32(e2), f2tf32(e3));
        }
        __syncthreads();

        #pragma unroll
        for (int kk = 0; kk < 16; kk++) {
            const int kk8 = kk * 8;
            uint32_t a0 = sc[(mb + lq)     * SCT + kk8 + lr];
            uint32_t a1 = sc[(mb + 8 + lq) * SCT + kk8 + lr];
            uint32_t a2 = sc[(mb + lq)     * SCT + kk8 + lr + 4];
            uint32_t a3 = sc[(mb + 8 + lq) * SCT + kk8 + lr + 4];
            uint32_t b0 = vs[(kk8 + lr)     * 40 + nvb + lq];
            uint32_t b1 = vs[(kk8 + lr + 4) * 40 + nvb + lq];
            mma_tf32(oc, a0, a1, a2, a3, b0, b1);
        }
    }

    rlo += __shfl_xor_sync(0xFFFFFFFFu, rlo, 1);
    rlo += __shfl_xor_sync(0xFFFFFFFFu, rlo, 2);
    rhi += __shfl_xor_sync(0xFFFFFFFFu, rhi, 1);
    rhi += __shfl_xor_sync(0xFFFFFFFFu, rhi, 2);
    if (lr == 0) {
        rsp[w * 16 + lq]     = rlo;
        rsp[w * 16 + 8 + lq] = rhi;
    }
    __syncthreads();
    if (t < 32) {
        int mt = t >> 4, r = t & 15;
        rs[t] = rsp[mt * 16 + r] + rsp[(mt + 2) * 16 + r]
              + rsp[(mt + 4) * 16 + r] + rsp[(mt + 6) * 16 + r];
    }
    __syncthreads();

    {
        float inv0 = 1.0f / rs[mb + lq];
        float inv1 = 1.0f / rs[mb + 8 + lq];
        int col = nvb + 2 * lr;
        *(float2*)&Op[baseQ + (size_t)(mb + lq)     * DD + col] =
            make_float2(oc[0] * inv0, oc[1] * inv0);
        *(float2*)&Op[baseQ + (size_t)(mb + 8 + lq) * DD + col] =
            make_float2(oc[2] * inv1, oc[3] * inv1);
    }
}

// ---------------------------------------------------------------------------
// Fused aggregate chain (unchanged from R13).
// ---------------------------------------------------------------------------
__global__ __launch_bounds__(1024) void aggr_kernel(
    const float* __restrict__ X,
    const float* __restrict__ resW, const float* __restrict__ resb,
    const float* __restrict__ ffW1, const float* __restrict__ ffb1,
    float* __restrict__ rbias)
{
    __shared__ float part[4][DD];
    __shared__ float ag[DD];
    __shared__ float ar[DD];
    const int b = blockIdx.x;
    const int t = threadIdx.x & 255;
    const int p = threadIdx.x >> 8;

    float s = 0.0f;
    const float* base = X + (size_t)b * NN * DD + (size_t)p * 128 * DD + t;
    #pragma unroll 8
    for (int n = 0; n < 128; n++) s += base[(size_t)n * DD];
    part[p][t] = s;
    __syncthreads();
    if (p == 0)
        ag[t] = gelu_f((part[0][t] + part[1][t] + part[2][t] + part[3][t]) * (1.0f / (float)NN));
    __syncthreads();

    s = 0.0f;
    #pragma unroll 8
    for (int k = p * 64; k < p * 64 + 64; k++)
        s = fmaf(ag[k], resW[(size_t)k * DD + t], s);
    part[p][t] = s;
    __syncthreads();
    if (p == 0)
        ar[t] = gelu_f(part[0][t] + part[1][t] + part[2][t] + part[3][t] + resb[t]);
    __syncthreads();

    s = 0.0f;
    #pragma unroll 8
    for (int k = p * 64; k < p * 64 + 64; k++)
        s = fmaf(ar[k], ffW1[(size_t)k * DD + t], s);
    part[p][t] = s;
    __syncthreads();
    if (p == 0)
        rbias[b * DD + t] = part[0][t] + part[1][t] + part[2][t] + part[3][t] + ffb1[t];
}

// ---------------------------------------------------------------------------
// class_sum (unchanged from R13).
// ---------------------------------------------------------------------------
__global__ __launch_bounds__(256) void class_sum_kernel(
    const float* __restrict__ F, const int* __restrict__ lab,
    float* __restrict__ G, float* __restrict__ CNT)
{
    __shared__ int slab[NN];
    __shared__ int idx[NN];
    __shared__ int scnt;
    const int c = blockIdx.x;
    const int b = blockIdx.y;
    const int t = threadIdx.x;

    for (int n = t; n < NN; n += 256) slab[n] = lab[b * NN + n];
    __syncthreads();

    if (t < 32) {
        int cnt = 0;
        for (int ch = 0; ch < NN / 32; ch++) {
            int n = ch * 32 + t;
            bool m = (slab[n] == c);
            unsigned mask = __ballot_sync(0xFFFFFFFFu, m);
            if (m) idx[cnt + __popc(mask & ((1u << t) - 1u))] = n;
            cnt += __popc(mask);
        }
        if (t == 0) scnt = cnt;
    }
    __syncthreads();

    const int m = scnt;
    const float* Fb = F + (size_t)b * NN * DD;
    float s = 0.0f;
    int i = 0;
    for (; i + 4 <= m; i += 4) {
        int n0 = idx[i], n1 = idx[i+1], n2 = idx[i+2], n3 = idx[i+3];
        float v0 = Fb[(size_t)n0 * DD + t];
        float v1 = Fb[(size_t)n1 * DD + t];
        float v2 = Fb[(size_t)n2 * DD + t];
        float v3 = Fb[(size_t)n3 * DD + t];
        s += (v0 + v1) + (v2 + v3);
    }
    for (; i < m; i++) s += Fb[(size_t)idx[i] * DD + t];

    G[((size_t)b * CC + c) * DD + t] = s;
    if (t == 0) CNT[b * CC + c] = (float)m;
}

// ---------------------------------------------------------------------------
// proto_out v2: grid (NN/32, BB) = (16, 16). Block stages G[b] (16 KB) +
// counts once in smem; 8 warps x 4 rows. Per row: float4 f loads (coalesced),
// float4 g from smem, 16 class dots + ||f||^2, butterfly reduce, lanes 0-15
// write the 16 outputs.
// ---------------------------------------------------------------------------
__global__ __launch_bounds__(256) void proto_out_kernel(
    const float* __restrict__ F, const float* __restrict__ G,
    const float* __restrict__ CNT, const int* __restrict__ lab,
    float* __restrict__ out)
{
    __shared__ float gs[CC * DD];     // 16 KB
    __shared__ float cnt_s[CC];
    const int nb = blockIdx.x * 32;   // row base
    const int b  = blockIdx.y;
    const int t  = threadIdx.x;
    const int w  = t >> 5, lane = t & 31;

    for (int i = t; i < CC * DD; i += 256)
        gs[i] = G[(size_t)b * CC * DD + i];
    if (t < CC) cnt_s[t] = CNT[b * CC + t];
    __syncthreads();

    const float4* gs4 = (const float4*)gs;   // [CC][64]

    #pragma unroll
    for (int rr = 0; rr < 4; rr++) {
        const int n = nb + w * 4 + rr;
        const float* f = F + ((size_t)b * NN + n) * DD;
        float4 fa = *(const float4*)&f[lane * 4];
        float4 fb = *(const float4*)&f[128 + lane * 4];

        float sd = fa.x*fa.x + fa.y*fa.y + fa.z*fa.z + fa.w*fa.w
                 + fb.x*fb.x + fb.y*fb.y + fb.z*fb.z + fb.w*fb.w;

        float dp[CC];
        #pragma unroll
        for (int c = 0; c < CC; c++) {
            float4 ga = gs4[c * 64 + lane];
            float4 gb = gs4[c * 64 + 32 + lane];
            dp[c] = fa.x*ga.x + fa.y*ga.y + fa.z*ga.z + fa.w*ga.w
                  + fb.x*gb.x + fb.y*gb.y + fb.z*gb.z + fb.w*gb.w;
        }

        #pragma unroll
        for (int o = 16; o; o >>= 1) {
            sd += __shfl_xor_sync(0xFFFFFFFFu, sd, o);
            #pragma unroll
            for (int c = 0; c < CC; c++)
                dp[c] += __shfl_xor_sync(0xFFFFFFFFu, dp[c], o);
        }

        if (lane < CC) {
            const int labn = lab[b * NN + n];
            float same = (labn == lane) ? 1.0f : 0.0f;
            out[((size_t)b * NN + n) * CC + lane] =
                (dp[lane] - same * sd) / (cnt_s[lane] - same);
        }
    }
}

// ---------------------------------------------------------------------------
extern "C" void kernel_launch(void* const* d_in, const int* in_sizes, int n_in,
                              void* d_out, int out_size)
{
    const float* E    = (const float*)d_in[0];
    const int*   lab  = (const int*)  d_in[1];
    const float* Wq0  = (const float*)d_in[2];
    const float* Wk0  = (const float*)d_in[3];
    const float* Wv0  = (const float*)d_in[4];
    const float* Wo0  = (const float*)d_in[5];
    const float* Wq1  = (const float*)d_in[6];
    const float* Wk1  = (const float*)d_in[7];
    const float* Wv1  = (const float*)d_in[8];
    const float* Wo1  = (const float*)d_in[9];
    const float* resW = (const float*)d_in[10];
    const float* resb = (const float*)d_in[11];
    const float* ffW1 = (const float*)d_in[12];
    const float* ffb1 = (const float*)d_in[13];
    const float* ffW2 = (const float*)d_in[14];
    const float* ffb2 = (const float*)d_in[15];
    float* out = (float*)d_out;

    float *bQ, *bK, *bV, *bO, *bX, *rbias, *G, *CNT;
    cudaGetSymbolAddress((void**)&bQ,    g_bufQ);
    cudaGetSymbolAddress((void**)&bK,    g_bufK);
    cudaGetSymbolAddress((void**)&bV,    g_bufV);
    cudaGetSymbolAddress((void**)&bO,    g_bufO);
    cudaGetSymbolAddress((void**)&bX,    g_bufX);
    cudaGetSymbolAddress((void**)&rbias, g_rbias);
    cudaGetSymbolAddress((void**)&G,     g_G);
    cudaGetSymbolAddress((void**)&CNT,   g_CNT);

    cudaFuncSetAttribute(attn_kernel,
                         cudaFuncAttributeMaxDynamicSharedMemorySize,
                         ATTN_SMEM_BYTES);

    const int M = BB * NN;                 // 8192
    dim3 gBig(M / GBM, DD / GBN);          // (64, 2)
    dim3 gQKV(M / GBM, DD / GBN, 3);       // (64, 2, 3)
    dim3 gAttn(NN / 32, HH, BB);           // (16, 8, 16)

    // ---- MHA 0 ----
    gemm_tf32_qkv_kernel<<<gQKV, 256>>>(E, Wq0, Wk0, Wv0, bQ, bK, bV, M, DD, DD);
    attn_kernel<<<gAttn, 256, ATTN_SMEM_BYTES>>>(bQ, bK, bV, bO);
    gemm_tf32_kernel<0, 1, 0><<<gBig, 256>>>(bO, Wo0, nullptr, bX, M, DD, DD);

    // ---- MHA 1 ----
    gemm_tf32_qkv_kernel<<<gQKV, 256>>>(bX, Wq1, Wk1, Wv1, bQ, bK, bV, M, DD, DD);
    attn_kernel<<<gAttn, 256, ATTN_SMEM_BYTES>>>(bQ, bK, bV, bO);
    gemm_tf32_kernel<0, 0, 0><<<gBig, 256>>>(bO, Wo1, nullptr, bX, M, DD, DD);

    // ---- aggregate path ----
    aggr_kernel<<<BB, 1024>>>(bX, resW, resb, ffW1, ffb1, rbias);
    gemm_tf32_kernel<1, 1, 2><<<gBig, 256>>>(E, ffW1 + (size_t)DD * DD, rbias, bQ, M, DD, DD);
    gemm_tf32_kernel<0, 0, 1><<<gBig, 256>>>(bQ, ffW2, ffb2, bK, M, DD, DD);

    // ---- prototypical scoring ----
    class_sum_kernel<<<dim3(CC, BB), 256>>>(bK, lab, G, CNT);
    proto_out_kernel<<<dim3(NN / 32, BB), 256>>>(bK, G, CNT, lab, out);
}